// round 12
// baseline (speedup 1.0000x reference)
#include <cuda_runtime.h>
#include <cuda_fp16.h>
#include <math.h>
#include <mma.h>

using namespace nvcuda;

// ---------------- problem constants ----------------
#define Bn     8
#define Ssz    512
#define DIMn   1024
#define Hn     16
#define DHn    64
#define INNERn 1024
#define MLPn   4096
#define En     8
#define Kn     2
#define LRn    77
#define CAPn   2
#define Dlay   2

static const long SZX = (long)Bn * Ssz * DIMn;           // 4,194,304
static const long SZSC = (long)Bn * Hn * Ssz * Ssz;      // 33,554,432
static const long SZH  = (long)Bn * Kn * Ssz * MLPn;     // 33,554,432

// ---- fp32 arena ----
static const long O_SC  = 0;
static const long O_RM  = O_SC + SZSC;
static const long O_LG  = O_RM + 8192;
static const long O_NL  = O_LG + 64;
static const long O_FW  = O_NL + 64;      // 32 floats (2 layers x 16)
static const long O_FE  = O_FW + 32;      // 32 ints
static const long O_USE = O_FE + 32;      // 16 ints (2 layers x 8 experts)
static const long ARENA_FLOATS = O_USE + 32;
__device__ __align__(16) float g_arena[ARENA_FLOATS];

// ---- fp16 arena ----
static const long H_LNQ = 0;
static const long H_LNK = H_LNQ + SZX;
static const long H_LNV = H_LNK + SZX;
static const long H_XN  = H_LNV + SZX;
static const long H_OB  = H_XN  + SZX;
static const long H_Q   = H_OB  + SZX;
static const long H_K   = H_Q   + SZX;
static const long H_V   = H_K   + SZX;
static const long H_P   = H_V   + SZX;            // fp16 attention probs
static const long H_H   = H_P   + SZSC;
static const long H_WQ  = H_H   + SZH;
static const long H_WK  = H_WQ  + (long)Dlay * DIMn * INNERn;
static const long H_WV  = H_WK  + (long)Dlay * DIMn * INNERn;
static const long H_WO  = H_WV  + (long)Dlay * DIMn * INNERn;
static const long H_W1  = H_WO  + (long)Dlay * INNERn * DIMn;
static const long H_W2  = H_W1  + (long)Dlay * En * DIMn * MLPn;
static const long ARENA_HALVES = H_W2 + (long)Dlay * En * MLPn * DIMn;
__device__ __align__(16) __half g_harena[ARENA_HALVES];

// ---------------- reductions ----------------
__device__ __forceinline__ float warpSum(float v) {
    #pragma unroll
    for (int o = 16; o; o >>= 1) v += __shfl_xor_sync(0xffffffffu, v, o);
    return v;
}
__device__ __forceinline__ float warpMax(float v) {
    #pragma unroll
    for (int o = 16; o; o >>= 1) v = fmaxf(v, __shfl_xor_sync(0xffffffffu, v, o));
    return v;
}

// ---------------- threefry2x32 (JAX-exact) ----------------
__device__ __forceinline__ void tf2x32(unsigned k0, unsigned k1, unsigned x0, unsigned x1,
                                       unsigned& o0, unsigned& o1) {
    unsigned ks[3] = {k0, k1, k0 ^ k1 ^ 0x1BD11BDAu};
    const int R0[4] = {13, 15, 26, 6};
    const int R1[4] = {17, 29, 16, 24};
    x0 += ks[0]; x1 += ks[1];
    #pragma unroll
    for (int i = 0; i < 5; i++) {
        #pragma unroll
        for (int r = 0; r < 4; r++) {
            int rot = (i & 1) ? R1[r] : R0[r];
            x0 += x1;
            x1 = (x1 << rot) | (x1 >> (32 - rot));
            x1 ^= x0;
        }
        x0 += ks[(i + 1) % 3];
        x1 += ks[(i + 2) % 3] + (unsigned)(i + 1);
    }
    o0 = x0; o1 = x1;
}

// ---------------- fp32 -> fp16 converts ----------------
__global__ void f2h4(const float4* __restrict__ src, __half2* __restrict__ dst, long n4) {
    long i = (long)blockIdx.x * blockDim.x + threadIdx.x;
    if (i >= n4) return;
    float4 v = src[i];
    dst[2 * i]     = __floats2half2_rn(v.x, v.y);
    dst[2 * i + 1] = __floats2half2_rn(v.z, v.w);
}

// selective per-(layer,expert) conversion; early-exit if expert unused
__global__ void f2h_sel(const float4* __restrict__ src, __half2* __restrict__ dst,
                        const int* __restrict__ used, long n4_per) {
    int e = blockIdx.y;                      // 0..15 = l*8+e
    if (!used[e]) return;
    long i = (long)blockIdx.x * blockDim.x + threadIdx.x;
    if (i >= n4_per) return;
    long idx = (long)e * n4_per + i;
    float4 v = src[idx];
    dst[2 * idx]     = __floats2half2_rn(v.x, v.y);
    dst[2 * idx + 1] = __floats2half2_rn(v.z, v.w);
}

// =================================================================
// fp16 WMMA machinery (r7 double-buffer mainloop — best known)
// =================================================================
using HFragA  = wmma::fragment<wmma::matrix_a, 16, 16, 16, __half, wmma::row_major>;
using HFragB  = wmma::fragment<wmma::matrix_b, 16, 16, 16, __half, wmma::row_major>;
using HFragBc = wmma::fragment<wmma::matrix_b, 16, 16, 16, __half, wmma::col_major>;
using HFragC  = wmma::fragment<wmma::accumulator, 16, 16, 16, float>;

__device__ __forceinline__ void cpa16(void* dst_smem, const void* src) {
    unsigned d = (unsigned)__cvta_generic_to_shared(dst_smem);
    asm volatile("cp.async.cg.shared.global [%0], [%1], 16;\n" :: "r"(d), "l"(src));
}
__device__ __forceinline__ void cp_commit() { asm volatile("cp.async.commit_group;\n"); }
template <int N>
__device__ __forceinline__ void cp_wait() { asm volatile("cp.async.wait_group %0;\n" :: "n"(N)); }

#define HA_STR 72
#define HB_STR 136
#define HA_STAGE (128 * HA_STR)
#define HB_STAGE (64 * HB_STR)
static const int SMEMH_BYTES = (2 * HA_STAGE + 2 * HB_STAGE) * 2;  // 71680 B

__device__ __forceinline__ void hmm_cp(const __half* __restrict__ A, const __half* __restrict__ B,
                                       int lda, int ldb, int K, int m0, int n0,
                                       __half* sm, HFragC (&acc)[2][4]) {
    __half* sA[2] = { sm, sm + HA_STAGE };
    __half* sB[2] = { sm + 2 * HA_STAGE, sm + 2 * HA_STAGE + HB_STAGE };
    int tid = threadIdx.x;
    int warp = tid >> 5, wm = warp & 3, wn = warp >> 2;
    int arow = tid >> 1, acH = (tid & 1) * 32;
    int brow = tid >> 2, bcH = (tid & 3) * 32;
    const __half* Ab = A + (long)(m0 + arow) * lda + acH;
    const __half* Bb = B + (long)brow * ldb + n0 + bcH;
    __half* dA[2] = { sA[0] + arow * HA_STR + acH, sA[1] + arow * HA_STR + acH };
    __half* dB[2] = { sB[0] + brow * HB_STR + bcH, sB[1] + brow * HB_STR + bcH };

    int nIt = K >> 6;
    #pragma unroll
    for (int i = 0; i < 4; i++) cpa16(dA[0] + i * 8, Ab + i * 8);
    #pragma unroll
    for (int i = 0; i < 4; i++) cpa16(dB[0] + i * 8, Bb + i * 8);
    cp_commit();

    #pragma unroll 1
    for (int it = 0; it < nIt; it++) {
        int s = it & 1;
        if (it + 1 < nIt) {
            int s2 = s ^ 1;
            const __half* a = Ab + (it + 1) * 64;
            const __half* b = Bb + (long)(it + 1) * 64 * ldb;
            #pragma unroll
            for (int i = 0; i < 4; i++) cpa16(dA[s2] + i * 8, a + i * 8);
            #pragma unroll
            for (int i = 0; i < 4; i++) cpa16(dB[s2] + i * 8, b + i * 8);
            cp_commit();
            cp_wait<1>();
        } else {
            cp_wait<0>();
        }
        __syncthreads();
        #pragma unroll
        for (int kk = 0; kk < 4; kk++) {
            HFragA af[2];
            #pragma unroll
            for (int i = 0; i < 2; i++)
                wmma::load_matrix_sync(af[i], sA[s] + (wm * 32 + i * 16) * HA_STR + kk * 16, HA_STR);
            #pragma unroll
            for (int j = 0; j < 4; j++) {
                HFragB bf;
                wmma::load_matrix_sync(bf, sB[s] + (kk * 16) * HB_STR + wn * 64 + j * 16, HB_STR);
                wmma::mma_sync(acc[0][j], af[0], bf, acc[0][j]);
                wmma::mma_sync(acc[1][j], af[1], bf, acc[1][j]);
            }
        }
        __syncthreads();
    }
}

__device__ __forceinline__ void hacc_zero(HFragC (&acc)[2][4]) {
    #pragma unroll
    for (int i = 0; i < 2; i++)
        #pragma unroll
        for (int j = 0; j < 4; j++) wmma::fill_fragment(acc[i][j], 0.0f);
}

// EPI: 1 = fp32 C += acc + bias ; 2 = fp16 C = gelu(acc+bias) ; 3 = atomicAdd(fp32 C, (acc+bias)*w) ; 4 = fp16 C = acc
template <int EPI>
__device__ __forceinline__ void hepilogue(HFragC (&acc)[2][4], float* stage_w,
                                          void* __restrict__ Cv, const float* __restrict__ bias,
                                          int ldc, int m0, int n0, float w) {
    int tid = threadIdx.x, warp = tid >> 5, lane = tid & 31;
    int wm = warp & 3, wn = warp >> 2;
    int r = lane >> 1, cb = (lane & 1) * 8;
    #pragma unroll
    for (int i = 0; i < 2; i++)
        #pragma unroll
        for (int j = 0; j < 4; j++) {
            wmma::store_matrix_sync(stage_w, acc[i][j], 20, wmma::mem_row_major);
            __syncwarp();
            int row = m0 + wm * 32 + i * 16 + r;
            int col0 = n0 + wn * 64 + j * 16 + cb;
            #pragma unroll
            for (int c = 0; c < 8; c++) {
                float v = stage_w[r * 20 + cb + c];
                int col = col0 + c;
                long idx = (long)row * ldc + col;
                if (EPI == 1) {
                    float* C = (float*)Cv;
                    C[idx] = C[idx] + v + bias[col];
                } else if (EPI == 2) {
                    float u = v + bias[col];
                    ((__half*)Cv)[idx] = __float2half_rn(0.5f * u * (1.0f + erff(u * 0.70710678118654752f)));
                } else if (EPI == 3) {
                    atomicAdd(&((float*)Cv)[idx], (v + bias[col]) * w);
                } else {
                    ((__half*)Cv)[idx] = __float2half_rn(v);
                }
            }
            __syncwarp();
        }
}

// fused QKV (fp16 in, fp16 out)
__global__ __launch_bounds__(256, 2) void qkv_h(const __half* __restrict__ lnq, const __half* __restrict__ lnk,
                                                const __half* __restrict__ lnv,
                                                const __half* __restrict__ Wq, const __half* __restrict__ Wk,
                                                const __half* __restrict__ Wv,
                                                __half* __restrict__ q, __half* __restrict__ k,
                                                __half* __restrict__ v) {
    extern __shared__ __half smh[];
    int z = blockIdx.z;
    const __half* A = (z == 0) ? lnq : (z == 1) ? lnk : lnv;
    const __half* B = (z == 0) ? Wq : (z == 1) ? Wk : Wv;
    __half* C = (z == 0) ? q : (z == 1) ? k : v;
    int m0 = blockIdx.y * 128, n0 = blockIdx.x * 128;
    HFragC acc[2][4];
    hacc_zero(acc);
    hmm_cp(A, B, DIMn, INNERn, DIMn, m0, n0, smh, acc);
    float* stage = (float*)smh + (threadIdx.x >> 5) * 320;
    hepilogue<4>(acc, stage, C, nullptr, INNERn, m0, n0, 0.0f);
}

// X += ob @ Wo + bo
__global__ __launch_bounds__(256, 2) void wo_h(const __half* __restrict__ A, const __half* __restrict__ B,
                                               float* __restrict__ C, const float* __restrict__ bias) {
    extern __shared__ __half smh[];
    int m0 = blockIdx.y * 128, n0 = blockIdx.x * 128;
    HFragC acc[2][4];
    hacc_zero(acc);
    hmm_cp(A, B, INNERn, DIMn, INNERn, m0, n0, smh, acc);
    float* stage = (float*)smh + (threadIdx.x >> 5) * 320;
    hepilogue<1>(acc, stage, C, bias, DIMn, m0, n0, 0.0f);
}

// MoE 1: H16 = gelu(xn16 @ W1[e] + b1[e])
__global__ __launch_bounds__(256, 2) void moe1_h(const __half* __restrict__ xn, const __half* __restrict__ W1l,
                                                 const float* __restrict__ b1l, __half* __restrict__ H,
                                                 const int* __restrict__ fe, const float* __restrict__ fw) {
    extern __shared__ __half smh[];
    int n = blockIdx.z;
    if (fw[n] == 0.0f) return;
    int e = fe[n];
    const __half* A = xn + (long)(n >> 1) * Ssz * DIMn;
    const __half* B = W1l + (long)e * DIMn * MLPn;
    __half* C = H + (long)n * Ssz * MLPn;
    const float* bias = b1l + (long)e * MLPn;
    int m0 = blockIdx.y * 128, n0 = blockIdx.x * 128;
    HFragC acc[2][4];
    hacc_zero(acc);
    hmm_cp(A, B, DIMn, MLPn, DIMn, m0, n0, smh, acc);
    float* stage = (float*)smh + (threadIdx.x >> 5) * 320;
    hepilogue<2>(acc, stage, C, bias, MLPn, m0, n0, 0.0f);
}

// MoE 2: X[slot>>1] += (H16 @ W2[e] + b2[e]) * w
__global__ __launch_bounds__(256, 2) void moe2_h(const __half* __restrict__ H, const __half* __restrict__ W2l,
                                                 const float* __restrict__ b2l, float* __restrict__ X,
                                                 const int* __restrict__ fe, const float* __restrict__ fw) {
    extern __shared__ __half smh[];
    int n = blockIdx.z;
    float w = fw[n];
    if (w == 0.0f) return;
    int e = fe[n];
    const __half* A = H + (long)n * Ssz * MLPn;
    const __half* B = W2l + (long)e * MLPn * DIMn;
    float* C = X + (long)(n >> 1) * Ssz * DIMn;
    const float* bias = b2l + (long)e * DIMn;
    int m0 = blockIdx.y * 128, n0 = blockIdx.x * 128;
    HFragC acc[2][4];
    hacc_zero(acc);
    hmm_cp(A, B, MLPn, DIMn, MLPn, m0, n0, smh, acc);
    float* stage = (float*)smh + (threadIdx.x >> 5) * 320;
    hepilogue<3>(acc, stage, C, bias, DIMn, m0, n0, w);
}

// =================================================================
// Attention (r7 pipeline): QK^T (TC, fp32 scores), softmax (fp32->fp16), PV (TC)
// =================================================================
__global__ __launch_bounds__(256, 2) void qk_h(const __half* __restrict__ qh, const __half* __restrict__ kh,
                                               float* __restrict__ sc) {
    __shared__ __half sQ[128 * 72];
    __shared__ __half sK[128 * 72];
    int z = blockIdx.z, b = z >> 4, h = z & 15;
    const __half* Qb = qh + (long)b * Ssz * INNERn + h * DHn;
    const __half* Kb = kh + (long)b * Ssz * INNERn + h * DHn;
    float* C = sc + (long)z * Ssz * Ssz;
    int m0 = blockIdx.y * 128, n0 = blockIdx.x * 128;
    int tid = threadIdx.x;
    int row = tid >> 1, colH = (tid & 1) * 32;
    #pragma unroll
    for (int i = 0; i < 4; i++) {
        cpa16(sQ + row * 72 + colH + i * 8, Qb + (long)(m0 + row) * INNERn + colH + i * 8);
        cpa16(sK + row * 72 + colH + i * 8, Kb + (long)(n0 + row) * INNERn + colH + i * 8);
    }
    cp_commit(); cp_wait<0>();
    __syncthreads();
    int warp = tid >> 5, wm = warp & 3, wn = warp >> 2;
    HFragC acc[2][4];
    hacc_zero(acc);
    #pragma unroll
    for (int kk = 0; kk < 4; kk++) {
        HFragA af[2];
        #pragma unroll
        for (int i = 0; i < 2; i++)
            wmma::load_matrix_sync(af[i], sQ + (wm * 32 + i * 16) * 72 + kk * 16, 72);
        #pragma unroll
        for (int j = 0; j < 4; j++) {
            HFragBc bf;
            wmma::load_matrix_sync(bf, sK + (wn * 64 + j * 16) * 72 + kk * 16, 72);
            wmma::mma_sync(acc[0][j], af[0], bf, acc[0][j]);
            wmma::mma_sync(acc[1][j], af[1], bf, acc[1][j]);
        }
    }
    #pragma unroll
    for (int i = 0; i < 2; i++)
        #pragma unroll
        for (int j = 0; j < 4; j++) {
            #pragma unroll
            for (int e = 0; e < acc[i][j].num_elements; e++) acc[i][j].x[e] *= 0.125f;
            wmma::store_matrix_sync(&C[(long)(m0 + wm * 32 + i * 16) * Ssz + n0 + wn * 64 + j * 16],
                                    acc[i][j], Ssz, wmma::mem_row_major);
        }
}

__global__ __launch_bounds__(128) void softmax_h(const float* __restrict__ S, __half* __restrict__ P) {
    __shared__ float sh[4];
    long row = blockIdx.x;
    const float* p = S + row * 512;
    __half* o = P + row * 512;
    int t = threadIdx.x;
    float v[4];
    #pragma unroll
    for (int i = 0; i < 4; i++) v[i] = p[t + i * 128];
    float m = fmaxf(fmaxf(v[0], v[1]), fmaxf(v[2], v[3]));
    m = warpMax(m);
    if ((t & 31) == 0) sh[t >> 5] = m;
    __syncthreads();
    if (t < 32) { float a = (t < 4) ? sh[t] : -INFINITY; a = warpMax(a); if (t == 0) sh[0] = a; }
    __syncthreads();
    m = sh[0];
    __syncthreads();
    float s = 0.f;
    #pragma unroll
    for (int i = 0; i < 4; i++) { v[i] = expf(v[i] - m); s += v[i]; }
    s = warpSum(s);
    if ((t & 31) == 0) sh[t >> 5] = s;
    __syncthreads();
    if (t < 32) { float a = (t < 4) ? sh[t] : 0.f; a = warpSum(a); if (t == 0) sh[0] = a; }
    __syncthreads();
    float inv = 1.0f / sh[0];
    #pragma unroll
    for (int i = 0; i < 4; i++) o[t + i * 128] = __float2half_rn(v[i] * inv);
}

#define PV_SPSZ (128 * 72)
#define PV_SVSZ (64 * 72)
static const int SMEMPV_BYTES = (2 * PV_SPSZ + 2 * PV_SVSZ) * 2;   // 55296 B

__global__ __launch_bounds__(256, 2) void pv_h(const __half* __restrict__ ph, const __half* __restrict__ vh,
                                               __half* __restrict__ ob) {
    extern __shared__ __half smp[];
    __half* sP[2] = { smp, smp + PV_SPSZ };
    __half* sV[2] = { smp + 2 * PV_SPSZ, smp + 2 * PV_SPSZ + PV_SVSZ };
    int z = blockIdx.z, b = z >> 4, h = z & 15;
    const __half* Pb = ph + (long)z * Ssz * Ssz;
    const __half* Vb = vh + (long)b * Ssz * INNERn + h * DHn;
    __half* Ob = ob + (long)b * Ssz * INNERn + h * DHn;
    int m0 = blockIdx.y * 128;
    int tid = threadIdx.x;
    int prow = tid >> 1, pcol = (tid & 1) * 32;
    int vrow = tid >> 2, vcol = (tid & 3) * 16;

    #pragma unroll
    for (int i = 0; i < 4; i++) cpa16(sP[0] + prow * 72 + pcol + i * 8, Pb + (long)(m0 + prow) * Ssz + pcol + i * 8);
    #pragma unroll
    for (int i = 0; i < 2; i++) cpa16(sV[0] + vrow * 72 + vcol + i * 8, Vb + (long)vrow * INNERn + vcol + i * 8);
    cp_commit();

    int warp = tid >> 5, wm = warp & 3, wn = warp >> 2;
    HFragC acc[2][2];
    #pragma unroll
    for (int i = 0; i < 2; i++)
        #pragma unroll
        for (int j = 0; j < 2; j++) wmma::fill_fragment(acc[i][j], 0.0f);

    #pragma unroll 1
    for (int it = 0; it < 8; it++) {
        int s = it & 1;
        if (it + 1 < 8) {
            int s2 = s ^ 1, k0 = (it + 1) * 64;
            #pragma unroll
            for (int i = 0; i < 4; i++)
                cpa16(sP[s2] + prow * 72 + pcol + i * 8, Pb + (long)(m0 + prow) * Ssz + k0 + pcol + i * 8);
            #pragma unroll
            for (int i = 0; i < 2; i++)
                cpa16(sV[s2] + vrow * 72 + vcol + i * 8, Vb + (long)(k0 + vrow) * INNERn + vcol + i * 8);
            cp_commit();
            cp_wait<1>();
        } else {
            cp_wait<0>();
        }
        __syncthreads();
        #pragma unroll
        for (int kk = 0; kk < 4; kk++) {
            HFragA af[2];
            #pragma unroll
            for (int i = 0; i < 2; i++)
                wmma::load_matrix_sync(af[i], sP[s] + (wm * 32 + i * 16) * 72 + kk * 16, 72);
            #pragma unroll
            for (int j = 0; j < 2; j++) {
                HFragB bf;
                wmma::load_matrix_sync(bf, sV[s] + (kk * 16) * 72 + wn * 32 + j * 16, 72);
                wmma::mma_sync(acc[0][j], af[0], bf, acc[0][j]);
                wmma::mma_sync(acc[1][j], af[1], bf, acc[1][j]);
            }
        }
        __syncthreads();
    }
    float* stage = (float*)smp + warp * 320;
    int lane = tid & 31, r = lane >> 1, cb = (lane & 1) * 8;
    #pragma unroll
    for (int i = 0; i < 2; i++)
        #pragma unroll
        for (int j = 0; j < 2; j++) {
            wmma::store_matrix_sync(stage, acc[i][j], 20, wmma::mem_row_major);
            __syncwarp();
            int row = m0 + wm * 32 + i * 16 + r;
            int col0 = wn * 32 + j * 16 + cb;
            #pragma unroll
            for (int c = 0; c < 8; c++)
                Ob[(long)row * INNERn + col0 + c] = __float2half_rn(stage[r * 20 + cb + c]);
            __syncwarp();
        }
}

// ---------------- LayerNorm (fp16 outputs) ----------------
__global__ __launch_bounds__(256) void ln3_k(const float* __restrict__ X,
                                             const float* __restrict__ wq, const float* __restrict__ bq,
                                             const float* __restrict__ wk, const float* __restrict__ bk,
                                             const float* __restrict__ wv, const float* __restrict__ bv,
                                             __half* __restrict__ oq, __half* __restrict__ ok,
                                             __half* __restrict__ ov) {
    __shared__ float sh[8];
    long row = blockIdx.x;
    const float* xr = X + row * DIMn;
    int t = threadIdx.x;
    float v[4]; float s = 0.f;
    #pragma unroll
    for (int i = 0; i < 4; i++) { v[i] = xr[t + i * 256]; s += v[i]; }
    s = warpSum(s);
    if ((t & 31) == 0) sh[t >> 5] = s;
    __syncthreads();
    if (t < 32) { float a = (t < 8) ? sh[t] : 0.f; a = warpSum(a); if (t == 0) sh[0] = a; }
    __syncthreads();
    float mean = sh[0] * (1.0f / DIMn);
    __syncthreads();
    float ss = 0.f;
    #pragma unroll
    for (int i = 0; i < 4; i++) { float d = v[i] - mean; ss += d * d; }
    ss = warpSum(ss);
    if ((t & 31) == 0) sh[t >> 5] = ss;
    __syncthreads();
    if (t < 32) { float a = (t < 8) ? sh[t] : 0.f; a = warpSum(a); if (t == 0) sh[0] = a; }
    __syncthreads();
    float rstd = rsqrtf(sh[0] * (1.0f / DIMn) + 1e-5f);
    #pragma unroll
    for (int i = 0; i < 4; i++) {
        int c = t + i * 256;
        float xh = (v[i] - mean) * rstd;
        long idx = row * DIMn + c;
        oq[idx] = __float2half_rn(xh * wq[c] + bq[c]);
        ok[idx] = __float2half_rn(xh * wk[c] + bk[c]);
        ov[idx] = __float2half_rn(xh * wv[c] + bv[c]);
    }
}

__global__ __launch_bounds__(256) void ln1_k(const float* __restrict__ X,
                                             const float* __restrict__ w, const float* __restrict__ b,
                                             __half* __restrict__ out) {
    __shared__ float sh[8];
    long row = blockIdx.x;
    const float* xr = X + row * DIMn;
    int t = threadIdx.x;
    float v[4]; float s = 0.f;
    #pragma unroll
    for (int i = 0; i < 4; i++) { v[i] = xr[t + i * 256]; s += v[i]; }
    s = warpSum(s);
    if ((t & 31) == 0) sh[t >> 5] = s;
    __syncthreads();
    if (t < 32) { float a = (t < 8) ? sh[t] : 0.f; a = warpSum(a); if (t == 0) sh[0] = a; }
    __syncthreads();
    float mean = sh[0] * (1.0f / DIMn);
    __syncthreads();
    float ss = 0.f;
    #pragma unroll
    for (int i = 0; i < 4; i++) { float d = v[i] - mean; ss += d * d; }
    ss = warpSum(ss);
    if ((t & 31) == 0) sh[t >> 5] = ss;
    __syncthreads();
    if (t < 32) { float a = (t < 8) ? sh[t] : 0.f; a = warpSum(a); if (t == 0) sh[0] = a; }
    __syncthreads();
    float rstd = rsqrtf(sh[0] * (1.0f / DIMn) + 1e-5f);
    #pragma unroll
    for (int i = 0; i < 4; i++) {
        int c = t + i * 256;
        long idx = row * DIMn + c;
        out[idx] = __float2half_rn((v[i] - mean) * rstd * w[c] + b[c]);
    }
}

// ---------------- router mean over LR ----------------
__global__ void rimean_k(const float* __restrict__ ri, float* __restrict__ rm) {
    int i = blockIdx.x * 256 + threadIdx.x;
    int b = i >> 10, d = i & 1023;
    float s = 0.f;
    for (int r = 0; r < LRn; r++) s += ri[((long)b * LRn + r) * DIMn + d];
    rm[i] = s * (1.0f / LRn);
}

// ---------------- router logits ----------------
__global__ __launch_bounds__(256) void logits_k(const float* __restrict__ rm,
                                                const float* __restrict__ Wr, const float* __restrict__ br,
                                                const float* __restrict__ Wn, const float* __restrict__ bn,
                                                float* __restrict__ lg, float* __restrict__ nl) {
    __shared__ float sh[16];
    int b = blockIdx.x >> 3, e = blockIdx.x & 7;
    int t = threadIdx.x;
    float s1 = 0.f, s2 = 0.f;
    for (int d = t; d < DIMn; d += 256) {
        float r = rm[b * DIMn + d];
        s1 += r * Wr[(long)d * En + e];
        s2 += r * Wn[(long)d * En + e];
    }
    s1 = warpSum(s1); s2 = warpSum(s2);
    if ((t & 31) == 0) { sh[t >> 5] = s1; sh[8 + (t >> 5)] = s2; }
    __syncthreads();
    if (t == 0) {
        float a = 0.f, c = 0.f;
        for (int i = 0; i < 8; i++) { a += sh[i]; c += sh[8 + i]; }
        lg[blockIdx.x] = a + br[e];
        nl[blockIdx.x] = c + bn[e];
    }
}

// ---------------- noisy top-k routing + capacity + used-expert flags ----------------
__global__ void route_k(const float* __restrict__ logits, const float* __restrict__ nlog, int l,
                        int* __restrict__ fe, float* __restrict__ fw, int* __restrict__ used) {
    __shared__ float sc[64];
    __shared__ int se[16];
    __shared__ float sg[16];
    int t = threadIdx.x;
    if (t < 64) {
        unsigned kk0, kk1;
        tf2x32(0u, 42u, 0u, (unsigned)l, kk0, kk1);
        unsigned o0, o1;
        tf2x32(kk0, kk1, 0u, (unsigned)t, o0, o1);
        unsigned bits = o0 ^ o1;
        float f = __uint_as_float(0x3f800000u | (bits >> 9)) - 1.0f;
        const float lo = -0.99999994f;
        float u = f * 2.0f + lo;
        u = fmaxf(lo, u);
        float g = 1.41421356237309515f * erfinvf(u);
        float xnl = nlog[t];
        float sp = fmaxf(xnl, 0.f) + log1pf(expf(-fabsf(xnl)));
        sc[t] = logits[t] + g * sp;
    }
    __syncthreads();
    if (t < 8) {
        const float* row = sc + t * 8;
        int e0 = 0; float v0 = row[0];
        for (int e = 1; e < 8; e++) if (row[e] > v0) { v0 = row[e]; e0 = e; }
        int e1 = -1; float v1 = -INFINITY;
        for (int e = 0; e < 8; e++) if (e != e0 && row[e] > v1) { v1 = row[e]; e1 = e; }
        float d = expf(v1 - v0);
        float inv = 1.0f / (1.0f + d);
        se[t * 2] = e0; se[t * 2 + 1] = e1;
        sg[t * 2] = inv; sg[t * 2 + 1] = d * inv;
    }
    __syncthreads();
    if (t == 0) {
        int cnt[8] = {0, 0, 0, 0, 0, 0, 0, 0};
        int us[8]  = {0, 0, 0, 0, 0, 0, 0, 0};
        for (int n = 0; n < 16; n++) {
            int e = se[n];
            float w = (cnt[e] < CAPn) ? sg[n] : 0.0f;
            cnt[e]++;
            fe[n] = e; fw[n] = w;
            if (w != 0.0f) us[e] = 1;
        }
        for (int e = 0; e < 8; e++) used[e] = us[e];
    }
}

// ---------------- host launch ----------------
static void conv_w(const float* src, __half* dst, long n) {
    long n4 = n / 4;
    int blocks = (int)((n4 + 255) / 256);
    f2h4<<<blocks, 256>>>((const float4*)src, (__half2*)dst, n4);
}

extern "C" void kernel_launch(void* const* d_in, const int* in_sizes, int n_in,
                              void* d_out, int out_size) {
    (void)in_sizes; (void)n_in; (void)out_size;
    const float* router_input = (const float*)d_in[0];
    const float* x0   = (const float*)d_in[1];
    const float* nq_w = (const float*)d_in[2];
    const float* nq_b = (const float*)d_in[3];
    const float* nk_w = (const float*)d_in[4];
    const float* nk_b = (const float*)d_in[5];
    const float* nv_w = (const float*)d_in[6];
    const float* nv_b = (const float*)d_in[7];
    const float* Wq   = (const float*)d_in[8];
    const float* Wk   = (const float*)d_in[9];
    const float* Wv   = (const float*)d_in[10];
    const float* Wo   = (const float*)d_in[11];
    const float* bo   = (const float*)d_in[12];
    const float* nm_w = (const float*)d_in[13];
    const float* nm_b = (const float*)d_in[14];
    const float* Wr   = (const float*)d_in[15];
    const float* br   = (const float*)d_in[16];
    const float* Wn   = (const float*)d_in[17];
    const float* bn   = (const float*)d_in[18];
    const float* W1   = (const float*)d_in[19];
    const float* b1   = (const float*)d_in[20];
    const float* W2   = (const float*)d_in[21];
    const float* b2   = (const float*)d_in[22];

    float* X = (float*)d_out;
    float* arena = nullptr;
    cudaGetSymbolAddress((void**)&arena, g_arena);
    __half* ha = nullptr;
    cudaGetSymbolAddress((void**)&ha, g_harena);

    float* sc   = arena + O_SC;
    float* rm   = arena + O_RM;
    float* lg   = arena + O_LG;
    float* nl   = arena + O_NL;
    float* fw   = arena + O_FW;
    int*   fe   = (int*)(arena + O_FE);
    int*   used = (int*)(arena + O_USE);

    __half* lnq = ha + H_LNQ;
    __half* lnk = ha + H_LNK;
    __half* lnv = ha + H_LNV;
    __half* xnh = ha + H_XN;
    __half* obh = ha + H_OB;
    __half* qh  = ha + H_Q;
    __half* kh  = ha + H_K;
    __half* vh  = ha + H_V;
    __half* phh = ha + H_P;
    __half* hbh = ha + H_H;
    __half* Wq16 = ha + H_WQ;
    __half* Wk16 = ha + H_WK;
    __half* Wv16 = ha + H_WV;
    __half* Wo16 = ha + H_WO;
    __half* W116 = ha + H_W1;
    __half* W216 = ha + H_W2;

    cudaFuncSetAttribute(qkv_h, cudaFuncAttributeMaxDynamicSharedMemorySize, SMEMH_BYTES);
    cudaFuncSetAttribute(wo_h, cudaFuncAttributeMaxDynamicSharedMemorySize, SMEMH_BYTES);
    cudaFuncSetAttribute(moe1_h, cudaFuncAttributeMaxDynamicSharedMemorySize, SMEMH_BYTES);
    cudaFuncSetAttribute(moe2_h, cudaFuncAttributeMaxDynamicSharedMemorySize, SMEMH_BYTES);
    cudaFuncSetAttribute(pv_h, cudaFuncAttributeMaxDynamicSharedMemorySize, SMEMPV_BYTES);

    // routing first (depends only on router_input) -> used-expert flags
    rimean_k<<<32, 256>>>(router_input, rm);
    for (int l = 0; l < Dlay; l++) {
        logits_k<<<Bn * En, 256>>>(rm, Wr + (long)l * DIMn * En, br + l * En,
                                   Wn + (long)l * DIMn * En, bn + l * En, lg, nl);
        route_k<<<1, 64>>>(lg, nl, l, fe + 16 * l, fw + 16 * l, used + 8 * l);
    }

    // dense weights unconditionally; MoE weights only for used experts
    conv_w(Wq, Wq16, (long)Dlay * DIMn * INNERn);
    conv_w(Wk, Wk16, (long)Dlay * DIMn * INNERn);
    conv_w(Wv, Wv16, (long)Dlay * DIMn * INNERn);
    conv_w(Wo, Wo16, (long)Dlay * INNERn * DIMn);
    {
        long n4_per = (long)DIMn * MLPn / 4;   // 1,048,576 float4 per (layer,expert)
        dim3 g((unsigned)((n4_per + 255) / 256), Dlay * En);
        f2h_sel<<<g, 256>>>((const float4*)W1, (__half2*)W116, used, n4_per);
        f2h_sel<<<g, 256>>>((const float4*)W2, (__half2*)W216, used, n4_per);
    }

    cudaMemcpyAsync(X, x0, sizeof(float) * SZX, cudaMemcpyDeviceToDevice);

    for (int l = 0; l < Dlay; l++) {
        const int* fe_l = fe + 16 * l;
        const float* fw_l = fw + 16 * l;

        ln3_k<<<Bn * Ssz, 256>>>(X, nq_w + l * DIMn, nq_b + l * DIMn,
                                 nk_w + l * DIMn, nk_b + l * DIMn,
                                 nv_w + l * DIMn, nv_b + l * DIMn, lnq, lnk, lnv);

        qkv_h<<<dim3(INNERn / 128, Bn * Ssz / 128, 3), 256, SMEMH_BYTES>>>(
            lnq, lnk, lnv,
            Wq16 + (long)l * DIMn * INNERn, Wk16 + (long)l * DIMn * INNERn,
            Wv16 + (long)l * DIMn * INNERn, qh, kh, vh);

        qk_h<<<dim3(Ssz / 128, Ssz / 128, Bn * Hn), 256>>>(qh, kh, sc);

        softmax_h<<<Bn * Hn * Ssz, 128>>>(sc, phh);

        pv_h<<<dim3(1, Ssz / 128, Bn * Hn), 256, SMEMPV_BYTES>>>(phh, vh, obh);

        wo_h<<<dim3(DIMn / 128, Bn * Ssz / 128), 256, SMEMH_BYTES>>>(
            obh, Wo16 + (long)l * INNERn * DIMn, X, bo + l * DIMn);

        ln1_k<<<Bn * Ssz, 256>>>(X, nm_w + l * DIMn, nm_b + l * DIMn, xnh);
        moe1_h<<<dim3(MLPn / 128, Ssz / 128, Bn * Kn), 256, SMEMH_BYTES>>>(
            xnh, W116 + (long)l * En * DIMn * MLPn, b1 + (long)l * En * MLPn, hbh, fe_l, fw_l);
        moe2_h<<<dim3(DIMn / 128, Ssz / 128, Bn * Kn), 256, SMEMH_BYTES>>>(
            hbh, W216 + (long)l * En * MLPn * DIMn, b2 + (long)l * En * DIMn, X, fe_l, fw_l);
    }
}

// round 13
// speedup vs baseline: 1.1402x; 1.1402x over previous
#include <cuda_runtime.h>
#include <cuda_fp16.h>
#include <math.h>
#include <mma.h>

using namespace nvcuda;

// ---------------- problem constants ----------------
#define Bn     8
#define Ssz    512
#define DIMn   1024
#define Hn     16
#define DHn    64
#define INNERn 1024
#define MLPn   4096
#define En     8
#define Kn     2
#define LRn    77
#define CAPn   2
#define Dlay   2

static const long SZX = (long)Bn * Ssz * DIMn;           // 4,194,304
static const long SZSC = (long)Bn * Hn * Ssz * Ssz;      // 33,554,432
static const long SZH  = (long)Bn * Kn * Ssz * MLPn;     // 33,554,432

// ---- fp32 arena ----
static const long O_SC  = 0;
static const long O_RM  = O_SC + SZSC;
static const long O_LG  = O_RM + 8192;
static const long O_NL  = O_LG + 64;
static const long O_FW  = O_NL + 64;      // 32 floats (2 layers x 16)
static const long O_FE  = O_FW + 32;      // 32 ints
static const long O_USE = O_FE + 32;      // 16 ints (2 layers x 8 experts)
static const long ARENA_FLOATS = O_USE + 32;
__device__ __align__(16) float g_arena[ARENA_FLOATS];

// ---- fp16 arena ----
static const long H_LNQ = 0;
static const long H_LNK = H_LNQ + SZX;
static const long H_LNV = H_LNK + SZX;
static const long H_XN  = H_LNV + SZX;
static const long H_OB  = H_XN  + SZX;
static const long H_Q   = H_OB  + SZX;
static const long H_K   = H_Q   + SZX;
static const long H_V   = H_K   + SZX;
static const long H_P   = H_V   + SZX;            // fp16 attention probs
static const long H_H   = H_P   + SZSC;
static const long H_WQ  = H_H   + SZH;
static const long H_WK  = H_WQ  + (long)Dlay * DIMn * INNERn;
static const long H_WV  = H_WK  + (long)Dlay * DIMn * INNERn;
static const long H_WO  = H_WV  + (long)Dlay * DIMn * INNERn;
static const long H_W1  = H_WO  + (long)Dlay * INNERn * DIMn;
static const long H_W2  = H_W1  + (long)Dlay * En * DIMn * MLPn;
static const long ARENA_HALVES = H_W2 + (long)Dlay * En * MLPn * DIMn;
__device__ __align__(16) __half g_harena[ARENA_HALVES];

// ---------------- reductions ----------------
__device__ __forceinline__ float warpSum(float v) {
    #pragma unroll
    for (int o = 16; o; o >>= 1) v += __shfl_xor_sync(0xffffffffu, v, o);
    return v;
}
__device__ __forceinline__ float warpMax(float v) {
    #pragma unroll
    for (int o = 16; o; o >>= 1) v = fmaxf(v, __shfl_xor_sync(0xffffffffu, v, o));
    return v;
}

// ---------------- threefry2x32 (JAX-exact) ----------------
__device__ __forceinline__ void tf2x32(unsigned k0, unsigned k1, unsigned x0, unsigned x1,
                                       unsigned& o0, unsigned& o1) {
    unsigned ks[3] = {k0, k1, k0 ^ k1 ^ 0x1BD11BDAu};
    const int R0[4] = {13, 15, 26, 6};
    const int R1[4] = {17, 29, 16, 24};
    x0 += ks[0]; x1 += ks[1];
    #pragma unroll
    for (int i = 0; i < 5; i++) {
        #pragma unroll
        for (int r = 0; r < 4; r++) {
            int rot = (i & 1) ? R1[r] : R0[r];
            x0 += x1;
            x1 = (x1 << rot) | (x1 >> (32 - rot));
            x1 ^= x0;
        }
        x0 += ks[(i + 1) % 3];
        x1 += ks[(i + 2) % 3] + (unsigned)(i + 1);
    }
    o0 = x0; o1 = x1;
}

// ---------------- fp32 -> fp16 converts ----------------
__global__ void f2h4(const float4* __restrict__ src, __half2* __restrict__ dst, long n4) {
    long i = (long)blockIdx.x * blockDim.x + threadIdx.x;
    if (i >= n4) return;
    float4 v = src[i];
    dst[2 * i]     = __floats2half2_rn(v.x, v.y);
    dst[2 * i + 1] = __floats2half2_rn(v.z, v.w);
}

// selective per-(layer,expert) conversion; early-exit if expert unused
__global__ void f2h_sel(const float4* __restrict__ src, __half2* __restrict__ dst,
                        const int* __restrict__ used, long n4_per) {
    int e = blockIdx.y;                      // 0..15 = l*8+e
    if (!used[e]) return;
    long i = (long)blockIdx.x * blockDim.x + threadIdx.x;
    if (i >= n4_per) return;
    long idx = (long)e * n4_per + i;
    float4 v = src[idx];
    dst[2 * idx]     = __floats2half2_rn(v.x, v.y);
    dst[2 * idx + 1] = __floats2half2_rn(v.z, v.w);
}

// =================================================================
// fp16 WMMA machinery (r7 double-buffer mainloop — best known)
// =================================================================
using HFragA  = wmma::fragment<wmma::matrix_a, 16, 16, 16, __half, wmma::row_major>;
using HFragB  = wmma::fragment<wmma::matrix_b, 16, 16, 16, __half, wmma::row_major>;
using HFragBc = wmma::fragment<wmma::matrix_b, 16, 16, 16, __half, wmma::col_major>;
using HFragC  = wmma::fragment<wmma::accumulator, 16, 16, 16, float>;

__device__ __forceinline__ void cpa16(void* dst_smem, const void* src) {
    unsigned d = (unsigned)__cvta_generic_to_shared(dst_smem);
    asm volatile("cp.async.cg.shared.global [%0], [%1], 16;\n" :: "r"(d), "l"(src));
}
__device__ __forceinline__ void cp_commit() { asm volatile("cp.async.commit_group;\n"); }
template <int N>
__device__ __forceinline__ void cp_wait() { asm volatile("cp.async.wait_group %0;\n" :: "n"(N)); }

// pack 8 fp32 -> one 16B fp16 store
__device__ __forceinline__ void st_half8(__half* dst, const float* v) {
    __half2 h0 = __floats2half2_rn(v[0], v[1]);
    __half2 h1 = __floats2half2_rn(v[2], v[3]);
    __half2 h2 = __floats2half2_rn(v[4], v[5]);
    __half2 h3 = __floats2half2_rn(v[6], v[7]);
    uint4 u;
    u.x = *(unsigned*)&h0; u.y = *(unsigned*)&h1;
    u.z = *(unsigned*)&h2; u.w = *(unsigned*)&h3;
    *(uint4*)dst = u;
}

#define HA_STR 72
#define HB_STR 136
#define HA_STAGE (128 * HA_STR)
#define HB_STAGE (64 * HB_STR)
static const int SMEMH_BYTES = (2 * HA_STAGE + 2 * HB_STAGE) * 2;  // 71680 B

__device__ __forceinline__ void hmm_cp(const __half* __restrict__ A, const __half* __restrict__ B,
                                       int lda, int ldb, int K, int m0, int n0,
                                       __half* sm, HFragC (&acc)[2][4]) {
    __half* sA[2] = { sm, sm + HA_STAGE };
    __half* sB[2] = { sm + 2 * HA_STAGE, sm + 2 * HA_STAGE + HB_STAGE };
    int tid = threadIdx.x;
    int warp = tid >> 5, wm = warp & 3, wn = warp >> 2;
    int arow = tid >> 1, acH = (tid & 1) * 32;
    int brow = tid >> 2, bcH = (tid & 3) * 32;
    const __half* Ab = A + (long)(m0 + arow) * lda + acH;
    const __half* Bb = B + (long)brow * ldb + n0 + bcH;
    __half* dA[2] = { sA[0] + arow * HA_STR + acH, sA[1] + arow * HA_STR + acH };
    __half* dB[2] = { sB[0] + brow * HB_STR + bcH, sB[1] + brow * HB_STR + bcH };

    int nIt = K >> 6;
    #pragma unroll
    for (int i = 0; i < 4; i++) cpa16(dA[0] + i * 8, Ab + i * 8);
    #pragma unroll
    for (int i = 0; i < 4; i++) cpa16(dB[0] + i * 8, Bb + i * 8);
    cp_commit();

    #pragma unroll 1
    for (int it = 0; it < nIt; it++) {
        int s = it & 1;
        if (it + 1 < nIt) {
            int s2 = s ^ 1;
            const __half* a = Ab + (it + 1) * 64;
            const __half* b = Bb + (long)(it + 1) * 64 * ldb;
            #pragma unroll
            for (int i = 0; i < 4; i++) cpa16(dA[s2] + i * 8, a + i * 8);
            #pragma unroll
            for (int i = 0; i < 4; i++) cpa16(dB[s2] + i * 8, b + i * 8);
            cp_commit();
            cp_wait<1>();
        } else {
            cp_wait<0>();
        }
        __syncthreads();
        #pragma unroll
        for (int kk = 0; kk < 4; kk++) {
            HFragA af[2];
            #pragma unroll
            for (int i = 0; i < 2; i++)
                wmma::load_matrix_sync(af[i], sA[s] + (wm * 32 + i * 16) * HA_STR + kk * 16, HA_STR);
            #pragma unroll
            for (int j = 0; j < 4; j++) {
                HFragB bf;
                wmma::load_matrix_sync(bf, sB[s] + (kk * 16) * HB_STR + wn * 64 + j * 16, HB_STR);
                wmma::mma_sync(acc[0][j], af[0], bf, acc[0][j]);
                wmma::mma_sync(acc[1][j], af[1], bf, acc[1][j]);
            }
        }
        __syncthreads();
    }
}

__device__ __forceinline__ void hacc_zero(HFragC (&acc)[2][4]) {
    #pragma unroll
    for (int i = 0; i < 2; i++)
        #pragma unroll
        for (int j = 0; j < 4; j++) wmma::fill_fragment(acc[i][j], 0.0f);
}

// EPI: 1 = fp32 C += acc + bias (vec128) ; 2 = fp16 C = gelu(acc+bias) (vec128)
//      3 = atomicAdd(fp32 C, (acc+bias)*w) (scalar) ; 4 = fp16 C = acc (vec128)
template <int EPI>
__device__ __forceinline__ void hepilogue(HFragC (&acc)[2][4], float* stage_w,
                                          void* __restrict__ Cv, const float* __restrict__ bias,
                                          int ldc, int m0, int n0, float w) {
    int tid = threadIdx.x, warp = tid >> 5, lane = tid & 31;
    int wm = warp & 3, wn = warp >> 2;
    int r = lane >> 1, cb = (lane & 1) * 8;
    #pragma unroll
    for (int i = 0; i < 2; i++)
        #pragma unroll
        for (int j = 0; j < 4; j++) {
            wmma::store_matrix_sync(stage_w, acc[i][j], 20, wmma::mem_row_major);
            __syncwarp();
            int row = m0 + wm * 32 + i * 16 + r;
            int col0 = n0 + wn * 64 + j * 16 + cb;
            long idx0 = (long)row * ldc + col0;
            float vals[8];
            #pragma unroll
            for (int c = 0; c < 8; c++) vals[c] = stage_w[r * 20 + cb + c];
            if (EPI == 1) {
                float* C = (float*)Cv;
                float4 c0 = *(float4*)(C + idx0);
                float4 c1 = *(float4*)(C + idx0 + 4);
                float4 b0 = *(const float4*)(bias + col0);
                float4 b1 = *(const float4*)(bias + col0 + 4);
                c0.x += vals[0] + b0.x; c0.y += vals[1] + b0.y;
                c0.z += vals[2] + b0.z; c0.w += vals[3] + b0.w;
                c1.x += vals[4] + b1.x; c1.y += vals[5] + b1.y;
                c1.z += vals[6] + b1.z; c1.w += vals[7] + b1.w;
                *(float4*)(C + idx0) = c0;
                *(float4*)(C + idx0 + 4) = c1;
            } else if (EPI == 2) {
                #pragma unroll
                for (int c = 0; c < 8; c++) {
                    float u = vals[c] + bias[col0 + c];
                    vals[c] = 0.5f * u * (1.0f + erff(u * 0.70710678118654752f));
                }
                st_half8((__half*)Cv + idx0, vals);
            } else if (EPI == 3) {
                float* C = (float*)Cv;
                #pragma unroll
                for (int c = 0; c < 8; c++)
                    atomicAdd(&C[idx0 + c], (vals[c] + bias[col0 + c]) * w);
            } else {
                st_half8((__half*)Cv + idx0, vals);
            }
            __syncwarp();
        }
}

// fused QKV (fp16 in, fp16 out)
__global__ __launch_bounds__(256, 2) void qkv_h(const __half* __restrict__ lnq, const __half* __restrict__ lnk,
                                                const __half* __restrict__ lnv,
                                                const __half* __restrict__ Wq, const __half* __restrict__ Wk,
                                                const __half* __restrict__ Wv,
                                                __half* __restrict__ q, __half* __restrict__ k,
                                                __half* __restrict__ v) {
    extern __shared__ __half smh[];
    int z = blockIdx.z;
    const __half* A = (z == 0) ? lnq : (z == 1) ? lnk : lnv;
    const __half* B = (z == 0) ? Wq : (z == 1) ? Wk : Wv;
    __half* C = (z == 0) ? q : (z == 1) ? k : v;
    int m0 = blockIdx.y * 128, n0 = blockIdx.x * 128;
    HFragC acc[2][4];
    hacc_zero(acc);
    hmm_cp(A, B, DIMn, INNERn, DIMn, m0, n0, smh, acc);
    float* stage = (float*)smh + (threadIdx.x >> 5) * 320;
    hepilogue<4>(acc, stage, C, nullptr, INNERn, m0, n0, 0.0f);
}

// X += ob @ Wo + bo
__global__ __launch_bounds__(256, 2) void wo_h(const __half* __restrict__ A, const __half* __restrict__ B,
                                               float* __restrict__ C, const float* __restrict__ bias) {
    extern __shared__ __half smh[];
    int m0 = blockIdx.y * 128, n0 = blockIdx.x * 128;
    HFragC acc[2][4];
    hacc_zero(acc);
    hmm_cp(A, B, INNERn, DIMn, INNERn, m0, n0, smh, acc);
    float* stage = (float*)smh + (threadIdx.x >> 5) * 320;
    hepilogue<1>(acc, stage, C, bias, DIMn, m0, n0, 0.0f);
}

// MoE 1: H16 = gelu(xn16 @ W1[e] + b1[e])
__global__ __launch_bounds__(256, 2) void moe1_h(const __half* __restrict__ xn, const __half* __restrict__ W1l,
                                                 const float* __restrict__ b1l, __half* __restrict__ H,
                                                 const int* __restrict__ fe, const float* __restrict__ fw) {
    extern __shared__ __half smh[];
    int n = blockIdx.z;
    if (fw[n] == 0.0f) return;
    int e = fe[n];
    const __half* A = xn + (long)(n >> 1) * Ssz * DIMn;
    const __half* B = W1l + (long)e * DIMn * MLPn;
    __half* C = H + (long)n * Ssz * MLPn;
    const float* bias = b1l + (long)e * MLPn;
    int m0 = blockIdx.y * 128, n0 = blockIdx.x * 128;
    HFragC acc[2][4];
    hacc_zero(acc);
    hmm_cp(A, B, DIMn, MLPn, DIMn, m0, n0, smh, acc);
    float* stage = (float*)smh + (threadIdx.x >> 5) * 320;
    hepilogue<2>(acc, stage, C, bias, MLPn, m0, n0, 0.0f);
}

// MoE 2: X[slot>>1] += (H16 @ W2[e] + b2[e]) * w
__global__ __launch_bounds__(256, 2) void moe2_h(const __half* __restrict__ H, const __half* __restrict__ W2l,
                                                 const float* __restrict__ b2l, float* __restrict__ X,
                                                 const int* __restrict__ fe, const float* __restrict__ fw) {
    extern __shared__ __half smh[];
    int n = blockIdx.z;
    float w = fw[n];
    if (w == 0.0f) return;
    int e = fe[n];
    const __half* A = H + (long)n * Ssz * MLPn;
    const __half* B = W2l + (long)e * MLPn * DIMn;
    float* C = X + (long)(n >> 1) * Ssz * DIMn;
    const float* bias = b2l + (long)e * DIMn;
    int m0 = blockIdx.y * 128, n0 = blockIdx.x * 128;
    HFragC acc[2][4];
    hacc_zero(acc);
    hmm_cp(A, B, MLPn, DIMn, MLPn, m0, n0, smh, acc);
    float* stage = (float*)smh + (threadIdx.x >> 5) * 320;
    hepilogue<3>(acc, stage, C, bias, DIMn, m0, n0, w);
}

// =================================================================
// Attention (r7 pipeline): QK^T (TC, fp32 scores), softmax (fp32->fp16), PV (TC)
// =================================================================
__global__ __launch_bounds__(256, 2) void qk_h(const __half* __restrict__ qh, const __half* __restrict__ kh,
                                               float* __restrict__ sc) {
    __shared__ __half sQ[128 * 72];
    __shared__ __half sK[128 * 72];
    int z = blockIdx.z, b = z >> 4, h = z & 15;
    const __half* Qb = qh + (long)b * Ssz * INNERn + h * DHn;
    const __half* Kb = kh + (long)b * Ssz * INNERn + h * DHn;
    float* C = sc + (long)z * Ssz * Ssz;
    int m0 = blockIdx.y * 128, n0 = blockIdx.x * 128;
    int tid = threadIdx.x;
    int row = tid >> 1, colH = (tid & 1) * 32;
    #pragma unroll
    for (int i = 0; i < 4; i++) {
        cpa16(sQ + row * 72 + colH + i * 8, Qb + (long)(m0 + row) * INNERn + colH + i * 8);
        cpa16(sK + row * 72 + colH + i * 8, Kb + (long)(n0 + row) * INNERn + colH + i * 8);
    }
    cp_commit(); cp_wait<0>();
    __syncthreads();
    int warp = tid >> 5, wm = warp & 3, wn = warp >> 2;
    HFragC acc[2][4];
    hacc_zero(acc);
    #pragma unroll
    for (int kk = 0; kk < 4; kk++) {
        HFragA af[2];
        #pragma unroll
        for (int i = 0; i < 2; i++)
            wmma::load_matrix_sync(af[i], sQ + (wm * 32 + i * 16) * 72 + kk * 16, 72);
        #pragma unroll
        for (int j = 0; j < 4; j++) {
            HFragBc bf;
            wmma::load_matrix_sync(bf, sK + (wn * 64 + j * 16) * 72 + kk * 16, 72);
            wmma::mma_sync(acc[0][j], af[0], bf, acc[0][j]);
            wmma::mma_sync(acc[1][j], af[1], bf, acc[1][j]);
        }
    }
    #pragma unroll
    for (int i = 0; i < 2; i++)
        #pragma unroll
        for (int j = 0; j < 4; j++) {
            #pragma unroll
            for (int e = 0; e < acc[i][j].num_elements; e++) acc[i][j].x[e] *= 0.125f;
            wmma::store_matrix_sync(&C[(long)(m0 + wm * 32 + i * 16) * Ssz + n0 + wn * 64 + j * 16],
                                    acc[i][j], Ssz, wmma::mem_row_major);
        }
}

__global__ __launch_bounds__(128) void softmax_h(const float* __restrict__ S, __half* __restrict__ P) {
    __shared__ float sh[4];
    long row = blockIdx.x;
    const float* p = S + row * 512;
    __half* o = P + row * 512;
    int t = threadIdx.x;
    float v[4];
    #pragma unroll
    for (int i = 0; i < 4; i++) v[i] = p[t + i * 128];
    float m = fmaxf(fmaxf(v[0], v[1]), fmaxf(v[2], v[3]));
    m = warpMax(m);
    if ((t & 31) == 0) sh[t >> 5] = m;
    __syncthreads();
    if (t < 32) { float a = (t < 4) ? sh[t] : -INFINITY; a = warpMax(a); if (t == 0) sh[0] = a; }
    __syncthreads();
    m = sh[0];
    __syncthreads();
    float s = 0.f;
    #pragma unroll
    for (int i = 0; i < 4; i++) { v[i] = expf(v[i] - m); s += v[i]; }
    s = warpSum(s);
    if ((t & 31) == 0) sh[t >> 5] = s;
    __syncthreads();
    if (t < 32) { float a = (t < 4) ? sh[t] : 0.f; a = warpSum(a); if (t == 0) sh[0] = a; }
    __syncthreads();
    float inv = 1.0f / sh[0];
    #pragma unroll
    for (int i = 0; i < 4; i++) o[t + i * 128] = __float2half_rn(v[i] * inv);
}

#define PV_SPSZ (128 * 72)
#define PV_SVSZ (64 * 72)
static const int SMEMPV_BYTES = (2 * PV_SPSZ + 2 * PV_SVSZ) * 2;   // 55296 B

__global__ __launch_bounds__(256, 2) void pv_h(const __half* __restrict__ ph, const __half* __restrict__ vh,
                                               __half* __restrict__ ob) {
    extern __shared__ __half smp[];
    __half* sP[2] = { smp, smp + PV_SPSZ };
    __half* sV[2] = { smp + 2 * PV_SPSZ, smp + 2 * PV_SPSZ + PV_SVSZ };
    int z = blockIdx.z, b = z >> 4, h = z & 15;
    const __half* Pb = ph + (long)z * Ssz * Ssz;
    const __half* Vb = vh + (long)b * Ssz * INNERn + h * DHn;
    __half* Ob = ob + (long)b * Ssz * INNERn + h * DHn;
    int m0 = blockIdx.y * 128;
    int tid = threadIdx.x;
    int prow = tid >> 1, pcol = (tid & 1) * 32;
    int vrow = tid >> 2, vcol = (tid & 3) * 16;

    #pragma unroll
    for (int i = 0; i < 4; i++) cpa16(sP[0] + prow * 72 + pcol + i * 8, Pb + (long)(m0 + prow) * Ssz + pcol + i * 8);
    #pragma unroll
    for (int i = 0; i < 2; i++) cpa16(sV[0] + vrow * 72 + vcol + i * 8, Vb + (long)vrow * INNERn + vcol + i * 8);
    cp_commit();

    int warp = tid >> 5, wm = warp & 3, wn = warp >> 2;
    HFragC acc[2][2];
    #pragma unroll
    for (int i = 0; i < 2; i++)
        #pragma unroll
        for (int j = 0; j < 2; j++) wmma::fill_fragment(acc[i][j], 0.0f);

    #pragma unroll 1
    for (int it = 0; it < 8; it++) {
        int s = it & 1;
        if (it + 1 < 8) {
            int s2 = s ^ 1, k0 = (it + 1) * 64;
            #pragma unroll
            for (int i = 0; i < 4; i++)
                cpa16(sP[s2] + prow * 72 + pcol + i * 8, Pb + (long)(m0 + prow) * Ssz + k0 + pcol + i * 8);
            #pragma unroll
            for (int i = 0; i < 2; i++)
                cpa16(sV[s2] + vrow * 72 + vcol + i * 8, Vb + (long)(k0 + vrow) * INNERn + vcol + i * 8);
            cp_commit();
            cp_wait<1>();
        } else {
            cp_wait<0>();
        }
        __syncthreads();
        #pragma unroll
        for (int kk = 0; kk < 4; kk++) {
            HFragA af[2];
            #pragma unroll
            for (int i = 0; i < 2; i++)
                wmma::load_matrix_sync(af[i], sP[s] + (wm * 32 + i * 16) * 72 + kk * 16, 72);
            #pragma unroll
            for (int j = 0; j < 2; j++) {
                HFragB bf;
                wmma::load_matrix_sync(bf, sV[s] + (kk * 16) * 72 + wn * 32 + j * 16, 72);
                wmma::mma_sync(acc[0][j], af[0], bf, acc[0][j]);
                wmma::mma_sync(acc[1][j], af[1], bf, acc[1][j]);
            }
        }
        __syncthreads();
    }
    float* stage = (float*)smp + warp * 320;
    int lane = tid & 31, r = lane >> 1, cb = (lane & 1) * 8;
    #pragma unroll
    for (int i = 0; i < 2; i++)
        #pragma unroll
        for (int j = 0; j < 2; j++) {
            wmma::store_matrix_sync(stage, acc[i][j], 20, wmma::mem_row_major);
            __syncwarp();
            int row = m0 + wm * 32 + i * 16 + r;
            int col0 = wn * 32 + j * 16 + cb;
            float vals[8];
            #pragma unroll
            for (int c = 0; c < 8; c++) vals[c] = stage[r * 20 + cb + c];
            st_half8(Ob + (long)row * INNERn + col0, vals);
            __syncwarp();
        }
}

// ---------------- LayerNorm (fp16 outputs) ----------------
__global__ __launch_bounds__(256) void ln3_k(const float* __restrict__ X,
                                             const float* __restrict__ wq, const float* __restrict__ bq,
                                             const float* __restrict__ wk, const float* __restrict__ bk,
                                             const float* __restrict__ wv, const float* __restrict__ bv,
                                             __half* __restrict__ oq, __half* __restrict__ ok,
                                             __half* __restrict__ ov) {
    __shared__ float sh[8];
    long row = blockIdx.x;
    const float* xr = X + row * DIMn;
    int t = threadIdx.x;
    float v[4]; float s = 0.f;
    #pragma unroll
    for (int i = 0; i < 4; i++) { v[i] = xr[t + i * 256]; s += v[i]; }
    s = warpSum(s);
    if ((t & 31) == 0) sh[t >> 5] = s;
    __syncthreads();
    if (t < 32) { float a = (t < 8) ? sh[t] : 0.f; a = warpSum(a); if (t == 0) sh[0] = a; }
    __syncthreads();
    float mean = sh[0] * (1.0f / DIMn);
    __syncthreads();
    float ss = 0.f;
    #pragma unroll
    for (int i = 0; i < 4; i++) { float d = v[i] - mean; ss += d * d; }
    ss = warpSum(ss);
    if ((t & 31) == 0) sh[t >> 5] = ss;
    __syncthreads();
    if (t < 32) { float a = (t < 8) ? sh[t] : 0.f; a = warpSum(a); if (t == 0) sh[0] = a; }
    __syncthreads();
    float rstd = rsqrtf(sh[0] * (1.0f / DIMn) + 1e-5f);
    #pragma unroll
    for (int i = 0; i < 4; i++) {
        int c = t + i * 256;
        float xh = (v[i] - mean) * rstd;
        long idx = row * DIMn + c;
        oq[idx] = __float2half_rn(xh * wq[c] + bq[c]);
        ok[idx] = __float2half_rn(xh * wk[c] + bk[c]);
        ov[idx] = __float2half_rn(xh * wv[c] + bv[c]);
    }
}

__global__ __launch_bounds__(256) void ln1_k(const float* __restrict__ X,
                                             const float* __restrict__ w, const float* __restrict__ b,
                                             __half* __restrict__ out) {
    __shared__ float sh[8];
    long row = blockIdx.x;
    const float* xr = X + row * DIMn;
    int t = threadIdx.x;
    float v[4]; float s = 0.f;
    #pragma unroll
    for (int i = 0; i < 4; i++) { v[i] = xr[t + i * 256]; s += v[i]; }
    s = warpSum(s);
    if ((t & 31) == 0) sh[t >> 5] = s;
    __syncthreads();
    if (t < 32) { float a = (t < 8) ? sh[t] : 0.f; a = warpSum(a); if (t == 0) sh[0] = a; }
    __syncthreads();
    float mean = sh[0] * (1.0f / DIMn);
    __syncthreads();
    float ss = 0.f;
    #pragma unroll
    for (int i = 0; i < 4; i++) { float d = v[i] - mean; ss += d * d; }
    ss = warpSum(ss);
    if ((t & 31) == 0) sh[t >> 5] = ss;
    __syncthreads();
    if (t < 32) { float a = (t < 8) ? sh[t] : 0.f; a = warpSum(a); if (t == 0) sh[0] = a; }
    __syncthreads();
    float rstd = rsqrtf(sh[0] * (1.0f / DIMn) + 1e-5f);
    #pragma unroll
    for (int i = 0; i < 4; i++) {
        int c = t + i * 256;
        long idx = row * DIMn + c;
        out[idx] = __float2half_rn((v[i] - mean) * rstd * w[c] + b[c]);
    }
}

// ---------------- router mean over LR ----------------
__global__ void rimean_k(const float* __restrict__ ri, float* __restrict__ rm) {
    int i = blockIdx.x * 256 + threadIdx.x;
    int b = i >> 10, d = i & 1023;
    float s = 0.f;
    for (int r = 0; r < LRn; r++) s += ri[((long)b * LRn + r) * DIMn + d];
    rm[i] = s * (1.0f / LRn);
}

// ---------------- router logits ----------------
__global__ __launch_bounds__(256) void logits_k(const float* __restrict__ rm,
                                                const float* __restrict__ Wr, const float* __restrict__ br,
                                                const float* __restrict__ Wn, const float* __restrict__ bn,
                                                float* __restrict__ lg, float* __restrict__ nl) {
    __shared__ float sh[16];
    int b = blockIdx.x >> 3, e = blockIdx.x & 7;
    int t = threadIdx.x;
    float s1 = 0.f, s2 = 0.f;
    for (int d = t; d < DIMn; d += 256) {
        float r = rm[b * DIMn + d];
        s1 += r * Wr[(long)d * En + e];
        s2 += r * Wn[(long)d * En + e];
    }
    s1 = warpSum(s1); s2 = warpSum(s2);
    if ((t & 31) == 0) { sh[t >> 5] = s1; sh[8 + (t >> 5)] = s2; }
    __syncthreads();
    if (t == 0) {
        float a = 0.f, c = 0.f;
        for (int i = 0; i < 8; i++) { a += sh[i]; c += sh[8 + i]; }
        lg[blockIdx.x] = a + br[e];
        nl[blockIdx.x] = c + bn[e];
    }
}

// ---------------- noisy top-k routing + capacity + used-expert flags ----------------
__global__ void route_k(const float* __restrict__ logits, const float* __restrict__ nlog, int l,
                        int* __restrict__ fe, float* __restrict__ fw, int* __restrict__ used) {
    __shared__ float sc[64];
    __shared__ int se[16];
    __shared__ float sg[16];
    int t = threadIdx.x;
    if (t < 64) {
        unsigned kk0, kk1;
        tf2x32(0u, 42u, 0u, (unsigned)l, kk0, kk1);
        unsigned o0, o1;
        tf2x32(kk0, kk1, 0u, (unsigned)t, o0, o1);
        unsigned bits = o0 ^ o1;
        float f = __uint_as_float(0x3f800000u | (bits >> 9)) - 1.0f;
        const float lo = -0.99999994f;
        float u = f * 2.0f + lo;
        u = fmaxf(lo, u);
        float g = 1.41421356237309515f * erfinvf(u);
        float xnl = nlog[t];
        float sp = fmaxf(xnl, 0.f) + log1pf(expf(-fabsf(xnl)));
        sc[t] = logits[t] + g * sp;
    }
    __syncthreads();
    if (t < 8) {
        const float* row = sc + t * 8;
        int e0 = 0; float v0 = row[0];
        for (int e = 1; e < 8; e++) if (row[e] > v0) { v0 = row[e]; e0 = e; }
        int e1 = -1; float v1 = -INFINITY;
        for (int e = 0; e < 8; e++) if (e != e0 && row[e] > v1) { v1 = row[e]; e1 = e; }
        float d = expf(v1 - v0);
        float inv = 1.0f / (1.0f + d);
        se[t * 2] = e0; se[t * 2 + 1] = e1;
        sg[t * 2] = inv; sg[t * 2 + 1] = d * inv;
    }
    __syncthreads();
    if (t == 0) {
        int cnt[8] = {0, 0, 0, 0, 0, 0, 0, 0};
        int us[8]  = {0, 0, 0, 0, 0, 0, 0, 0};
        for (int n = 0; n < 16; n++) {
            int e = se[n];
            float w = (cnt[e] < CAPn) ? sg[n] : 0.0f;
            cnt[e]++;
            fe[n] = e; fw[n] = w;
            if (w != 0.0f) us[e] = 1;
        }
        for (int e = 0; e < 8; e++) used[e] = us[e];
    }
}

// ---------------- host launch ----------------
static void conv_w(const float* src, __half* dst, long n) {
    long n4 = n / 4;
    int blocks = (int)((n4 + 255) / 256);
    f2h4<<<blocks, 256>>>((const float4*)src, (__half2*)dst, n4);
}

extern "C" void kernel_launch(void* const* d_in, const int* in_sizes, int n_in,
                              void* d_out, int out_size) {
    (void)in_sizes; (void)n_in; (void)out_size;
    const float* router_input = (const float*)d_in[0];
    const float* x0   = (const float*)d_in[1];
    const float* nq_w = (const float*)d_in[2];
    const float* nq_b = (const float*)d_in[3];
    const float* nk_w = (const float*)d_in[4];
    const float* nk_b = (const float*)d_in[5];
    const float* nv_w = (const float*)d_in[6];
    const float* nv_b = (const float*)d_in[7];
    const float* Wq   = (const float*)d_in[8];
    const float* Wk   = (const float*)d_in[9];
    const float* Wv   = (const float*)d_in[10];
    const float* Wo   = (const float*)d_in[11];
    const float* bo   = (const float*)d_in[12];
    const float* nm_w = (const float*)d_in[13];
    const float* nm_b = (const float*)d_in[14];
    const float* Wr   = (const float*)d_in[15];
    const float* br   = (const float*)d_in[16];
    const float* Wn   = (const float*)d_in[17];
    const float* bn   = (const float*)d_in[18];
    const float* W1   = (const float*)d_in[19];
    const float* b1   = (const float*)d_in[20];
    const float* W2   = (const float*)d_in[21];
    const float* b2   = (const float*)d_in[22];

    float* X = (float*)d_out;
    float* arena = nullptr;
    cudaGetSymbolAddress((void**)&arena, g_arena);
    __half* ha = nullptr;
    cudaGetSymbolAddress((void**)&ha, g_harena);

    float* sc   = arena + O_SC;
    float* rm   = arena + O_RM;
    float* lg   = arena + O_LG;
    float* nl   = arena + O_NL;
    float* fw   = arena + O_FW;
    int*   fe   = (int*)(arena + O_FE);
    int*   used = (int*)(arena + O_USE);

    __half* lnq = ha + H_LNQ;
    __half* lnk = ha + H_LNK;
    __half* lnv = ha + H_LNV;
    __half* xnh = ha + H_XN;
    __half* obh = ha + H_OB;
    __half* qh  = ha + H_Q;
    __half* kh  = ha + H_K;
    __half* vh  = ha + H_V;
    __half* phh = ha + H_P;
    __half* hbh = ha + H_H;
    __half* Wq16 = ha + H_WQ;
    __half* Wk16 = ha + H_WK;
    __half* Wv16 = ha + H_WV;
    __half* Wo16 = ha + H_WO;
    __half* W116 = ha + H_W1;
    __half* W216 = ha + H_W2;

    cudaFuncSetAttribute(qkv_h, cudaFuncAttributeMaxDynamicSharedMemorySize, SMEMH_BYTES);
    cudaFuncSetAttribute(wo_h, cudaFuncAttributeMaxDynamicSharedMemorySize, SMEMH_BYTES);
    cudaFuncSetAttribute(moe1_h, cudaFuncAttributeMaxDynamicSharedMemorySize, SMEMH_BYTES);
    cudaFuncSetAttribute(moe2_h, cudaFuncAttributeMaxDynamicSharedMemorySize, SMEMH_BYTES);
    cudaFuncSetAttribute(pv_h, cudaFuncAttributeMaxDynamicSharedMemorySize, SMEMPV_BYTES);

    // routing first (depends only on router_input) -> used-expert flags
    rimean_k<<<32, 256>>>(router_input, rm);
    for (int l = 0; l < Dlay; l++) {
        logits_k<<<Bn * En, 256>>>(rm, Wr + (long)l * DIMn * En, br + l * En,
                                   Wn + (long)l * DIMn * En, bn + l * En, lg, nl);
        route_k<<<1, 64>>>(lg, nl, l, fe + 16 * l, fw + 16 * l, used + 8 * l);
    }

    // dense weights unconditionally; MoE weights only for used experts
    conv_w(Wq, Wq16, (long)Dlay * DIMn * INNERn);
    conv_w(Wk, Wk16, (long)Dlay * DIMn * INNERn);
    conv_w(Wv, Wv16, (long)Dlay * DIMn * INNERn);
    conv_w(Wo, Wo16, (long)Dlay * INNERn * DIMn);
    {
        long n4_per = (long)DIMn * MLPn / 4;   // 1,048,576 float4 per (layer,expert)
        dim3 g((unsigned)((n4_per + 255) / 256), Dlay * En);
        f2h_sel<<<g, 256>>>((const float4*)W1, (__half2*)W116, used, n4_per);
        f2h_sel<<<g, 256>>>((const float4*)W2, (__half2*)W216, used, n4_per);
    }

    cudaMemcpyAsync(X, x0, sizeof(float) * SZX, cudaMemcpyDeviceToDevice);

    for (int l = 0; l < Dlay; l++) {
        const int* fe_l = fe + 16 * l;
        const float* fw_l = fw + 16 * l;

        ln3_k<<<Bn * Ssz, 256>>>(X, nq_w + l * DIMn, nq_b + l * DIMn,
                                 nk_w + l * DIMn, nk_b + l * DIMn,
                                 nv_w + l * DIMn, nv_b + l * DIMn, lnq, lnk, lnv);

        qkv_h<<<dim3(INNERn / 128, Bn * Ssz / 128, 3), 256, SMEMH_BYTES>>>(
            lnq, lnk, lnv,
            Wq16 + (long)l * DIMn * INNERn, Wk16 + (long)l * DIMn * INNERn,
            Wv16 + (long)l * DIMn * INNERn, qh, kh, vh);

        qk_h<<<dim3(Ssz / 128, Ssz / 128, Bn * Hn), 256>>>(qh, kh, sc);

        softmax_h<<<Bn * Hn * Ssz, 128>>>(sc, phh);

        pv_h<<<dim3(1, Ssz / 128, Bn * Hn), 256, SMEMPV_BYTES>>>(phh, vh, obh);

        wo_h<<<dim3(DIMn / 128, Bn * Ssz / 128), 256, SMEMH_BYTES>>>(
            obh, Wo16 + (long)l * INNERn * DIMn, X, bo + l * DIMn);

        ln1_k<<<Bn * Ssz, 256>>>(X, nm_w + l * DIMn, nm_b + l * DIMn, xnh);
        moe1_h<<<dim3(MLPn / 128, Ssz / 128, Bn * Kn), 256, SMEMH_BYTES>>>(
            xnh, W116 + (long)l * En * DIMn * MLPn, b1 + (long)l * En * MLPn, hbh, fe_l, fw_l);
        moe2_h<<<dim3(DIMn / 128, Ssz / 128, Bn * Kn), 256, SMEMH_BYTES>>>(
            hbh, W216 + (long)l * En * MLPn * DIMn, b2 + (long)l * En * DIMn, X, fe_l, fw_l);
    }
}

// round 14
// speedup vs baseline: 1.1436x; 1.0030x over previous
#include <cuda_runtime.h>
#include <cuda_fp16.h>
#include <math.h>
#include <mma.h>

using namespace nvcuda;

// ---------------- problem constants ----------------
#define Bn     8
#define Ssz    512
#define DIMn   1024
#define Hn     16
#define DHn    64
#define INNERn 1024
#define MLPn   4096
#define En     8
#define Kn     2
#define LRn    77
#define CAPn   2
#define Dlay   2

static const long SZX = (long)Bn * Ssz * DIMn;           // 4,194,304
static const long SZSC = (long)Bn * Hn * Ssz * Ssz;      // 33,554,432
static const long SZH  = (long)Bn * Kn * Ssz * MLPn;     // 33,554,432

// ---- fp32 arena (routing only now) ----
static const long O_RM  = 0;
static const long O_LG  = O_RM + 8192;
static const long O_NL  = O_LG + 64;
static const long O_FW  = O_NL + 64;      // 32 floats (2 layers x 16)
static const long O_FE  = O_FW + 32;      // 32 ints
static const long O_USE = O_FE + 32;      // 16 ints (2 layers x 8 experts)
static const long ARENA_FLOATS = O_USE + 32;
__device__ __align__(16) float g_arena[ARENA_FLOATS];

// ---- fp16 arena ----
static const long H_LNQ = 0;
static const long H_LNK = H_LNQ + SZX;
static const long H_LNV = H_LNK + SZX;
static const long H_XN  = H_LNV + SZX;
static const long H_OB  = H_XN  + SZX;
static const long H_Q   = H_OB  + SZX;
static const long H_K   = H_Q   + SZX;
static const long H_V   = H_K   + SZX;
static const long H_S   = H_V   + SZX;            // fp16 scores
static const long H_P   = H_S   + SZSC;           // fp16 probs
static const long H_H   = H_P   + SZSC;
static const long H_WQ  = H_H   + SZH;
static const long H_WK  = H_WQ  + (long)Dlay * DIMn * INNERn;
static const long H_WV  = H_WK  + (long)Dlay * DIMn * INNERn;
static const long H_WO  = H_WV  + (long)Dlay * DIMn * INNERn;
static const long H_W1  = H_WO  + (long)Dlay * INNERn * DIMn;
static const long H_W2  = H_W1  + (long)Dlay * En * DIMn * MLPn;
static const long ARENA_HALVES = H_W2 + (long)Dlay * En * MLPn * DIMn;
__device__ __align__(16) __half g_harena[ARENA_HALVES];

// ---------------- reductions ----------------
__device__ __forceinline__ float warpSum(float v) {
    #pragma unroll
    for (int o = 16; o; o >>= 1) v += __shfl_xor_sync(0xffffffffu, v, o);
    return v;
}
__device__ __forceinline__ float warpMax(float v) {
    #pragma unroll
    for (int o = 16; o; o >>= 1) v = fmaxf(v, __shfl_xor_sync(0xffffffffu, v, o));
    return v;
}

// ---------------- threefry2x32 (JAX-exact) ----------------
__device__ __forceinline__ void tf2x32(unsigned k0, unsigned k1, unsigned x0, unsigned x1,
                                       unsigned& o0, unsigned& o1) {
    unsigned ks[3] = {k0, k1, k0 ^ k1 ^ 0x1BD11BDAu};
    const int R0[4] = {13, 15, 26, 6};
    const int R1[4] = {17, 29, 16, 24};
    x0 += ks[0]; x1 += ks[1];
    #pragma unroll
    for (int i = 0; i < 5; i++) {
        #pragma unroll
        for (int r = 0; r < 4; r++) {
            int rot = (i & 1) ? R1[r] : R0[r];
            x0 += x1;
            x1 = (x1 << rot) | (x1 >> (32 - rot));
            x1 ^= x0;
        }
        x0 += ks[(i + 1) % 3];
        x1 += ks[(i + 2) % 3] + (unsigned)(i + 1);
    }
    o0 = x0; o1 = x1;
}

// ---------------- fp32 -> fp16 converts ----------------
__global__ void f2h4(const float4* __restrict__ src, __half2* __restrict__ dst, long n4) {
    long i = (long)blockIdx.x * blockDim.x + threadIdx.x;
    if (i >= n4) return;
    float4 v = src[i];
    dst[2 * i]     = __floats2half2_rn(v.x, v.y);
    dst[2 * i + 1] = __floats2half2_rn(v.z, v.w);
}

// selective per-(layer,expert) conversion; early-exit if expert unused
__global__ void f2h_sel(const float4* __restrict__ src, __half2* __restrict__ dst,
                        const int* __restrict__ used, long n4_per) {
    int e = blockIdx.y;                      // 0..15 = l*8+e
    if (!used[e]) return;
    long i = (long)blockIdx.x * blockDim.x + threadIdx.x;
    if (i >= n4_per) return;
    long idx = (long)e * n4_per + i;
    float4 v = src[idx];
    dst[2 * idx]     = __floats2half2_rn(v.x, v.y);
    dst[2 * idx + 1] = __floats2half2_rn(v.z, v.w);
}

// =================================================================
// fp16 WMMA machinery
// =================================================================
using HFragA  = wmma::fragment<wmma::matrix_a, 16, 16, 16, __half, wmma::row_major>;
using HFragB  = wmma::fragment<wmma::matrix_b, 16, 16, 16, __half, wmma::row_major>;
using HFragBc = wmma::fragment<wmma::matrix_b, 16, 16, 16, __half, wmma::col_major>;
using HFragC  = wmma::fragment<wmma::accumulator, 16, 16, 16, float>;

__device__ __forceinline__ void cpa16(void* dst_smem, const void* src) {
    unsigned d = (unsigned)__cvta_generic_to_shared(dst_smem);
    asm volatile("cp.async.cg.shared.global [%0], [%1], 16;\n" :: "r"(d), "l"(src));
}
__device__ __forceinline__ void cp_commit() { asm volatile("cp.async.commit_group;\n"); }
template <int N>
__device__ __forceinline__ void cp_wait() { asm volatile("cp.async.wait_group %0;\n" :: "n"(N)); }

// pack 8 fp32 -> one 16B fp16 store
__device__ __forceinline__ void st_half8(__half* dst, const float* v) {
    __half2 h0 = __floats2half2_rn(v[0], v[1]);
    __half2 h1 = __floats2half2_rn(v[2], v[3]);
    __half2 h2 = __floats2half2_rn(v[4], v[5]);
    __half2 h3 = __floats2half2_rn(v[6], v[7]);
    uint4 u;
    u.x = *(unsigned*)&h0; u.y = *(unsigned*)&h1;
    u.z = *(unsigned*)&h2; u.w = *(unsigned*)&h3;
    *(uint4*)dst = u;
}

#define HA_STR 72
#define HB_STR 136
#define HA_STAGE (128 * HA_STR)
#define HB_STAGE (64 * HB_STR)
static const int SMEMH_BYTES = (2 * HA_STAGE + 2 * HB_STAGE) * 2;  // 71680 B

__device__ __forceinline__ void hmm_cp(const __half* __restrict__ A, const __half* __restrict__ B,
                                       int lda, int ldb, int K, int m0, int n0,
                                       __half* sm, HFragC (&acc)[2][4]) {
    __half* sA[2] = { sm, sm + HA_STAGE };
    __half* sB[2] = { sm + 2 * HA_STAGE, sm + 2 * HA_STAGE + HB_STAGE };
    int tid = threadIdx.x;
    int warp = tid >> 5, wm = warp & 3, wn = warp >> 2;
    int arow = tid >> 1, acH = (tid & 1) * 32;
    int brow = tid >> 2, bcH = (tid & 3) * 32;
    const __half* Ab = A + (long)(m0 + arow) * lda + acH;
    const __half* Bb = B + (long)brow * ldb + n0 + bcH;
    __half* dA[2] = { sA[0] + arow * HA_STR + acH, sA[1] + arow * HA_STR + acH };
    __half* dB[2] = { sB[0] + brow * HB_STR + bcH, sB[1] + brow * HB_STR + bcH };

    int nIt = K >> 6;
    #pragma unroll
    for (int i = 0; i < 4; i++) cpa16(dA[0] + i * 8, Ab + i * 8);
    #pragma unroll
    for (int i = 0; i < 4; i++) cpa16(dB[0] + i * 8, Bb + i * 8);
    cp_commit();

    #pragma unroll 1
    for (int it = 0; it < nIt; it++) {
        int s = it & 1;
        if (it + 1 < nIt) {
            int s2 = s ^ 1;
            const __half* a = Ab + (it + 1) * 64;
            const __half* b = Bb + (long)(it + 1) * 64 * ldb;
            #pragma unroll
            for (int i = 0; i < 4; i++) cpa16(dA[s2] + i * 8, a + i * 8);
            #pragma unroll
            for (int i = 0; i < 4; i++) cpa16(dB[s2] + i * 8, b + i * 8);
            cp_commit();
            cp_wait<1>();
        } else {
            cp_wait<0>();
        }
        __syncthreads();
        #pragma unroll
        for (int kk = 0; kk < 4; kk++) {
            HFragA af[2];
            #pragma unroll
            for (int i = 0; i < 2; i++)
                wmma::load_matrix_sync(af[i], sA[s] + (wm * 32 + i * 16) * HA_STR + kk * 16, HA_STR);
            #pragma unroll
            for (int j = 0; j < 4; j++) {
                HFragB bf;
                wmma::load_matrix_sync(bf, sB[s] + (kk * 16) * HB_STR + wn * 64 + j * 16, HB_STR);
                wmma::mma_sync(acc[0][j], af[0], bf, acc[0][j]);
                wmma::mma_sync(acc[1][j], af[1], bf, acc[1][j]);
            }
        }
        __syncthreads();
    }
}

__device__ __forceinline__ void hacc_zero(HFragC (&acc)[2][4]) {
    #pragma unroll
    for (int i = 0; i < 2; i++)
        #pragma unroll
        for (int j = 0; j < 4; j++) wmma::fill_fragment(acc[i][j], 0.0f);
}

// EPI: 1 = fp32 C += acc + bias (vec128) ; 2 = fp16 C = gelu(acc+bias) (vec128)
//      3 = atomicAdd(fp32 C, (acc+bias)*w) (scalar) ; 4 = fp16 C = acc (vec128)
template <int EPI>
__device__ __forceinline__ void hepilogue(HFragC (&acc)[2][4], float* stage_w,
                                          void* __restrict__ Cv, const float* __restrict__ bias,
                                          int ldc, int m0, int n0, float w) {
    int tid = threadIdx.x, warp = tid >> 5, lane = tid & 31;
    int wm = warp & 3, wn = warp >> 2;
    int r = lane >> 1, cb = (lane & 1) * 8;
    #pragma unroll
    for (int i = 0; i < 2; i++)
        #pragma unroll
        for (int j = 0; j < 4; j++) {
            wmma::store_matrix_sync(stage_w, acc[i][j], 20, wmma::mem_row_major);
            __syncwarp();
            int row = m0 + wm * 32 + i * 16 + r;
            int col0 = n0 + wn * 64 + j * 16 + cb;
            long idx0 = (long)row * ldc + col0;
            float vals[8];
            #pragma unroll
            for (int c = 0; c < 8; c++) vals[c] = stage_w[r * 20 + cb + c];
            if (EPI == 1) {
                float* C = (float*)Cv;
                float4 c0 = *(float4*)(C + idx0);
                float4 c1 = *(float4*)(C + idx0 + 4);
                float4 b0 = *(const float4*)(bias + col0);
                float4 b1 = *(const float4*)(bias + col0 + 4);
                c0.x += vals[0] + b0.x; c0.y += vals[1] + b0.y;
                c0.z += vals[2] + b0.z; c0.w += vals[3] + b0.w;
                c1.x += vals[4] + b1.x; c1.y += vals[5] + b1.y;
                c1.z += vals[6] + b1.z; c1.w += vals[7] + b1.w;
                *(float4*)(C + idx0) = c0;
                *(float4*)(C + idx0 + 4) = c1;
            } else if (EPI == 2) {
                #pragma unroll
                for (int c = 0; c < 8; c++) {
                    float u = vals[c] + bias[col0 + c];
                    vals[c] = 0.5f * u * (1.0f + erff(u * 0.70710678118654752f));
                }
                st_half8((__half*)Cv + idx0, vals);
            } else if (EPI == 3) {
                float* C = (float*)Cv;
                #pragma unroll
                for (int c = 0; c < 8; c++)
                    atomicAdd(&C[idx0 + c], (vals[c] + bias[col0 + c]) * w);
            } else {
                st_half8((__half*)Cv + idx0, vals);
            }
            __syncwarp();
        }
}

// fused QKV (fp16 in, fp16 out)
__global__ __launch_bounds__(256, 2) void qkv_h(const __half* __restrict__ lnq, const __half* __restrict__ lnk,
                                                const __half* __restrict__ lnv,
                                                const __half* __restrict__ Wq, const __half* __restrict__ Wk,
                                                const __half* __restrict__ Wv,
                                                __half* __restrict__ q, __half* __restrict__ k,
                                                __half* __restrict__ v) {
    extern __shared__ __half smh[];
    int z = blockIdx.z;
    const __half* A = (z == 0) ? lnq : (z == 1) ? lnk : lnv;
    const __half* B = (z == 0) ? Wq : (z == 1) ? Wk : Wv;
    __half* C = (z == 0) ? q : (z == 1) ? k : v;
    int m0 = blockIdx.y * 128, n0 = blockIdx.x * 128;
    HFragC acc[2][4];
    hacc_zero(acc);
    hmm_cp(A, B, DIMn, INNERn, DIMn, m0, n0, smh, acc);
    float* stage = (float*)smh + (threadIdx.x >> 5) * 320;
    hepilogue<4>(acc, stage, C, nullptr, INNERn, m0, n0, 0.0f);
}

// X += ob @ Wo + bo
__global__ __launch_bounds__(256, 2) void wo_h(const __half* __restrict__ A, const __half* __restrict__ B,
                                               float* __restrict__ C, const float* __restrict__ bias) {
    extern __shared__ __half smh[];
    int m0 = blockIdx.y * 128, n0 = blockIdx.x * 128;
    HFragC acc[2][4];
    hacc_zero(acc);
    hmm_cp(A, B, INNERn, DIMn, INNERn, m0, n0, smh, acc);
    float* stage = (float*)smh + (threadIdx.x >> 5) * 320;
    hepilogue<1>(acc, stage, C, bias, DIMn, m0, n0, 0.0f);
}

// MoE 1: H16 = gelu(xn16 @ W1[e] + b1[e])
__global__ __launch_bounds__(256, 2) void moe1_h(const __half* __restrict__ xn, const __half* __restrict__ W1l,
                                                 const float* __restrict__ b1l, __half* __restrict__ H,
                                                 const int* __restrict__ fe, const float* __restrict__ fw) {
    extern __shared__ __half smh[];
    int n = blockIdx.z;
    if (fw[n] == 0.0f) return;
    int e = fe[n];
    const __half* A = xn + (long)(n >> 1) * Ssz * DIMn;
    const __half* B = W1l + (long)e * DIMn * MLPn;
    __half* C = H + (long)n * Ssz * MLPn;
    const float* bias = b1l + (long)e * MLPn;
    int m0 = blockIdx.y * 128, n0 = blockIdx.x * 128;
    HFragC acc[2][4];
    hacc_zero(acc);
    hmm_cp(A, B, DIMn, MLPn, DIMn, m0, n0, smh, acc);
    float* stage = (float*)smh + (threadIdx.x >> 5) * 320;
    hepilogue<2>(acc, stage, C, bias, MLPn, m0, n0, 0.0f);
}

// MoE 2: X[slot>>1] += (H16 @ W2[e] + b2[e]) * w
__global__ __launch_bounds__(256, 2) void moe2_h(const __half* __restrict__ H, const __half* __restrict__ W2l,
                                                 const float* __restrict__ b2l, float* __restrict__ X,
                                                 const int* __restrict__ fe, const float* __restrict__ fw) {
    extern __shared__ __half smh[];
    int n = blockIdx.z;
    float w = fw[n];
    if (w == 0.0f) return;
    int e = fe[n];
    const __half* A = H + (long)n * Ssz * MLPn;
    const __half* B = W2l + (long)e * MLPn * DIMn;
    float* C = X + (long)(n >> 1) * Ssz * DIMn;
    const float* bias = b2l + (long)e * DIMn;
    int m0 = blockIdx.y * 128, n0 = blockIdx.x * 128;
    HFragC acc[2][4];
    hacc_zero(acc);
    hmm_cp(A, B, MLPn, DIMn, MLPn, m0, n0, smh, acc);
    float* stage = (float*)smh + (threadIdx.x >> 5) * 320;
    hepilogue<3>(acc, stage, C, bias, DIMn, m0, n0, w);
}

// =================================================================
// Attention: QK^T (fp16 scores, vectorized epilogue), softmax (vec fp16), PV
// =================================================================
__global__ __launch_bounds__(256, 2) void qk_h(const __half* __restrict__ qh, const __half* __restrict__ kh,
                                               __half* __restrict__ sc) {
    __shared__ __half sQ[128 * 72];
    __shared__ __half sK[128 * 72];
    int z = blockIdx.z, b = z >> 4, h = z & 15;
    const __half* Qb = qh + (long)b * Ssz * INNERn + h * DHn;
    const __half* Kb = kh + (long)b * Ssz * INNERn + h * DHn;
    __half* C = sc + (long)z * Ssz * Ssz;
    int m0 = blockIdx.y * 128, n0 = blockIdx.x * 128;
    int tid = threadIdx.x;
    int row = tid >> 1, colH = (tid & 1) * 32;
    #pragma unroll
    for (int i = 0; i < 4; i++) {
        cpa16(sQ + row * 72 + colH + i * 8, Qb + (long)(m0 + row) * INNERn + colH + i * 8);
        cpa16(sK + row * 72 + colH + i * 8, Kb + (long)(n0 + row) * INNERn + colH + i * 8);
    }
    cp_commit(); cp_wait<0>();
    __syncthreads();
    int warp = tid >> 5, wm = warp & 3, wn = warp >> 2;
    HFragC acc[2][4];
    hacc_zero(acc);
    #pragma unroll
    for (int kk = 0; kk < 4; kk++) {
        HFragA af[2];
        #pragma unroll
        for (int i = 0; i < 2; i++)
            wmma::load_matrix_sync(af[i], sQ + (wm * 32 + i * 16) * 72 + kk * 16, 72);
        #pragma unroll
        for (int j = 0; j < 4; j++) {
            HFragBc bf;
            wmma::load_matrix_sync(bf, sK + (wn * 64 + j * 16) * 72 + kk * 16, 72);
            wmma::mma_sync(acc[0][j], af[0], bf, acc[0][j]);
            wmma::mma_sync(acc[1][j], af[1], bf, acc[1][j]);
        }
    }
    #pragma unroll
    for (int i = 0; i < 2; i++)
        #pragma unroll
        for (int j = 0; j < 4; j++)
            #pragma unroll
            for (int e = 0; e < acc[i][j].num_elements; e++) acc[i][j].x[e] *= 0.125f;
    __syncthreads();   // all smem MMA reads done; reuse sQ as epilogue stage
    float* stage = (float*)sQ + warp * 320;
    hepilogue<4>(acc, stage, C, nullptr, Ssz, m0, n0, 0.0f);
}

// softmax rows of 512: fp16 in -> fp16 out, fully vectorized (4 contiguous cols/thread)
__global__ __launch_bounds__(128) void softmax_h(const __half* __restrict__ S, __half* __restrict__ P) {
    __shared__ float sh[4];
    long row = blockIdx.x;
    const __half2* p2 = (const __half2*)(S + row * 512);
    __half2* o2 = (__half2*)(P + row * 512);
    int t = threadIdx.x;
    float2 a = __half22float2(p2[2 * t]);
    float2 b = __half22float2(p2[2 * t + 1]);
    float v[4] = {a.x, a.y, b.x, b.y};
    float m = fmaxf(fmaxf(v[0], v[1]), fmaxf(v[2], v[3]));
    m = warpMax(m);
    if ((t & 31) == 0) sh[t >> 5] = m;
    __syncthreads();
    if (t < 32) { float x = (t < 4) ? sh[t] : -INFINITY; x = warpMax(x); if (t == 0) sh[0] = x; }
    __syncthreads();
    m = sh[0];
    __syncthreads();
    float s = 0.f;
    #pragma unroll
    for (int i = 0; i < 4; i++) { v[i] = expf(v[i] - m); s += v[i]; }
    s = warpSum(s);
    if ((t & 31) == 0) sh[t >> 5] = s;
    __syncthreads();
    if (t < 32) { float x = (t < 4) ? sh[t] : 0.f; x = warpSum(x); if (t == 0) sh[0] = x; }
    __syncthreads();
    float inv = 1.0f / sh[0];
    o2[2 * t]     = __floats2half2_rn(v[0] * inv, v[1] * inv);
    o2[2 * t + 1] = __floats2half2_rn(v[2] * inv, v[3] * inv);
}

#define PV_SPSZ (128 * 72)
#define PV_SVSZ (64 * 72)
static const int SMEMPV_BYTES = (2 * PV_SPSZ + 2 * PV_SVSZ) * 2;   // 55296 B

__global__ __launch_bounds__(256, 2) void pv_h(const __half* __restrict__ ph, const __half* __restrict__ vh,
                                               __half* __restrict__ ob) {
    extern __shared__ __half smp[];
    __half* sP[2] = { smp, smp + PV_SPSZ };
    __half* sV[2] = { smp + 2 * PV_SPSZ, smp + 2 * PV_SPSZ + PV_SVSZ };
    int z = blockIdx.z, b = z >> 4, h = z & 15;
    const __half* Pb = ph + (long)z * Ssz * Ssz;
    const __half* Vb = vh + (long)b * Ssz * INNERn + h * DHn;
    __half* Ob = ob + (long)b * Ssz * INNERn + h * DHn;
    int m0 = blockIdx.y * 128;
    int tid = threadIdx.x;
    int prow = tid >> 1, pcol = (tid & 1) * 32;
    int vrow = tid >> 2, vcol = (tid & 3) * 16;

    #pragma unroll
    for (int i = 0; i < 4; i++) cpa16(sP[0] + prow * 72 + pcol + i * 8, Pb + (long)(m0 + prow) * Ssz + pcol + i * 8);
    #pragma unroll
    for (int i = 0; i < 2; i++) cpa16(sV[0] + vrow * 72 + vcol + i * 8, Vb + (long)vrow * INNERn + vcol + i * 8);
    cp_commit();

    int warp = tid >> 5, wm = warp & 3, wn = warp >> 2;
    HFragC acc[2][2];
    #pragma unroll
    for (int i = 0; i < 2; i++)
        #pragma unroll
        for (int j = 0; j < 2; j++) wmma::fill_fragment(acc[i][j], 0.0f);

    #pragma unroll 1
    for (int it = 0; it < 8; it++) {
        int s = it & 1;
        if (it + 1 < 8) {
            int s2 = s ^ 1, k0 = (it + 1) * 64;
            #pragma unroll
            for (int i = 0; i < 4; i++)
                cpa16(sP[s2] + prow * 72 + pcol + i * 8, Pb + (long)(m0 + prow) * Ssz + k0 + pcol + i * 8);
            #pragma unroll
            for (int i = 0; i < 2; i++)
                cpa16(sV[s2] + vrow * 72 + vcol + i * 8, Vb + (long)(k0 + vrow) * INNERn + vcol + i * 8);
            cp_commit();
            cp_wait<1>();
        } else {
            cp_wait<0>();
        }
        __syncthreads();
        #pragma unroll
        for (int kk = 0; kk < 4; kk++) {
            HFragA af[2];
            #pragma unroll
            for (int i = 0; i < 2; i++)
                wmma::load_matrix_sync(af[i], sP[s] + (wm * 32 + i * 16) * 72 + kk * 16, 72);
            #pragma unroll
            for (int j = 0; j < 2; j++) {
                HFragB bf;
                wmma::load_matrix_sync(bf, sV[s] + (kk * 16) * 72 + wn * 32 + j * 16, 72);
                wmma::mma_sync(acc[0][j], af[0], bf, acc[0][j]);
                wmma::mma_sync(acc[1][j], af[1], bf, acc[1][j]);
            }
        }
        __syncthreads();
    }
    float* stage = (float*)smp + warp * 320;
    int lane = tid & 31, r = lane >> 1, cb = (lane & 1) * 8;
    #pragma unroll
    for (int i = 0; i < 2; i++)
        #pragma unroll
        for (int j = 0; j < 2; j++) {
            wmma::store_matrix_sync(stage, acc[i][j], 20, wmma::mem_row_major);
            __syncwarp();
            int row = m0 + wm * 32 + i * 16 + r;
            int col0 = wn * 32 + j * 16 + cb;
            float vals[8];
            #pragma unroll
            for (int c = 0; c < 8; c++) vals[c] = stage[r * 20 + cb + c];
            st_half8(Ob + (long)row * INNERn + col0, vals);
            __syncwarp();
        }
}

// ---------------- LayerNorm (fp16 outputs) ----------------
__global__ __launch_bounds__(256) void ln3_k(const float* __restrict__ X,
                                             const float* __restrict__ wq, const float* __restrict__ bq,
                                             const float* __restrict__ wk, const float* __restrict__ bk,
                                             const float* __restrict__ wv, const float* __restrict__ bv,
                                             __half* __restrict__ oq, __half* __restrict__ ok,
                                             __half* __restrict__ ov) {
    __shared__ float sh[8];
    long row = blockIdx.x;
    const float* xr = X + row * DIMn;
    int t = threadIdx.x;
    float v[4]; float s = 0.f;
    #pragma unroll
    for (int i = 0; i < 4; i++) { v[i] = xr[t + i * 256]; s += v[i]; }
    s = warpSum(s);
    if ((t & 31) == 0) sh[t >> 5] = s;
    __syncthreads();
    if (t < 32) { float a = (t < 8) ? sh[t] : 0.f; a = warpSum(a); if (t == 0) sh[0] = a; }
    __syncthreads();
    float mean = sh[0] * (1.0f / DIMn);
    __syncthreads();
    float ss = 0.f;
    #pragma unroll
    for (int i = 0; i < 4; i++) { float d = v[i] - mean; ss += d * d; }
    ss = warpSum(ss);
    if ((t & 31) == 0) sh[t >> 5] = ss;
    __syncthreads();
    if (t < 32) { float a = (t < 8) ? sh[t] : 0.f; a = warpSum(a); if (t == 0) sh[0] = a; }
    __syncthreads();
    float rstd = rsqrtf(sh[0] * (1.0f / DIMn) + 1e-5f);
    #pragma unroll
    for (int i = 0; i < 4; i++) {
        int c = t + i * 256;
        float xh = (v[i] - mean) * rstd;
        long idx = row * DIMn + c;
        oq[idx] = __float2half_rn(xh * wq[c] + bq[c]);
        ok[idx] = __float2half_rn(xh * wk[c] + bk[c]);
        ov[idx] = __float2half_rn(xh * wv[c] + bv[c]);
    }
}

__global__ __launch_bounds__(256) void ln1_k(const float* __restrict__ X,
                                             const float* __restrict__ w, const float* __restrict__ b,
                                             __half* __restrict__ out) {
    __shared__ float sh[8];
    long row = blockIdx.x;
    const float* xr = X + row * DIMn;
    int t = threadIdx.x;
    float v[4]; float s = 0.f;
    #pragma unroll
    for (int i = 0; i < 4; i++) { v[i] = xr[t + i * 256]; s += v[i]; }
    s = warpSum(s);
    if ((t & 31) == 0) sh[t >> 5] = s;
    __syncthreads();
    if (t < 32) { float a = (t < 8) ? sh[t] : 0.f; a = warpSum(a); if (t == 0) sh[0] = a; }
    __syncthreads();
    float mean = sh[0] * (1.0f / DIMn);
    __syncthreads();
    float ss = 0.f;
    #pragma unroll
    for (int i = 0; i < 4; i++) { float d = v[i] - mean; ss += d * d; }
    ss = warpSum(ss);
    if ((t & 31) == 0) sh[t >> 5] = ss;
    __syncthreads();
    if (t < 32) { float a = (t < 8) ? sh[t] : 0.f; a = warpSum(a); if (t == 0) sh[0] = a; }
    __syncthreads();
    float rstd = rsqrtf(sh[0] * (1.0f / DIMn) + 1e-5f);
    #pragma unroll
    for (int i = 0; i < 4; i++) {
        int c = t + i * 256;
        long idx = row * DIMn + c;
        out[idx] = __float2half_rn((v[i] - mean) * rstd * w[c] + b[c]);
    }
}

// ---------------- router mean over LR ----------------
__global__ void rimean_k(const float* __restrict__ ri, float* __restrict__ rm) {
    int i = blockIdx.x * 256 + threadIdx.x;
    int b = i >> 10, d = i & 1023;
    float s = 0.f;
    for (int r = 0; r < LRn; r++) s += ri[((long)b * LRn + r) * DIMn + d];
    rm[i] = s * (1.0f / LRn);
}

// ---------------- router logits ----------------
__global__ __launch_bounds__(256) void logits_k(const float* __restrict__ rm,
                                                const float* __restrict__ Wr, const float* __restrict__ br,
                                                const float* __restrict__ Wn, const float* __restrict__ bn,
                                                float* __restrict__ lg, float* __restrict__ nl) {
    __shared__ float sh[16];
    int b = blockIdx.x >> 3, e = blockIdx.x & 7;
    int t = threadIdx.x;
    float s1 = 0.f, s2 = 0.f;
    for (int d = t; d < DIMn; d += 256) {
        float r = rm[b * DIMn + d];
        s1 += r * Wr[(long)d * En + e];
        s2 += r * Wn[(long)d * En + e];
    }
    s1 = warpSum(s1); s2 = warpSum(s2);
    if ((t & 31) == 0) { sh[t >> 5] = s1; sh[8 + (t >> 5)] = s2; }
    __syncthreads();
    if (t == 0) {
        float a = 0.f, c = 0.f;
        for (int i = 0; i < 8; i++) { a += sh[i]; c += sh[8 + i]; }
        lg[blockIdx.x] = a + br[e];
        nl[blockIdx.x] = c + bn[e];
    }
}

// ---------------- noisy top-k routing + capacity + used-expert flags ----------------
__global__ void route_k(const float* __restrict__ logits, const float* __restrict__ nlog, int l,
                        int* __restrict__ fe, float* __restrict__ fw, int* __restrict__ used) {
    __shared__ float sc[64];
    __shared__ int se[16];
    __shared__ float sg[16];
    int t = threadIdx.x;
    if (t < 64) {
        unsigned kk0, kk1;
        tf2x32(0u, 42u, 0u, (unsigned)l, kk0, kk1);
        unsigned o0, o1;
        tf2x32(kk0, kk1, 0u, (unsigned)t, o0, o1);
        unsigned bits = o0 ^ o1;
        float f = __uint_as_float(0x3f800000u | (bits >> 9)) - 1.0f;
        const float lo = -0.99999994f;
        float u = f * 2.0f + lo;
        u = fmaxf(lo, u);
        float g = 1.41421356237309515f * erfinvf(u);
        float xnl = nlog[t];
        float sp = fmaxf(xnl, 0.f) + log1pf(expf(-fabsf(xnl)));
        sc[t] = logits[t] + g * sp;
    }
    __syncthreads();
    if (t < 8) {
        const float* row = sc + t * 8;
        int e0 = 0; float v0 = row[0];
        for (int e = 1; e < 8; e++) if (row[e] > v0) { v0 = row[e]; e0 = e; }
        int e1 = -1; float v1 = -INFINITY;
        for (int e = 0; e < 8; e++) if (e != e0 && row[e] > v1) { v1 = row[e]; e1 = e; }
        float d = expf(v1 - v0);
        float inv = 1.0f / (1.0f + d);
        se[t * 2] = e0; se[t * 2 + 1] = e1;
        sg[t * 2] = inv; sg[t * 2 + 1] = d * inv;
    }
    __syncthreads();
    if (t == 0) {
        int cnt[8] = {0, 0, 0, 0, 0, 0, 0, 0};
        int us[8]  = {0, 0, 0, 0, 0, 0, 0, 0};
        for (int n = 0; n < 16; n++) {
            int e = se[n];
            float w = (cnt[e] < CAPn) ? sg[n] : 0.0f;
            cnt[e]++;
            fe[n] = e; fw[n] = w;
            if (w != 0.0f) us[e] = 1;
        }
        for (int e = 0; e < 8; e++) used[e] = us[e];
    }
}

// ---------------- host launch ----------------
static void conv_w(const float* src, __half* dst, long n) {
    long n4 = n / 4;
    int blocks = (int)((n4 + 255) / 256);
    f2h4<<<blocks, 256>>>((const float4*)src, (__half2*)dst, n4);
}

extern "C" void kernel_launch(void* const* d_in, const int* in_sizes, int n_in,
                              void* d_out, int out_size) {
    (void)in_sizes; (void)n_in; (void)out_size;
    const float* router_input = (const float*)d_in[0];
    const float* x0   = (const float*)d_in[1];
    const float* nq_w = (const float*)d_in[2];
    const float* nq_b = (const float*)d_in[3];
    const float* nk_w = (const float*)d_in[4];
    const float* nk_b = (const float*)d_in[5];
    const float* nv_w = (const float*)d_in[6];
    const float* nv_b = (const float*)d_in[7];
    const float* Wq   = (const float*)d_in[8];
    const float* Wk   = (const float*)d_in[9];
    const float* Wv   = (const float*)d_in[10];
    const float* Wo   = (const float*)d_in[11];
    const float* bo   = (const float*)d_in[12];
    const float* nm_w = (const float*)d_in[13];
    const float* nm_b = (const float*)d_in[14];
    const float* Wr   = (const float*)d_in[15];
    const float* br   = (const float*)d_in[16];
    const float* Wn   = (const float*)d_in[17];
    const float* bn   = (const float*)d_in[18];
    const float* W1   = (const float*)d_in[19];
    const float* b1   = (const float*)d_in[20];
    const float* W2   = (const float*)d_in[21];
    const float* b2   = (const float*)d_in[22];

    float* X = (float*)d_out;
    float* arena = nullptr;
    cudaGetSymbolAddress((void**)&arena, g_arena);
    __half* ha = nullptr;
    cudaGetSymbolAddress((void**)&ha, g_harena);

    float* rm   = arena + O_RM;
    float* lg   = arena + O_LG;
    float* nl   = arena + O_NL;
    float* fw   = arena + O_FW;
    int*   fe   = (int*)(arena + O_FE);
    int*   used = (int*)(arena + O_USE);

    __half* lnq = ha + H_LNQ;
    __half* lnk = ha + H_LNK;
    __half* lnv = ha + H_LNV;
    __half* xnh = ha + H_XN;
    __half* obh = ha + H_OB;
    __half* qh  = ha + H_Q;
    __half* kh  = ha + H_K;
    __half* vh  = ha + H_V;
    __half* sch = ha + H_S;
    __half* phh = ha + H_P;
    __half* hbh = ha + H_H;
    __half* Wq16 = ha + H_WQ;
    __half* Wk16 = ha + H_WK;
    __half* Wv16 = ha + H_WV;
    __half* Wo16 = ha + H_WO;
    __half* W116 = ha + H_W1;
    __half* W216 = ha + H_W2;

    cudaFuncSetAttribute(qkv_h, cudaFuncAttributeMaxDynamicSharedMemorySize, SMEMH_BYTES);
    cudaFuncSetAttribute(wo_h, cudaFuncAttributeMaxDynamicSharedMemorySize, SMEMH_BYTES);
    cudaFuncSetAttribute(moe1_h, cudaFuncAttributeMaxDynamicSharedMemorySize, SMEMH_BYTES);
    cudaFuncSetAttribute(moe2_h, cudaFuncAttributeMaxDynamicSharedMemorySize, SMEMH_BYTES);
    cudaFuncSetAttribute(pv_h, cudaFuncAttributeMaxDynamicSharedMemorySize, SMEMPV_BYTES);

    // routing first (depends only on router_input) -> used-expert flags
    rimean_k<<<32, 256>>>(router_input, rm);
    for (int l = 0; l < Dlay; l++) {
        logits_k<<<Bn * En, 256>>>(rm, Wr + (long)l * DIMn * En, br + l * En,
                                   Wn + (long)l * DIMn * En, bn + l * En, lg, nl);
        route_k<<<1, 64>>>(lg, nl, l, fe + 16 * l, fw + 16 * l, used + 8 * l);
    }

    // dense weights unconditionally; MoE weights only for used experts
    conv_w(Wq, Wq16, (long)Dlay * DIMn * INNERn);
    conv_w(Wk, Wk16, (long)Dlay * DIMn * INNERn);
    conv_w(Wv, Wv16, (long)Dlay * DIMn * INNERn);
    conv_w(Wo, Wo16, (long)Dlay * INNERn * DIMn);
    {
        long n4_per = (long)DIMn * MLPn / 4;   // 1,048,576 float4 per (layer,expert)
        dim3 g((unsigned)((n4_per + 255) / 256), Dlay * En);
        f2h_sel<<<g, 256>>>((const float4*)W1, (__half2*)W116, used, n4_per);
        f2h_sel<<<g, 256>>>((const float4*)W2, (__half2*)W216, used, n4_per);
    }

    cudaMemcpyAsync(X, x0, sizeof(float) * SZX, cudaMemcpyDeviceToDevice);

    for (int l = 0; l < Dlay; l++) {
        const int* fe_l = fe + 16 * l;
        const float* fw_l = fw + 16 * l;

        ln3_k<<<Bn * Ssz, 256>>>(X, nq_w + l * DIMn, nq_b + l * DIMn,
                                 nk_w + l * DIMn, nk_b + l * DIMn,
                                 nv_w + l * DIMn, nv_b + l * DIMn, lnq, lnk, lnv);

        qkv_h<<<dim3(INNERn / 128, Bn * Ssz / 128, 3), 256, SMEMH_BYTES>>>(
            lnq, lnk, lnv,
            Wq16 + (long)l * DIMn * INNERn, Wk16 + (long)l * DIMn * INNERn,
            Wv16 + (long)l * DIMn * INNERn, qh, kh, vh);

        qk_h<<<dim3(Ssz / 128, Ssz / 128, Bn * Hn), 256>>>(qh, kh, sch);

        softmax_h<<<Bn * Hn * Ssz, 128>>>(sch, phh);

        pv_h<<<dim3(1, Ssz / 128, Bn * Hn), 256, SMEMPV_BYTES>>>(phh, vh, obh);

        wo_h<<<dim3(DIMn / 128, Bn * Ssz / 128), 256, SMEMH_BYTES>>>(
            obh, Wo16 + (long)l * INNERn * DIMn, X, bo + l * DIMn);

        ln1_k<<<Bn * Ssz, 256>>>(X, nm_w + l * DIMn, nm_b + l * DIMn, xnh);
        moe1_h<<<dim3(MLPn / 128, Ssz / 128, Bn * Kn), 256, SMEMH_BYTES>>>(
            xnh, W116 + (long)l * En * DIMn * MLPn, b1 + (long)l * En * MLPn, hbh, fe_l, fw_l);
        moe2_h<<<dim3(DIMn / 128, Ssz / 128, Bn * Kn), 256, SMEMH_BYTES>>>(
            hbh, W216 + (long)l * En * MLPn * DIMn, b2 + (long)l * En * DIMn, X, fe_l, fw_l);
    }
}

// round 15
// speedup vs baseline: 1.1528x; 1.0080x over previous
#include <cuda_runtime.h>
#include <cuda_fp16.h>
#include <math.h>
#include <mma.h>

using namespace nvcuda;

// ---------------- problem constants ----------------
#define Bn     8
#define Ssz    512
#define DIMn   1024
#define Hn     16
#define DHn    64
#define INNERn 1024
#define MLPn   4096
#define En     8
#define Kn     2
#define LRn    77
#define CAPn   2
#define Dlay   2

static const long SZX = (long)Bn * Ssz * DIMn;           // 4,194,304
static const long SZSC = (long)Bn * Hn * Ssz * Ssz;      // 33,554,432
static const long SZH  = (long)Bn * Kn * Ssz * MLPn;     // 33,554,432

// ---- fp32 arena (routing only) ----
static const long O_RM  = 0;
static const long O_LG  = O_RM + 8192;
static const long O_NL  = O_LG + 64;
static const long O_FW  = O_NL + 64;      // 32 floats (2 layers x 16)
static const long O_FE  = O_FW + 32;      // 32 ints
static const long O_USE = O_FE + 32;      // 16 ints (2 layers x 8 experts)
static const long ARENA_FLOATS = O_USE + 32;
__device__ __align__(16) float g_arena[ARENA_FLOATS];

// ---- fp16 arena ----
static const long H_LNQ = 0;
static const long H_LNK = H_LNQ + SZX;
static const long H_LNV = H_LNK + SZX;
static const long H_XN  = H_LNV + SZX;
static const long H_OB  = H_XN  + SZX;
static const long H_Q   = H_OB  + SZX;
static const long H_K   = H_Q   + SZX;
static const long H_V   = H_K   + SZX;
static const long H_S   = H_V   + SZX;            // fp16 scores
static const long H_P   = H_S   + SZSC;           // fp16 probs
static const long H_H   = H_P   + SZSC;
static const long H_WQ  = H_H   + SZH;
static const long H_WK  = H_WQ  + (long)Dlay * DIMn * INNERn;
static const long H_WV  = H_WK  + (long)Dlay * DIMn * INNERn;
static const long H_WO  = H_WV  + (long)Dlay * DIMn * INNERn;
static const long H_W1  = H_WO  + (long)Dlay * INNERn * DIMn;
static const long H_W2  = H_W1  + (long)Dlay * En * DIMn * MLPn;
static const long ARENA_HALVES = H_W2 + (long)Dlay * En * MLPn * DIMn;
__device__ __align__(16) __half g_harena[ARENA_HALVES];

// ---------------- reductions ----------------
__device__ __forceinline__ float warpSum(float v) {
    #pragma unroll
    for (int o = 16; o; o >>= 1) v += __shfl_xor_sync(0xffffffffu, v, o);
    return v;
}
__device__ __forceinline__ float warpMax(float v) {
    #pragma unroll
    for (int o = 16; o; o >>= 1) v = fmaxf(v, __shfl_xor_sync(0xffffffffu, v, o));
    return v;
}

// ---------------- threefry2x32 (JAX-exact) ----------------
__device__ __forceinline__ void tf2x32(unsigned k0, unsigned k1, unsigned x0, unsigned x1,
                                       unsigned& o0, unsigned& o1) {
    unsigned ks[3] = {k0, k1, k0 ^ k1 ^ 0x1BD11BDAu};
    const int R0[4] = {13, 15, 26, 6};
    const int R1[4] = {17, 29, 16, 24};
    x0 += ks[0]; x1 += ks[1];
    #pragma unroll
    for (int i = 0; i < 5; i++) {
        #pragma unroll
        for (int r = 0; r < 4; r++) {
            int rot = (i & 1) ? R1[r] : R0[r];
            x0 += x1;
            x1 = (x1 << rot) | (x1 >> (32 - rot));
            x1 ^= x0;
        }
        x0 += ks[(i + 1) % 3];
        x1 += ks[(i + 2) % 3] + (unsigned)(i + 1);
    }
    o0 = x0; o1 = x1;
}

// ---------------- fp32 -> fp16 converts (MLP=2, coalesced split) ----------------
__global__ void f2h4(const float4* __restrict__ src, __half2* __restrict__ dst, long n4) {
    long half = n4 >> 1;
    long i = (long)blockIdx.x * blockDim.x + threadIdx.x;
    if (i >= half) return;
    float4 v0 = src[i];
    float4 v1 = src[i + half];
    dst[2 * i]     = __floats2half2_rn(v0.x, v0.y);
    dst[2 * i + 1] = __floats2half2_rn(v0.z, v0.w);
    dst[2 * (i + half)]     = __floats2half2_rn(v1.x, v1.y);
    dst[2 * (i + half) + 1] = __floats2half2_rn(v1.z, v1.w);
}

// selective per-(layer,expert) conversion; early-exit if expert unused; MLP=2
__global__ void f2h_sel(const float4* __restrict__ src, __half2* __restrict__ dst,
                        const int* __restrict__ used, long n4_per) {
    int e = blockIdx.y;                      // 0..15 = l*8+e
    if (!used[e]) return;
    long half = n4_per >> 1;
    long i = (long)blockIdx.x * blockDim.x + threadIdx.x;
    if (i >= half) return;
    long base = (long)e * n4_per;
    long i0 = base + i, i1 = base + i + half;
    float4 v0 = src[i0];
    float4 v1 = src[i1];
    dst[2 * i0]     = __floats2half2_rn(v0.x, v0.y);
    dst[2 * i0 + 1] = __floats2half2_rn(v0.z, v0.w);
    dst[2 * i1]     = __floats2half2_rn(v1.x, v1.y);
    dst[2 * i1 + 1] = __floats2half2_rn(v1.z, v1.w);
}

// =================================================================
// fp16 WMMA machinery
// =================================================================
using HFragA  = wmma::fragment<wmma::matrix_a, 16, 16, 16, __half, wmma::row_major>;
using HFragB  = wmma::fragment<wmma::matrix_b, 16, 16, 16, __half, wmma::row_major>;
using HFragBc = wmma::fragment<wmma::matrix_b, 16, 16, 16, __half, wmma::col_major>;
using HFragC  = wmma::fragment<wmma::accumulator, 16, 16, 16, float>;

__device__ __forceinline__ void cpa16(void* dst_smem, const void* src) {
    unsigned d = (unsigned)__cvta_generic_to_shared(dst_smem);
    asm volatile("cp.async.cg.shared.global [%0], [%1], 16;\n" :: "r"(d), "l"(src));
}
__device__ __forceinline__ void cp_commit() { asm volatile("cp.async.commit_group;\n"); }
template <int N>
__device__ __forceinline__ void cp_wait() { asm volatile("cp.async.wait_group %0;\n" :: "n"(N)); }

// pack 8 fp32 -> one 16B fp16 store
__device__ __forceinline__ void st_half8(__half* dst, const float* v) {
    __half2 h0 = __floats2half2_rn(v[0], v[1]);
    __half2 h1 = __floats2half2_rn(v[2], v[3]);
    __half2 h2 = __floats2half2_rn(v[4], v[5]);
    __half2 h3 = __floats2half2_rn(v[6], v[7]);
    uint4 u;
    u.x = *(unsigned*)&h0; u.y = *(unsigned*)&h1;
    u.z = *(unsigned*)&h2; u.w = *(unsigned*)&h3;
    *(uint4*)dst = u;
}
// pack 4 fp32 -> one 8B fp16 store
__device__ __forceinline__ void st_half4(__half* dst, float a, float b, float c, float d) {
    __half2 h0 = __floats2half2_rn(a, b);
    __half2 h1 = __floats2half2_rn(c, d);
    uint2 u;
    u.x = *(unsigned*)&h0; u.y = *(unsigned*)&h1;
    *(uint2*)dst = u;
}

#define HA_STR 72
#define HB_STR 136
#define HA_STAGE (128 * HA_STR)
#define HB_STAGE (64 * HB_STR)
static const int SMEMH_BYTES = (2 * HA_STAGE + 2 * HB_STAGE) * 2;  // 71680 B

__device__ __forceinline__ void hmm_cp(const __half* __restrict__ A, const __half* __restrict__ B,
                                       int lda, int ldb, int K, int m0, int n0,
                                       __half* sm, HFragC (&acc)[2][4]) {
    __half* sA[2] = { sm, sm + HA_STAGE };
    __half* sB[2] = { sm + 2 * HA_STAGE, sm + 2 * HA_STAGE + HB_STAGE };
    int tid = threadIdx.x;
    int warp = tid >> 5, wm = warp & 3, wn = warp >> 2;
    int arow = tid >> 1, acH = (tid & 1) * 32;
    int brow = tid >> 2, bcH = (tid & 3) * 32;
    const __half* Ab = A + (long)(m0 + arow) * lda + acH;
    const __half* Bb = B + (long)brow * ldb + n0 + bcH;
    __half* dA[2] = { sA[0] + arow * HA_STR + acH, sA[1] + arow * HA_STR + acH };
    __half* dB[2] = { sB[0] + brow * HB_STR + bcH, sB[1] + brow * HB_STR + bcH };

    int nIt = K >> 6;
    #pragma unroll
    for (int i = 0; i < 4; i++) cpa16(dA[0] + i * 8, Ab + i * 8);
    #pragma unroll
    for (int i = 0; i < 4; i++) cpa16(dB[0] + i * 8, Bb + i * 8);
    cp_commit();

    #pragma unroll 1
    for (int it = 0; it < nIt; it++) {
        int s = it & 1;
        if (it + 1 < nIt) {
            int s2 = s ^ 1;
            const __half* a = Ab + (it + 1) * 64;
            const __half* b = Bb + (long)(it + 1) * 64 * ldb;
            #pragma unroll
            for (int i = 0; i < 4; i++) cpa16(dA[s2] + i * 8, a + i * 8);
            #pragma unroll
            for (int i = 0; i < 4; i++) cpa16(dB[s2] + i * 8, b + i * 8);
            cp_commit();
            cp_wait<1>();
        } else {
            cp_wait<0>();
        }
        __syncthreads();
        #pragma unroll
        for (int kk = 0; kk < 4; kk++) {
            HFragA af[2];
            #pragma unroll
            for (int i = 0; i < 2; i++)
                wmma::load_matrix_sync(af[i], sA[s] + (wm * 32 + i * 16) * HA_STR + kk * 16, HA_STR);
            #pragma unroll
            for (int j = 0; j < 4; j++) {
                HFragB bf;
                wmma::load_matrix_sync(bf, sB[s] + (kk * 16) * HB_STR + wn * 64 + j * 16, HB_STR);
                wmma::mma_sync(acc[0][j], af[0], bf, acc[0][j]);
                wmma::mma_sync(acc[1][j], af[1], bf, acc[1][j]);
            }
        }
        __syncthreads();
    }
}

__device__ __forceinline__ void hacc_zero(HFragC (&acc)[2][4]) {
    #pragma unroll
    for (int i = 0; i < 2; i++)
        #pragma unroll
        for (int j = 0; j < 4; j++) wmma::fill_fragment(acc[i][j], 0.0f);
}

// EPI: 1 = fp32 C += acc + bias (vec128) ; 2 = fp16 C = gelu(acc+bias) (vec128)
//      3 = atomicAdd(fp32 C, (acc+bias)*w) (scalar) ; 4 = fp16 C = acc (vec128)
template <int EPI>
__device__ __forceinline__ void hepilogue(HFragC (&acc)[2][4], float* stage_w,
                                          void* __restrict__ Cv, const float* __restrict__ bias,
                                          int ldc, int m0, int n0, float w) {
    int tid = threadIdx.x, warp = tid >> 5, lane = tid & 31;
    int wm = warp & 3, wn = warp >> 2;
    int r = lane >> 1, cb = (lane & 1) * 8;
    #pragma unroll
    for (int i = 0; i < 2; i++)
        #pragma unroll
        for (int j = 0; j < 4; j++) {
            wmma::store_matrix_sync(stage_w, acc[i][j], 20, wmma::mem_row_major);
            __syncwarp();
            int row = m0 + wm * 32 + i * 16 + r;
            int col0 = n0 + wn * 64 + j * 16 + cb;
            long idx0 = (long)row * ldc + col0;
            float vals[8];
            #pragma unroll
            for (int c = 0; c < 8; c++) vals[c] = stage_w[r * 20 + cb + c];
            if (EPI == 1) {
                float* C = (float*)Cv;
                float4 c0 = *(float4*)(C + idx0);
                float4 c1 = *(float4*)(C + idx0 + 4);
                float4 b0 = *(const float4*)(bias + col0);
                float4 b1 = *(const float4*)(bias + col0 + 4);
                c0.x += vals[0] + b0.x; c0.y += vals[1] + b0.y;
                c0.z += vals[2] + b0.z; c0.w += vals[3] + b0.w;
                c1.x += vals[4] + b1.x; c1.y += vals[5] + b1.y;
                c1.z += vals[6] + b1.z; c1.w += vals[7] + b1.w;
                *(float4*)(C + idx0) = c0;
                *(float4*)(C + idx0 + 4) = c1;
            } else if (EPI == 2) {
                #pragma unroll
                for (int c = 0; c < 8; c++) {
                    float u = vals[c] + bias[col0 + c];
                    vals[c] = 0.5f * u * (1.0f + erff(u * 0.70710678118654752f));
                }
                st_half8((__half*)Cv + idx0, vals);
            } else if (EPI == 3) {
                float* C = (float*)Cv;
                #pragma unroll
                for (int c = 0; c < 8; c++)
                    atomicAdd(&C[idx0 + c], (vals[c] + bias[col0 + c]) * w);
            } else {
                st_half8((__half*)Cv + idx0, vals);
            }
            __syncwarp();
        }
}

// fused QKV (fp16 in, fp16 out)
__global__ __launch_bounds__(256, 2) void qkv_h(const __half* __restrict__ lnq, const __half* __restrict__ lnk,
                                                const __half* __restrict__ lnv,
                                                const __half* __restrict__ Wq, const __half* __restrict__ Wk,
                                                const __half* __restrict__ Wv,
                                                __half* __restrict__ q, __half* __restrict__ k,
                                                __half* __restrict__ v) {
    extern __shared__ __half smh[];
    int z = blockIdx.z;
    const __half* A = (z == 0) ? lnq : (z == 1) ? lnk : lnv;
    const __half* B = (z == 0) ? Wq : (z == 1) ? Wk : Wv;
    __half* C = (z == 0) ? q : (z == 1) ? k : v;
    int m0 = blockIdx.y * 128, n0 = blockIdx.x * 128;
    HFragC acc[2][4];
    hacc_zero(acc);
    hmm_cp(A, B, DIMn, INNERn, DIMn, m0, n0, smh, acc);
    float* stage = (float*)smh + (threadIdx.x >> 5) * 320;
    hepilogue<4>(acc, stage, C, nullptr, INNERn, m0, n0, 0.0f);
}

// X += ob @ Wo + bo
__global__ __launch_bounds__(256, 2) void wo_h(const __half* __restrict__ A, const __half* __restrict__ B,
                                               float* __restrict__ C, const float* __restrict__ bias) {
    extern __shared__ __half smh[];
    int m0 = blockIdx.y * 128, n0 = blockIdx.x * 128;
    HFragC acc[2][4];
    hacc_zero(acc);
    hmm_cp(A, B, INNERn, DIMn, INNERn, m0, n0, smh, acc);
    float* stage = (float*)smh + (threadIdx.x >> 5) * 320;
    hepilogue<1>(acc, stage, C, bias, DIMn, m0, n0, 0.0f);
}

// MoE 1: H16 = gelu(xn16 @ W1[e] + b1[e])
__global__ __launch_bounds__(256, 2) void moe1_h(const __half* __restrict__ xn, const __half* __restrict__ W1l,
                                                 const float* __restrict__ b1l, __half* __restrict__ H,
                                                 const int* __restrict__ fe, const float* __restrict__ fw) {
    extern __shared__ __half smh[];
    int n = blockIdx.z;
    if (fw[n] == 0.0f) return;
    int e = fe[n];
    const __half* A = xn + (long)(n >> 1) * Ssz * DIMn;
    const __half* B = W1l + (long)e * DIMn * MLPn;
    __half* C = H + (long)n * Ssz * MLPn;
    const float* bias = b1l + (long)e * MLPn;
    int m0 = blockIdx.y * 128, n0 = blockIdx.x * 128;
    HFragC acc[2][4];
    hacc_zero(acc);
    hmm_cp(A, B, DIMn, MLPn, DIMn, m0, n0, smh, acc);
    float* stage = (float*)smh + (threadIdx.x >> 5) * 320;
    hepilogue<2>(acc, stage, C, bias, MLPn, m0, n0, 0.0f);
}

// MoE 2: X[slot>>1] += (H16 @ W2[e] + b2[e]) * w
__global__ __launch_bounds__(256, 2) void moe2_h(const __half* __restrict__ H, const __half* __restrict__ W2l,
                                                 const float* __restrict__ b2l, float* __restrict__ X,
                                                 const int* __restrict__ fe, const float* __restrict__ fw) {
    extern __shared__ __half smh[];
    int n = blockIdx.z;
    float w = fw[n];
    if (w == 0.0f) return;
    int e = fe[n];
    const __half* A = H + (long)n * Ssz * MLPn;
    const __half* B = W2l + (long)e * MLPn * DIMn;
    float* C = X + (long)(n >> 1) * Ssz * DIMn;
    const float* bias = b2l + (long)e * DIMn;
    int m0 = blockIdx.y * 128, n0 = blockIdx.x * 128;
    HFragC acc[2][4];
    hacc_zero(acc);
    hmm_cp(A, B, MLPn, DIMn, MLPn, m0, n0, smh, acc);
    float* stage = (float*)smh + (threadIdx.x >> 5) * 320;
    hepilogue<3>(acc, stage, C, bias, DIMn, m0, n0, w);
}

// =================================================================
// Attention: QK^T (fp16 scores, vectorized epilogue), softmax (vec fp16), PV
// =================================================================
__global__ __launch_bounds__(256, 2) void qk_h(const __half* __restrict__ qh, const __half* __restrict__ kh,
                                               __half* __restrict__ sc) {
    __shared__ __half sQ[128 * 72];
    __shared__ __half sK[128 * 72];
    int z = blockIdx.z, b = z >> 4, h = z & 15;
    const __half* Qb = qh + (long)b * Ssz * INNERn + h * DHn;
    const __half* Kb = kh + (long)b * Ssz * INNERn + h * DHn;
    __half* C = sc + (long)z * Ssz * Ssz;
    int m0 = blockIdx.y * 128, n0 = blockIdx.x * 128;
    int tid = threadIdx.x;
    int row = tid >> 1, colH = (tid & 1) * 32;
    #pragma unroll
    for (int i = 0; i < 4; i++) {
        cpa16(sQ + row * 72 + colH + i * 8, Qb + (long)(m0 + row) * INNERn + colH + i * 8);
        cpa16(sK + row * 72 + colH + i * 8, Kb + (long)(n0 + row) * INNERn + colH + i * 8);
    }
    cp_commit(); cp_wait<0>();
    __syncthreads();
    int warp = tid >> 5, wm = warp & 3, wn = warp >> 2;
    HFragC acc[2][4];
    hacc_zero(acc);
    #pragma unroll
    for (int kk = 0; kk < 4; kk++) {
        HFragA af[2];
        #pragma unroll
        for (int i = 0; i < 2; i++)
            wmma::load_matrix_sync(af[i], sQ + (wm * 32 + i * 16) * 72 + kk * 16, 72);
        #pragma unroll
        for (int j = 0; j < 4; j++) {
            HFragBc bf;
            wmma::load_matrix_sync(bf, sK + (wn * 64 + j * 16) * 72 + kk * 16, 72);
            wmma::mma_sync(acc[0][j], af[0], bf, acc[0][j]);
            wmma::mma_sync(acc[1][j], af[1], bf, acc[1][j]);
        }
    }
    #pragma unroll
    for (int i = 0; i < 2; i++)
        #pragma unroll
        for (int j = 0; j < 4; j++)
            #pragma unroll
            for (int e = 0; e < acc[i][j].num_elements; e++) acc[i][j].x[e] *= 0.125f;
    __syncthreads();   // all smem MMA reads done; reuse sQ as epilogue stage
    float* stage = (float*)sQ + warp * 320;
    hepilogue<4>(acc, stage, C, nullptr, Ssz, m0, n0, 0.0f);
}

// softmax rows of 512: fp16 in -> fp16 out, 8B vector I/O
__global__ __launch_bounds__(128) void softmax_h(const __half* __restrict__ S, __half* __restrict__ P) {
    __shared__ float sh[4];
    long row = blockIdx.x;
    const uint2* p2 = (const uint2*)(S + row * 512);
    uint2* o2 = (uint2*)(P + row * 512);
    int t = threadIdx.x;
    uint2 u = p2[t];
    __half2 ha = *(__half2*)&u.x, hb = *(__half2*)&u.y;
    float2 a = __half22float2(ha);
    float2 b = __half22float2(hb);
    float v[4] = {a.x, a.y, b.x, b.y};
    float m = fmaxf(fmaxf(v[0], v[1]), fmaxf(v[2], v[3]));
    m = warpMax(m);
    if ((t & 31) == 0) sh[t >> 5] = m;
    __syncthreads();
    if (t < 32) { float x = (t < 4) ? sh[t] : -INFINITY; x = warpMax(x); if (t == 0) sh[0] = x; }
    __syncthreads();
    m = sh[0];
    __syncthreads();
    float s = 0.f;
    #pragma unroll
    for (int i = 0; i < 4; i++) { v[i] = expf(v[i] - m); s += v[i]; }
    s = warpSum(s);
    if ((t & 31) == 0) sh[t >> 5] = s;
    __syncthreads();
    if (t < 32) { float x = (t < 4) ? sh[t] : 0.f; x = warpSum(x); if (t == 0) sh[0] = x; }
    __syncthreads();
    float inv = 1.0f / sh[0];
    __half2 w0 = __floats2half2_rn(v[0] * inv, v[1] * inv);
    __half2 w1 = __floats2half2_rn(v[2] * inv, v[3] * inv);
    uint2 o;
    o.x = *(unsigned*)&w0; o.y = *(unsigned*)&w1;
    o2[t] = o;
}

#define PV_SPSZ (128 * 72)
#define PV_SVSZ (64 * 72)
static const int SMEMPV_BYTES = (2 * PV_SPSZ + 2 * PV_SVSZ) * 2;   // 55296 B

__global__ __launch_bounds__(256, 2) void pv_h(const __half* __restrict__ ph, const __half* __restrict__ vh,
                                               __half* __restrict__ ob) {
    extern __shared__ __half smp[];
    __half* sP[2] = { smp, smp + PV_SPSZ };
    __half* sV[2] = { smp + 2 * PV_SPSZ, smp + 2 * PV_SPSZ + PV_SVSZ };
    int z = blockIdx.z, b = z >> 4, h = z & 15;
    const __half* Pb = ph + (long)z * Ssz * Ssz;
    const __half* Vb = vh + (long)b * Ssz * INNERn + h * DHn;
    __half* Ob = ob + (long)b * Ssz * INNERn + h * DHn;
    int m0 = blockIdx.y * 128;
    int tid = threadIdx.x;
    int prow = tid >> 1, pcol = (tid & 1) * 32;
    int vrow = tid >> 2, vcol = (tid & 3) * 16;

    #pragma unroll
    for (int i = 0; i < 4; i++) cpa16(sP[0] + prow * 72 + pcol + i * 8, Pb + (long)(m0 + prow) * Ssz + pcol + i * 8);
    #pragma unroll
    for (int i = 0; i < 2; i++) cpa16(sV[0] + vrow * 72 + vcol + i * 8, Vb + (long)vrow * INNERn + vcol + i * 8);
    cp_commit();

    int warp = tid >> 5, wm = warp & 3, wn = warp >> 2;
    HFragC acc[2][2];
    #pragma unroll
    for (int i = 0; i < 2; i++)
        #pragma unroll
        for (int j = 0; j < 2; j++) wmma::fill_fragment(acc[i][j], 0.0f);

    #pragma unroll 1
    for (int it = 0; it < 8; it++) {
        int s = it & 1;
        if (it + 1 < 8) {
            int s2 = s ^ 1, k0 = (it + 1) * 64;
            #pragma unroll
            for (int i = 0; i < 4; i++)
                cpa16(sP[s2] + prow * 72 + pcol + i * 8, Pb + (long)(m0 + prow) * Ssz + k0 + pcol + i * 8);
            #pragma unroll
            for (int i = 0; i < 2; i++)
                cpa16(sV[s2] + vrow * 72 + vcol + i * 8, Vb + (long)(k0 + vrow) * INNERn + vcol + i * 8);
            cp_commit();
            cp_wait<1>();
        } else {
            cp_wait<0>();
        }
        __syncthreads();
        #pragma unroll
        for (int kk = 0; kk < 4; kk++) {
            HFragA af[2];
            #pragma unroll
            for (int i = 0; i < 2; i++)
                wmma::load_matrix_sync(af[i], sP[s] + (wm * 32 + i * 16) * 72 + kk * 16, 72);
            #pragma unroll
            for (int j = 0; j < 2; j++) {
                HFragB bf;
                wmma::load_matrix_sync(bf, sV[s] + (kk * 16) * 72 + wn * 32 + j * 16, 72);
                wmma::mma_sync(acc[0][j], af[0], bf, acc[0][j]);
                wmma::mma_sync(acc[1][j], af[1], bf, acc[1][j]);
            }
        }
        __syncthreads();
    }
    float* stage = (float*)smp + warp * 320;
    int lane = tid & 31, r = lane >> 1, cb = (lane & 1) * 8;
    #pragma unroll
    for (int i = 0; i < 2; i++)
        #pragma unroll
        for (int j = 0; j < 2; j++) {
            wmma::store_matrix_sync(stage, acc[i][j], 20, wmma::mem_row_major);
            __syncwarp();
            int row = m0 + wm * 32 + i * 16 + r;
            int col0 = wn * 32 + j * 16 + cb;
            float vals[8];
            #pragma unroll
            for (int c = 0; c < 8; c++) vals[c] = stage[r * 20 + cb + c];
            st_half8(Ob + (long)row * INNERn + col0, vals);
            __syncwarp();
        }
}

// ---------------- LayerNorm (vectorized, fp16 outputs) ----------------
__global__ __launch_bounds__(256) void ln3_k(const float* __restrict__ X,
                                             const float* __restrict__ wq, const float* __restrict__ bq,
                                             const float* __restrict__ wk, const float* __restrict__ bk,
                                             const float* __restrict__ wv, const float* __restrict__ bv,
                                             __half* __restrict__ oq, __half* __restrict__ ok,
                                             __half* __restrict__ ov) {
    __shared__ float sh[8];
    long row = blockIdx.x;
    const float* xr = X + row * DIMn;
    int t = threadIdx.x;
    int c0 = t * 4;
    float4 xv = *(const float4*)(xr + c0);
    float v[4] = {xv.x, xv.y, xv.z, xv.w};
    float s = v[0] + v[1] + v[2] + v[3];
    s = warpSum(s);
    if ((t & 31) == 0) sh[t >> 5] = s;
    __syncthreads();
    if (t < 32) { float a = (t < 8) ? sh[t] : 0.f; a = warpSum(a); if (t == 0) sh[0] = a; }
    __syncthreads();
    float mean = sh[0] * (1.0f / DIMn);
    __syncthreads();
    float ss = 0.f;
    #pragma unroll
    for (int i = 0; i < 4; i++) { float d = v[i] - mean; ss += d * d; }
    ss = warpSum(ss);
    if ((t & 31) == 0) sh[t >> 5] = ss;
    __syncthreads();
    if (t < 32) { float a = (t < 8) ? sh[t] : 0.f; a = warpSum(a); if (t == 0) sh[0] = a; }
    __syncthreads();
    float rstd = rsqrtf(sh[0] * (1.0f / DIMn) + 1e-5f);
    float xh[4];
    #pragma unroll
    for (int i = 0; i < 4; i++) xh[i] = (v[i] - mean) * rstd;
    long idx = row * DIMn + c0;
    float4 w4, b4;
    w4 = *(const float4*)(wq + c0); b4 = *(const float4*)(bq + c0);
    st_half4(oq + idx, xh[0] * w4.x + b4.x, xh[1] * w4.y + b4.y, xh[2] * w4.z + b4.z, xh[3] * w4.w + b4.w);
    w4 = *(const float4*)(wk + c0); b4 = *(const float4*)(bk + c0);
    st_half4(ok + idx, xh[0] * w4.x + b4.x, xh[1] * w4.y + b4.y, xh[2] * w4.z + b4.z, xh[3] * w4.w + b4.w);
    w4 = *(const float4*)(wv + c0); b4 = *(const float4*)(bv + c0);
    st_half4(ov + idx, xh[0] * w4.x + b4.x, xh[1] * w4.y + b4.y, xh[2] * w4.z + b4.z, xh[3] * w4.w + b4.w);
}

__global__ __launch_bounds__(256) void ln1_k(const float* __restrict__ X,
                                             const float* __restrict__ w, const float* __restrict__ b,
                                             __half* __restrict__ out) {
    __shared__ float sh[8];
    long row = blockIdx.x;
    const float* xr = X + row * DIMn;
    int t = threadIdx.x;
    int c0 = t * 4;
    float4 xv = *(const float4*)(xr + c0);
    float v[4] = {xv.x, xv.y, xv.z, xv.w};
    float s = v[0] + v[1] + v[2] + v[3];
    s = warpSum(s);
    if ((t & 31) == 0) sh[t >> 5] = s;
    __syncthreads();
    if (t < 32) { float a = (t < 8) ? sh[t] : 0.f; a = warpSum(a); if (t == 0) sh[0] = a; }
    __syncthreads();
    float mean = sh[0] * (1.0f / DIMn);
    __syncthreads();
    float ss = 0.f;
    #pragma unroll
    for (int i = 0; i < 4; i++) { float d = v[i] - mean; ss += d * d; }
    ss = warpSum(ss);
    if ((t & 31) == 0) sh[t >> 5] = ss;
    __syncthreads();
    if (t < 32) { float a = (t < 8) ? sh[t] : 0.f; a = warpSum(a); if (t == 0) sh[0] = a; }
    __syncthreads();
    float rstd = rsqrtf(sh[0] * (1.0f / DIMn) + 1e-5f);
    float4 w4 = *(const float4*)(w + c0);
    float4 b4 = *(const float4*)(b + c0);
    long idx = row * DIMn + c0;
    st_half4(out + idx,
             (v[0] - mean) * rstd * w4.x + b4.x,
             (v[1] - mean) * rstd * w4.y + b4.y,
             (v[2] - mean) * rstd * w4.z + b4.z,
             (v[3] - mean) * rstd * w4.w + b4.w);
}

// ---------------- router mean over LR ----------------
__global__ void rimean_k(const float* __restrict__ ri, float* __restrict__ rm) {
    int i = blockIdx.x * 256 + threadIdx.x;
    int b = i >> 10, d = i & 1023;
    float s = 0.f;
    for (int r = 0; r < LRn; r++) s += ri[((long)b * LRn + r) * DIMn + d];
    rm[i] = s * (1.0f / LRn);
}

// ---------------- router logits ----------------
__global__ __launch_bounds__(256) void logits_k(const float* __restrict__ rm,
                                                const float* __restrict__ Wr, const float* __restrict__ br,
                                                const float* __restrict__ Wn, const float* __restrict__ bn,
                                                float* __restrict__ lg, float* __restrict__ nl) {
    __shared__ float sh[16];
    int b = blockIdx.x >> 3, e = blockIdx.x & 7;
    int t = threadIdx.x;
    float s1 = 0.f, s2 = 0.f;
    for (int d = t; d < DIMn; d += 256) {
        float r = rm[b * DIMn + d];
        s1 += r * Wr[(long)d * En + e];
        s2 += r * Wn[(long)d * En + e];
    }
    s1 = warpSum(s1); s2 = warpSum(s2);
    if ((t & 31) == 0) { sh[t >> 5] = s1; sh[8 + (t >> 5)] = s2; }
    __syncthreads();
    if (t == 0) {
        float a = 0.f, c = 0.f;
        for (int i = 0; i < 8; i++) { a += sh[i]; c += sh[8 + i]; }
        lg[blockIdx.x] = a + br[e];
        nl[blockIdx.x] = c + bn[e];
    }
}

// ---------------- noisy top-k routing + capacity + used-expert flags ----------------
__global__ void route_k(const float* __restrict__ logits, const float* __restrict__ nlog, int l,
                        int* __restrict__ fe, float* __restrict__ fw, int* __restrict__ used) {
    __shared__ float sc[64];
    __shared__ int se[16];
    __shared__ float sg[16];
    int t = threadIdx.x;
    if (t < 64) {
        unsigned kk0, kk1;
        tf2x32(0u, 42u, 0u, (unsigned)l, kk0, kk1);
        unsigned o0, o1;
        tf2x32(kk0, kk1, 0u, (unsigned)t, o0, o1);
        unsigned bits = o0 ^ o1;
        float f = __uint_as_float(0x3f800000u | (bits >> 9)) - 1.0f;
        const float lo = -0.99999994f;
        float u = f * 2.0f + lo;
        u = fmaxf(lo, u);
        float g = 1.41421356237309515f * erfinvf(u);
        float xnl = nlog[t];
        float sp = fmaxf(xnl, 0.f) + log1pf(expf(-fabsf(xnl)));
        sc[t] = logits[t] + g * sp;
    }
    __syncthreads();
    if (t < 8) {
        const float* row = sc + t * 8;
        int e0 = 0; float v0 = row[0];
        for (int e = 1; e < 8; e++) if (row[e] > v0) { v0 = row[e]; e0 = e; }
        int e1 = -1; float v1 = -INFINITY;
        for (int e = 0; e < 8; e++) if (e != e0 && row[e] > v1) { v1 = row[e]; e1 = e; }
        float d = expf(v1 - v0);
        float inv = 1.0f / (1.0f + d);
        se[t * 2] = e0; se[t * 2 + 1] = e1;
        sg[t * 2] = inv; sg[t * 2 + 1] = d * inv;
    }
    __syncthreads();
    if (t == 0) {
        int cnt[8] = {0, 0, 0, 0, 0, 0, 0, 0};
        int us[8]  = {0, 0, 0, 0, 0, 0, 0, 0};
        for (int n = 0; n < 16; n++) {
            int e = se[n];
            float w = (cnt[e] < CAPn) ? sg[n] : 0.0f;
            cnt[e]++;
            fe[n] = e; fw[n] = w;
            if (w != 0.0f) us[e] = 1;
        }
        for (int e = 0; e < 8; e++) used[e] = us[e];
    }
}

// ---------------- host launch ----------------
static void conv_w(const float* src, __half* dst, long n) {
    long half = n / 8;   // n4/2
    int blocks = (int)((half + 255) / 256);
    f2h4<<<blocks, 256>>>((const float4*)src, (__half2*)dst, n / 4);
}

extern "C" void kernel_launch(void* const* d_in, const int* in_sizes, int n_in,
                              void* d_out, int out_size) {
    (void)in_sizes; (void)n_in; (void)out_size;
    const float* router_input = (const float*)d_in[0];
    const float* x0   = (const float*)d_in[1];
    const float* nq_w = (const float*)d_in[2];
    const float* nq_b = (const float*)d_in[3];
    const float* nk_w = (const float*)d_in[4];
    const float* nk_b = (const float*)d_in[5];
    const float* nv_w = (const float*)d_in[6];
    const float* nv_b = (const float*)d_in[7];
    const float* Wq   = (const float*)d_in[8];
    const float* Wk   = (const float*)d_in[9];
    const float* Wv   = (const float*)d_in[10];
    const float* Wo   = (const float*)d_in[11];
    const float* bo   = (const float*)d_in[12];
    const float* nm_w = (const float*)d_in[13];
    const float* nm_b = (const float*)d_in[14];
    const float* Wr   = (const float*)d_in[15];
    const float* br   = (const float*)d_in[16];
    const float* Wn   = (const float*)d_in[17];
    const float* bn   = (const float*)d_in[18];
    const float* W1   = (const float*)d_in[19];
    const float* b1   = (const float*)d_in[20];
    const float* W2   = (const float*)d_in[21];
    const float* b2   = (const float*)d_in[22];

    float* X = (float*)d_out;
    float* arena = nullptr;
    cudaGetSymbolAddress((void**)&arena, g_arena);
    __half* ha = nullptr;
    cudaGetSymbolAddress((void**)&ha, g_harena);

    float* rm   = arena + O_RM;
    float* lg   = arena + O_LG;
    float* nl   = arena + O_NL;
    float* fw   = arena + O_FW;
    int*   fe   = (int*)(arena + O_FE);
    int*   used = (int*)(arena + O_USE);

    __half* lnq = ha + H_LNQ;
    __half* lnk = ha + H_LNK;
    __half* lnv = ha + H_LNV;
    __half* xnh = ha + H_XN;
    __half* obh = ha + H_OB;
    __half* qh  = ha + H_Q;
    __half* kh  = ha + H_K;
    __half* vh  = ha + H_V;
    __half* sch = ha + H_S;
    __half* phh = ha + H_P;
    __half* hbh = ha + H_H;
    __half* Wq16 = ha + H_WQ;
    __half* Wk16 = ha + H_WK;
    __half* Wv16 = ha + H_WV;
    __half* Wo16 = ha + H_WO;
    __half* W116 = ha + H_W1;
    __half* W216 = ha + H_W2;

    cudaFuncSetAttribute(qkv_h, cudaFuncAttributeMaxDynamicSharedMemorySize, SMEMH_BYTES);
    cudaFuncSetAttribute(wo_h, cudaFuncAttributeMaxDynamicSharedMemorySize, SMEMH_BYTES);
    cudaFuncSetAttribute(moe1_h, cudaFuncAttributeMaxDynamicSharedMemorySize, SMEMH_BYTES);
    cudaFuncSetAttribute(moe2_h, cudaFuncAttributeMaxDynamicSharedMemorySize, SMEMH_BYTES);
    cudaFuncSetAttribute(pv_h, cudaFuncAttributeMaxDynamicSharedMemorySize, SMEMPV_BYTES);

    // routing first (depends only on router_input) -> used-expert flags
    rimean_k<<<32, 256>>>(router_input, rm);
    for (int l = 0; l < Dlay; l++) {
        logits_k<<<Bn * En, 256>>>(rm, Wr + (long)l * DIMn * En, br + l * En,
                                   Wn + (long)l * DIMn * En, bn + l * En, lg, nl);
        route_k<<<1, 64>>>(lg, nl, l, fe + 16 * l, fw + 16 * l, used + 8 * l);
    }

    // dense weights unconditionally; MoE weights only for used experts
    conv_w(Wq, Wq16, (long)Dlay * DIMn * INNERn);
    conv_w(Wk, Wk16, (long)Dlay * DIMn * INNERn);
    conv_w(Wv, Wv16, (long)Dlay * DIMn * INNERn);
    conv_w(Wo, Wo16, (long)Dlay * INNERn * DIMn);
    {
        long n4_per = (long)DIMn * MLPn / 4;   // 1,048,576 float4 per (layer,expert)
        long half = n4_per >> 1;
        dim3 g((unsigned)((half + 255) / 256), Dlay * En);
        f2h_sel<<<g, 256>>>((const float4*)W1, (__half2*)W116, used, n4_per);
        f2h_sel<<<g, 256>>>((const float4*)W2, (__half2*)W216, used, n4_per);
    }

    cudaMemcpyAsync(X, x0, sizeof(float) * SZX, cudaMemcpyDeviceToDevice);

    for (int l = 0; l < Dlay; l++) {
        const int* fe_l = fe + 16 * l;
        const float* fw_l = fw + 16 * l;

        ln3_k<<<Bn * Ssz, 256>>>(X, nq_w + l * DIMn, nq_b + l * DIMn,
                                 nk_w + l * DIMn, nk_b + l * DIMn,
                                 nv_w + l * DIMn, nv_b + l * DIMn, lnq, lnk, lnv);

        qkv_h<<<dim3(INNERn / 128, Bn * Ssz / 128, 3), 256, SMEMH_BYTES>>>(
            lnq, lnk, lnv,
            Wq16 + (long)l * DIMn * INNERn, Wk16 + (long)l * DIMn * INNERn,
            Wv16 + (long)l * DIMn * INNERn, qh, kh, vh);

        qk_h<<<dim3(Ssz / 128, Ssz / 128, Bn * Hn), 256>>>(qh, kh, sch);

        softmax_h<<<Bn * Hn * Ssz, 128>>>(sch, phh);

        pv_h<<<dim3(1, Ssz / 128, Bn * Hn), 256, SMEMPV_BYTES>>>(phh, vh, obh);

        wo_h<<<dim3(DIMn / 128, Bn * Ssz / 128), 256, SMEMH_BYTES>>>(
            obh, Wo16 + (long)l * INNERn * DIMn, X, bo + l * DIMn);

        ln1_k<<<Bn * Ssz, 256>>>(X, nm_w + l * DIMn, nm_b + l * DIMn, xnh);
        moe1_h<<<dim3(MLPn / 128, Ssz / 128, Bn * Kn), 256, SMEMH_BYTES>>>(
            xnh, W116 + (long)l * En * DIMn * MLPn, b1 + (long)l * En * MLPn, hbh, fe_l, fw_l);
        moe2_h<<<dim3(DIMn / 128, Ssz / 128, Bn * Kn), 256, SMEMH_BYTES>>>(
            hbh, W216 + (long)l * En * MLPn * DIMn, b2 + (long)l * En * DIMn, X, fe_l, fw_l);
    }
}

// round 16
// speedup vs baseline: 1.1592x; 1.0055x over previous
#include <cuda_runtime.h>
#include <cuda_fp16.h>
#include <math.h>
#include <mma.h>

using namespace nvcuda;

// ---------------- problem constants ----------------
#define Bn     8
#define Ssz    512
#define DIMn   1024
#define Hn     16
#define DHn    64
#define INNERn 1024
#define MLPn   4096
#define En     8
#define Kn     2
#define LRn    77
#define CAPn   2
#define Dlay   2

static const long SZX = (long)Bn * Ssz * DIMn;           // 4,194,304
static const long SZSC = (long)Bn * Hn * Ssz * Ssz;      // 33,554,432
static const long SZH  = (long)Bn * Kn * Ssz * MLPn;     // 33,554,432

// ---- fp32 arena (routing only) ----
static const long O_RM  = 0;
static const long O_LG  = O_RM + 8192;
static const long O_NL  = O_LG + 64;
static const long O_FW  = O_NL + 64;      // 32 floats (2 layers x 16)
static const long O_FE  = O_FW + 32;      // 32 ints
static const long O_USE = O_FE + 32;      // 16 ints (2 layers x 8 experts)
static const long ARENA_FLOATS = O_USE + 32;
__device__ __align__(16) float g_arena[ARENA_FLOATS];

// ---- fp16 arena ----
static const long H_LNQ = 0;
static const long H_LNK = H_LNQ + SZX;
static const long H_LNV = H_LNK + SZX;
static const long H_XN  = H_LNV + SZX;
static const long H_OB  = H_XN  + SZX;
static const long H_Q   = H_OB  + SZX;
static const long H_K   = H_Q   + SZX;
static const long H_V   = H_K   + SZX;
static const long H_S   = H_V   + SZX;            // fp16 scores
static const long H_P   = H_S   + SZSC;           // fp16 probs
static const long H_H   = H_P   + SZSC;
static const long H_WQ  = H_H   + SZH;
static const long H_WK  = H_WQ  + (long)Dlay * DIMn * INNERn;
static const long H_WV  = H_WK  + (long)Dlay * DIMn * INNERn;
static const long H_WO  = H_WV  + (long)Dlay * DIMn * INNERn;
static const long H_W1  = H_WO  + (long)Dlay * INNERn * DIMn;
static const long H_W2  = H_W1  + (long)Dlay * En * DIMn * MLPn;
static const long ARENA_HALVES = H_W2 + (long)Dlay * En * MLPn * DIMn;
__device__ __align__(16) __half g_harena[ARENA_HALVES];

// ---------------- reductions ----------------
__device__ __forceinline__ float warpSum(float v) {
    #pragma unroll
    for (int o = 16; o; o >>= 1) v += __shfl_xor_sync(0xffffffffu, v, o);
    return v;
}
__device__ __forceinline__ float warpMax(float v) {
    #pragma unroll
    for (int o = 16; o; o >>= 1) v = fmaxf(v, __shfl_xor_sync(0xffffffffu, v, o));
    return v;
}

// ---------------- threefry2x32 (JAX-exact) ----------------
__device__ __forceinline__ void tf2x32(unsigned k0, unsigned k1, unsigned x0, unsigned x1,
                                       unsigned& o0, unsigned& o1) {
    unsigned ks[3] = {k0, k1, k0 ^ k1 ^ 0x1BD11BDAu};
    const int R0[4] = {13, 15, 26, 6};
    const int R1[4] = {17, 29, 16, 24};
    x0 += ks[0]; x1 += ks[1];
    #pragma unroll
    for (int i = 0; i < 5; i++) {
        #pragma unroll
        for (int r = 0; r < 4; r++) {
            int rot = (i & 1) ? R1[r] : R0[r];
            x0 += x1;
            x1 = (x1 << rot) | (x1 >> (32 - rot));
            x1 ^= x0;
        }
        x0 += ks[(i + 1) % 3];
        x1 += ks[(i + 2) % 3] + (unsigned)(i + 1);
    }
    o0 = x0; o1 = x1;
}

// ---------------- fp32 -> fp16 converts (MLP=2, coalesced split) ----------------
__global__ void f2h4(const float4* __restrict__ src, __half2* __restrict__ dst, long n4) {
    long half = n4 >> 1;
    long i = (long)blockIdx.x * blockDim.x + threadIdx.x;
    if (i >= half) return;
    float4 v0 = src[i];
    float4 v1 = src[i + half];
    dst[2 * i]     = __floats2half2_rn(v0.x, v0.y);
    dst[2 * i + 1] = __floats2half2_rn(v0.z, v0.w);
    dst[2 * (i + half)]     = __floats2half2_rn(v1.x, v1.y);
    dst[2 * (i + half) + 1] = __floats2half2_rn(v1.z, v1.w);
}

// selective per-(layer,expert) conversion; early-exit if expert unused; MLP=2
__global__ void f2h_sel(const float4* __restrict__ src, __half2* __restrict__ dst,
                        const int* __restrict__ used, long n4_per) {
    int e = blockIdx.y;                      // 0..15 = l*8+e
    if (!used[e]) return;
    long half = n4_per >> 1;
    long i = (long)blockIdx.x * blockDim.x + threadIdx.x;
    if (i >= half) return;
    long base = (long)e * n4_per;
    long i0 = base + i, i1 = base + i + half;
    float4 v0 = src[i0];
    float4 v1 = src[i1];
    dst[2 * i0]     = __floats2half2_rn(v0.x, v0.y);
    dst[2 * i0 + 1] = __floats2half2_rn(v0.z, v0.w);
    dst[2 * i1]     = __floats2half2_rn(v1.x, v1.y);
    dst[2 * i1 + 1] = __floats2half2_rn(v1.z, v1.w);
}

// =================================================================
// fp16 WMMA machinery
// =================================================================
using HFragA  = wmma::fragment<wmma::matrix_a, 16, 16, 16, __half, wmma::row_major>;
using HFragB  = wmma::fragment<wmma::matrix_b, 16, 16, 16, __half, wmma::row_major>;
using HFragBc = wmma::fragment<wmma::matrix_b, 16, 16, 16, __half, wmma::col_major>;
using HFragC  = wmma::fragment<wmma::accumulator, 16, 16, 16, float>;

__device__ __forceinline__ void cpa16(void* dst_smem, const void* src) {
    unsigned d = (unsigned)__cvta_generic_to_shared(dst_smem);
    asm volatile("cp.async.cg.shared.global [%0], [%1], 16;\n" :: "r"(d), "l"(src));
}
__device__ __forceinline__ void cp_commit() { asm volatile("cp.async.commit_group;\n"); }
template <int N>
__device__ __forceinline__ void cp_wait() { asm volatile("cp.async.wait_group %0;\n" :: "n"(N)); }

// pack 8 fp32 -> one 16B fp16 store
__device__ __forceinline__ void st_half8(__half* dst, const float* v) {
    __half2 h0 = __floats2half2_rn(v[0], v[1]);
    __half2 h1 = __floats2half2_rn(v[2], v[3]);
    __half2 h2 = __floats2half2_rn(v[4], v[5]);
    __half2 h3 = __floats2half2_rn(v[6], v[7]);
    uint4 u;
    u.x = *(unsigned*)&h0; u.y = *(unsigned*)&h1;
    u.z = *(unsigned*)&h2; u.w = *(unsigned*)&h3;
    *(uint4*)dst = u;
}
// pack 4 fp32 -> one 8B fp16 store
__device__ __forceinline__ void st_half4(__half* dst, float a, float b, float c, float d) {
    __half2 h0 = __floats2half2_rn(a, b);
    __half2 h1 = __floats2half2_rn(c, d);
    uint2 u;
    u.x = *(unsigned*)&h0; u.y = *(unsigned*)&h1;
    *(uint2*)dst = u;
}

#define HA_STR 72
#define HB_STR 136
#define HA_STAGE (128 * HA_STR)
#define HB_STAGE (64 * HB_STR)
static const int SMEMH_BYTES = (2 * HA_STAGE + 2 * HB_STAGE) * 2;  // 71680 B

__device__ __forceinline__ void hmm_cp(const __half* __restrict__ A, const __half* __restrict__ B,
                                       int lda, int ldb, int K, int m0, int n0,
                                       __half* sm, HFragC (&acc)[2][4]) {
    __half* sA[2] = { sm, sm + HA_STAGE };
    __half* sB[2] = { sm + 2 * HA_STAGE, sm + 2 * HA_STAGE + HB_STAGE };
    int tid = threadIdx.x;
    int warp = tid >> 5, wm = warp & 3, wn = warp >> 2;
    int arow = tid >> 1, acH = (tid & 1) * 32;
    int brow = tid >> 2, bcH = (tid & 3) * 32;
    const __half* Ab = A + (long)(m0 + arow) * lda + acH;
    const __half* Bb = B + (long)brow * ldb + n0 + bcH;
    __half* dA[2] = { sA[0] + arow * HA_STR + acH, sA[1] + arow * HA_STR + acH };
    __half* dB[2] = { sB[0] + brow * HB_STR + bcH, sB[1] + brow * HB_STR + bcH };

    int nIt = K >> 6;
    #pragma unroll
    for (int i = 0; i < 4; i++) cpa16(dA[0] + i * 8, Ab + i * 8);
    #pragma unroll
    for (int i = 0; i < 4; i++) cpa16(dB[0] + i * 8, Bb + i * 8);
    cp_commit();

    #pragma unroll 1
    for (int it = 0; it < nIt; it++) {
        int s = it & 1;
        if (it + 1 < nIt) {
            int s2 = s ^ 1;
            const __half* a = Ab + (it + 1) * 64;
            const __half* b = Bb + (long)(it + 1) * 64 * ldb;
            #pragma unroll
            for (int i = 0; i < 4; i++) cpa16(dA[s2] + i * 8, a + i * 8);
            #pragma unroll
            for (int i = 0; i < 4; i++) cpa16(dB[s2] + i * 8, b + i * 8);
            cp_commit();
            cp_wait<1>();
        } else {
            cp_wait<0>();
        }
        __syncthreads();
        #pragma unroll
        for (int kk = 0; kk < 4; kk++) {
            HFragA af[2];
            #pragma unroll
            for (int i = 0; i < 2; i++)
                wmma::load_matrix_sync(af[i], sA[s] + (wm * 32 + i * 16) * HA_STR + kk * 16, HA_STR);
            #pragma unroll
            for (int j = 0; j < 4; j++) {
                HFragB bf;
                wmma::load_matrix_sync(bf, sB[s] + (kk * 16) * HB_STR + wn * 64 + j * 16, HB_STR);
                wmma::mma_sync(acc[0][j], af[0], bf, acc[0][j]);
                wmma::mma_sync(acc[1][j], af[1], bf, acc[1][j]);
            }
        }
        __syncthreads();
    }
}

__device__ __forceinline__ void hacc_zero(HFragC (&acc)[2][4]) {
    #pragma unroll
    for (int i = 0; i < 2; i++)
        #pragma unroll
        for (int j = 0; j < 4; j++) wmma::fill_fragment(acc[i][j], 0.0f);
}

// EPI: 1 = fp32 C += acc + bias (vec128) ; 2 = fp16 C = gelu(acc+bias) (vec128)
//      3 = atomicAdd(fp32 C, (acc+bias)*w) (scalar) ; 4 = fp16 C = acc (vec128)
template <int EPI>
__device__ __forceinline__ void hepilogue(HFragC (&acc)[2][4], float* stage_w,
                                          void* __restrict__ Cv, const float* __restrict__ bias,
                                          int ldc, int m0, int n0, float w) {
    int tid = threadIdx.x, warp = tid >> 5, lane = tid & 31;
    int wm = warp & 3, wn = warp >> 2;
    int r = lane >> 1, cb = (lane & 1) * 8;
    #pragma unroll
    for (int i = 0; i < 2; i++)
        #pragma unroll
        for (int j = 0; j < 4; j++) {
            wmma::store_matrix_sync(stage_w, acc[i][j], 20, wmma::mem_row_major);
            __syncwarp();
            int row = m0 + wm * 32 + i * 16 + r;
            int col0 = n0 + wn * 64 + j * 16 + cb;
            long idx0 = (long)row * ldc + col0;
            float vals[8];
            #pragma unroll
            for (int c = 0; c < 8; c++) vals[c] = stage_w[r * 20 + cb + c];
            if (EPI == 1) {
                float* C = (float*)Cv;
                float4 c0 = *(float4*)(C + idx0);
                float4 c1 = *(float4*)(C + idx0 + 4);
                float4 b0 = *(const float4*)(bias + col0);
                float4 b1 = *(const float4*)(bias + col0 + 4);
                c0.x += vals[0] + b0.x; c0.y += vals[1] + b0.y;
                c0.z += vals[2] + b0.z; c0.w += vals[3] + b0.w;
                c1.x += vals[4] + b1.x; c1.y += vals[5] + b1.y;
                c1.z += vals[6] + b1.z; c1.w += vals[7] + b1.w;
                *(float4*)(C + idx0) = c0;
                *(float4*)(C + idx0 + 4) = c1;
            } else if (EPI == 2) {
                #pragma unroll
                for (int c = 0; c < 8; c++) {
                    float u = vals[c] + bias[col0 + c];
                    vals[c] = 0.5f * u * (1.0f + erff(u * 0.70710678118654752f));
                }
                st_half8((__half*)Cv + idx0, vals);
            } else if (EPI == 3) {
                float* C = (float*)Cv;
                #pragma unroll
                for (int c = 0; c < 8; c++)
                    atomicAdd(&C[idx0 + c], (vals[c] + bias[col0 + c]) * w);
            } else {
                st_half8((__half*)Cv + idx0, vals);
            }
            __syncwarp();
        }
}

// fused QKV (fp16 in, fp16 out)
__global__ __launch_bounds__(256, 2) void qkv_h(const __half* __restrict__ lnq, const __half* __restrict__ lnk,
                                                const __half* __restrict__ lnv,
                                                const __half* __restrict__ Wq, const __half* __restrict__ Wk,
                                                const __half* __restrict__ Wv,
                                                __half* __restrict__ q, __half* __restrict__ k,
                                                __half* __restrict__ v) {
    extern __shared__ __half smh[];
    int z = blockIdx.z;
    const __half* A = (z == 0) ? lnq : (z == 1) ? lnk : lnv;
    const __half* B = (z == 0) ? Wq : (z == 1) ? Wk : Wv;
    __half* C = (z == 0) ? q : (z == 1) ? k : v;
    int m0 = blockIdx.y * 128, n0 = blockIdx.x * 128;
    HFragC acc[2][4];
    hacc_zero(acc);
    hmm_cp(A, B, DIMn, INNERn, DIMn, m0, n0, smh, acc);
    float* stage = (float*)smh + (threadIdx.x >> 5) * 320;
    hepilogue<4>(acc, stage, C, nullptr, INNERn, m0, n0, 0.0f);
}

// X += ob @ Wo + bo
__global__ __launch_bounds__(256, 2) void wo_h(const __half* __restrict__ A, const __half* __restrict__ B,
                                               float* __restrict__ C, const float* __restrict__ bias) {
    extern __shared__ __half smh[];
    int m0 = blockIdx.y * 128, n0 = blockIdx.x * 128;
    HFragC acc[2][4];
    hacc_zero(acc);
    hmm_cp(A, B, INNERn, DIMn, INNERn, m0, n0, smh, acc);
    float* stage = (float*)smh + (threadIdx.x >> 5) * 320;
    hepilogue<1>(acc, stage, C, bias, DIMn, m0, n0, 0.0f);
}

// MoE 1: H16 = gelu(xn16 @ W1[e] + b1[e])
__global__ __launch_bounds__(256, 2) void moe1_h(const __half* __restrict__ xn, const __half* __restrict__ W1l,
                                                 const float* __restrict__ b1l, __half* __restrict__ H,
                                                 const int* __restrict__ fe, const float* __restrict__ fw) {
    extern __shared__ __half smh[];
    int n = blockIdx.z;
    if (fw[n] == 0.0f) return;
    int e = fe[n];
    const __half* A = xn + (long)(n >> 1) * Ssz * DIMn;
    const __half* B = W1l + (long)e * DIMn * MLPn;
    __half* C = H + (long)n * Ssz * MLPn;
    const float* bias = b1l + (long)e * MLPn;
    int m0 = blockIdx.y * 128, n0 = blockIdx.x * 128;
    HFragC acc[2][4];
    hacc_zero(acc);
    hmm_cp(A, B, DIMn, MLPn, DIMn, m0, n0, smh, acc);
    float* stage = (float*)smh + (threadIdx.x >> 5) * 320;
    hepilogue<2>(acc, stage, C, bias, MLPn, m0, n0, 0.0f);
}

// MoE 2: X[slot>>1] += (H16 @ W2[e] + b2[e]) * w
__global__ __launch_bounds__(256, 2) void moe2_h(const __half* __restrict__ H, const __half* __restrict__ W2l,
                                                 const float* __restrict__ b2l, float* __restrict__ X,
                                                 const int* __restrict__ fe, const float* __restrict__ fw) {
    extern __shared__ __half smh[];
    int n = blockIdx.z;
    float w = fw[n];
    if (w == 0.0f) return;
    int e = fe[n];
    const __half* A = H + (long)n * Ssz * MLPn;
    const __half* B = W2l + (long)e * MLPn * DIMn;
    float* C = X + (long)(n >> 1) * Ssz * DIMn;
    const float* bias = b2l + (long)e * DIMn;
    int m0 = blockIdx.y * 128, n0 = blockIdx.x * 128;
    HFragC acc[2][4];
    hacc_zero(acc);
    hmm_cp(A, B, MLPn, DIMn, MLPn, m0, n0, smh, acc);
    float* stage = (float*)smh + (threadIdx.x >> 5) * 320;
    hepilogue<3>(acc, stage, C, bias, DIMn, m0, n0, w);
}

// =================================================================
// Attention: QK^T (fp16 scores, vectorized epilogue), softmax (vec fp16), PV
// =================================================================
__global__ __launch_bounds__(256, 2) void qk_h(const __half* __restrict__ qh, const __half* __restrict__ kh,
                                               __half* __restrict__ sc) {
    __shared__ __half sQ[128 * 72];
    __shared__ __half sK[128 * 72];
    int z = blockIdx.z, b = z >> 4, h = z & 15;
    const __half* Qb = qh + (long)b * Ssz * INNERn + h * DHn;
    const __half* Kb = kh + (long)b * Ssz * INNERn + h * DHn;
    __half* C = sc + (long)z * Ssz * Ssz;
    int m0 = blockIdx.y * 128, n0 = blockIdx.x * 128;
    int tid = threadIdx.x;
    int row = tid >> 1, colH = (tid & 1) * 32;
    #pragma unroll
    for (int i = 0; i < 4; i++) {
        cpa16(sQ + row * 72 + colH + i * 8, Qb + (long)(m0 + row) * INNERn + colH + i * 8);
        cpa16(sK + row * 72 + colH + i * 8, Kb + (long)(n0 + row) * INNERn + colH + i * 8);
    }
    cp_commit(); cp_wait<0>();
    __syncthreads();
    int warp = tid >> 5, wm = warp & 3, wn = warp >> 2;
    HFragC acc[2][4];
    hacc_zero(acc);
    #pragma unroll
    for (int kk = 0; kk < 4; kk++) {
        HFragA af[2];
        #pragma unroll
        for (int i = 0; i < 2; i++)
            wmma::load_matrix_sync(af[i], sQ + (wm * 32 + i * 16) * 72 + kk * 16, 72);
        #pragma unroll
        for (int j = 0; j < 4; j++) {
            HFragBc bf;
            wmma::load_matrix_sync(bf, sK + (wn * 64 + j * 16) * 72 + kk * 16, 72);
            wmma::mma_sync(acc[0][j], af[0], bf, acc[0][j]);
            wmma::mma_sync(acc[1][j], af[1], bf, acc[1][j]);
        }
    }
    #pragma unroll
    for (int i = 0; i < 2; i++)
        #pragma unroll
        for (int j = 0; j < 4; j++)
            #pragma unroll
            for (int e = 0; e < acc[i][j].num_elements; e++) acc[i][j].x[e] *= 0.125f;
    __syncthreads();   // all smem MMA reads done; reuse sQ as epilogue stage
    float* stage = (float*)sQ + warp * 320;
    hepilogue<4>(acc, stage, C, nullptr, Ssz, m0, n0, 0.0f);
}

// softmax rows of 512: fp16 in -> fp16 out, 8B vector I/O
__global__ __launch_bounds__(128) void softmax_h(const __half* __restrict__ S, __half* __restrict__ P) {
    __shared__ float sh[4];
    long row = blockIdx.x;
    const uint2* p2 = (const uint2*)(S + row * 512);
    uint2* o2 = (uint2*)(P + row * 512);
    int t = threadIdx.x;
    uint2 u = p2[t];
    __half2 ha = *(__half2*)&u.x, hb = *(__half2*)&u.y;
    float2 a = __half22float2(ha);
    float2 b = __half22float2(hb);
    float v[4] = {a.x, a.y, b.x, b.y};
    float m = fmaxf(fmaxf(v[0], v[1]), fmaxf(v[2], v[3]));
    m = warpMax(m);
    if ((t & 31) == 0) sh[t >> 5] = m;
    __syncthreads();
    if (t < 32) { float x = (t < 4) ? sh[t] : -INFINITY; x = warpMax(x); if (t == 0) sh[0] = x; }
    __syncthreads();
    m = sh[0];
    __syncthreads();
    float s = 0.f;
    #pragma unroll
    for (int i = 0; i < 4; i++) { v[i] = expf(v[i] - m); s += v[i]; }
    s = warpSum(s);
    if ((t & 31) == 0) sh[t >> 5] = s;
    __syncthreads();
    if (t < 32) { float x = (t < 4) ? sh[t] : 0.f; x = warpSum(x); if (t == 0) sh[0] = x; }
    __syncthreads();
    float inv = 1.0f / sh[0];
    __half2 w0 = __floats2half2_rn(v[0] * inv, v[1] * inv);
    __half2 w1 = __floats2half2_rn(v[2] * inv, v[3] * inv);
    uint2 o;
    o.x = *(unsigned*)&w0; o.y = *(unsigned*)&w1;
    o2[t] = o;
}

#define PV_SPSZ (128 * 72)
#define PV_SVSZ (64 * 72)
static const int SMEMPV_BYTES = (2 * PV_SPSZ + 2 * PV_SVSZ) * 2;   // 55296 B

__global__ __launch_bounds__(256, 2) void pv_h(const __half* __restrict__ ph, const __half* __restrict__ vh,
                                               __half* __restrict__ ob) {
    extern __shared__ __half smp[];
    __half* sP[2] = { smp, smp + PV_SPSZ };
    __half* sV[2] = { smp + 2 * PV_SPSZ, smp + 2 * PV_SPSZ + PV_SVSZ };
    int z = blockIdx.z, b = z >> 4, h = z & 15;
    const __half* Pb = ph + (long)z * Ssz * Ssz;
    const __half* Vb = vh + (long)b * Ssz * INNERn + h * DHn;
    __half* Ob = ob + (long)b * Ssz * INNERn + h * DHn;
    int m0 = blockIdx.y * 128;
    int tid = threadIdx.x;
    int prow = tid >> 1, pcol = (tid & 1) * 32;
    int vrow = tid >> 2, vcol = (tid & 3) * 16;

    #pragma unroll
    for (int i = 0; i < 4; i++) cpa16(sP[0] + prow * 72 + pcol + i * 8, Pb + (long)(m0 + prow) * Ssz + pcol + i * 8);
    #pragma unroll
    for (int i = 0; i < 2; i++) cpa16(sV[0] + vrow * 72 + vcol + i * 8, Vb + (long)vrow * INNERn + vcol + i * 8);
    cp_commit();

    int warp = tid >> 5, wm = warp & 3, wn = warp >> 2;
    HFragC acc[2][2];
    #pragma unroll
    for (int i = 0; i < 2; i++)
        #pragma unroll
        for (int j = 0; j < 2; j++) wmma::fill_fragment(acc[i][j], 0.0f);

    #pragma unroll 1
    for (int it = 0; it < 8; it++) {
        int s = it & 1;
        if (it + 1 < 8) {
            int s2 = s ^ 1, k0 = (it + 1) * 64;
            #pragma unroll
            for (int i = 0; i < 4; i++)
                cpa16(sP[s2] + prow * 72 + pcol + i * 8, Pb + (long)(m0 + prow) * Ssz + k0 + pcol + i * 8);
            #pragma unroll
            for (int i = 0; i < 2; i++)
                cpa16(sV[s2] + vrow * 72 + vcol + i * 8, Vb + (long)(k0 + vrow) * INNERn + vcol + i * 8);
            cp_commit();
            cp_wait<1>();
        } else {
            cp_wait<0>();
        }
        __syncthreads();
        #pragma unroll
        for (int kk = 0; kk < 4; kk++) {
            HFragA af[2];
            #pragma unroll
            for (int i = 0; i < 2; i++)
                wmma::load_matrix_sync(af[i], sP[s] + (wm * 32 + i * 16) * 72 + kk * 16, 72);
            #pragma unroll
            for (int j = 0; j < 2; j++) {
                HFragB bf;
                wmma::load_matrix_sync(bf, sV[s] + (kk * 16) * 72 + wn * 32 + j * 16, 72);
                wmma::mma_sync(acc[0][j], af[0], bf, acc[0][j]);
                wmma::mma_sync(acc[1][j], af[1], bf, acc[1][j]);
            }
        }
        __syncthreads();
    }
    float* stage = (float*)smp + warp * 320;
    int lane = tid & 31, r = lane >> 1, cb = (lane & 1) * 8;
    #pragma unroll
    for (int i = 0; i < 2; i++)
        #pragma unroll
        for (int j = 0; j < 2; j++) {
            wmma::store_matrix_sync(stage, acc[i][j], 20, wmma::mem_row_major);
            __syncwarp();
            int row = m0 + wm * 32 + i * 16 + r;
            int col0 = wn * 32 + j * 16 + cb;
            float vals[8];
            #pragma unroll
            for (int c = 0; c < 8; c++) vals[c] = stage[r * 20 + cb + c];
            st_half8(Ob + (long)row * INNERn + col0, vals);
            __syncwarp();
        }
}

// ---------------- LayerNorm (vectorized, fp16 outputs) ----------------
__global__ __launch_bounds__(256) void ln3_k(const float* __restrict__ X,
                                             const float* __restrict__ wq, const float* __restrict__ bq,
                                             const float* __restrict__ wk, const float* __restrict__ bk,
                                             const float* __restrict__ wv, const float* __restrict__ bv,
                                             __half* __restrict__ oq, __half* __restrict__ ok,
                                             __half* __restrict__ ov) {
    __shared__ float sh[8];
    long row = blockIdx.x;
    const float* xr = X + row * DIMn;
    int t = threadIdx.x;
    int c0 = t * 4;
    float4 xv = *(const float4*)(xr + c0);
    float v[4] = {xv.x, xv.y, xv.z, xv.w};
    float s = v[0] + v[1] + v[2] + v[3];
    s = warpSum(s);
    if ((t & 31) == 0) sh[t >> 5] = s;
    __syncthreads();
    if (t < 32) { float a = (t < 8) ? sh[t] : 0.f; a = warpSum(a); if (t == 0) sh[0] = a; }
    __syncthreads();
    float mean = sh[0] * (1.0f / DIMn);
    __syncthreads();
    float ss = 0.f;
    #pragma unroll
    for (int i = 0; i < 4; i++) { float d = v[i] - mean; ss += d * d; }
    ss = warpSum(ss);
    if ((t & 31) == 0) sh[t >> 5] = ss;
    __syncthreads();
    if (t < 32) { float a = (t < 8) ? sh[t] : 0.f; a = warpSum(a); if (t == 0) sh[0] = a; }
    __syncthreads();
    float rstd = rsqrtf(sh[0] * (1.0f / DIMn) + 1e-5f);
    float xh[4];
    #pragma unroll
    for (int i = 0; i < 4; i++) xh[i] = (v[i] - mean) * rstd;
    long idx = row * DIMn + c0;
    float4 w4, b4;
    w4 = *(const float4*)(wq + c0); b4 = *(const float4*)(bq + c0);
    st_half4(oq + idx, xh[0] * w4.x + b4.x, xh[1] * w4.y + b4.y, xh[2] * w4.z + b4.z, xh[3] * w4.w + b4.w);
    w4 = *(const float4*)(wk + c0); b4 = *(const float4*)(bk + c0);
    st_half4(ok + idx, xh[0] * w4.x + b4.x, xh[1] * w4.y + b4.y, xh[2] * w4.z + b4.z, xh[3] * w4.w + b4.w);
    w4 = *(const float4*)(wv + c0); b4 = *(const float4*)(bv + c0);
    st_half4(ov + idx, xh[0] * w4.x + b4.x, xh[1] * w4.y + b4.y, xh[2] * w4.z + b4.z, xh[3] * w4.w + b4.w);
}

__global__ __launch_bounds__(256) void ln1_k(const float* __restrict__ X,
                                             const float* __restrict__ w, const float* __restrict__ b,
                                             __half* __restrict__ out) {
    __shared__ float sh[8];
    long row = blockIdx.x;
    const float* xr = X + row * DIMn;
    int t = threadIdx.x;
    int c0 = t * 4;
    float4 xv = *(const float4*)(xr + c0);
    float v[4] = {xv.x, xv.y, xv.z, xv.w};
    float s = v[0] + v[1] + v[2] + v[3];
    s = warpSum(s);
    if ((t & 31) == 0) sh[t >> 5] = s;
    __syncthreads();
    if (t < 32) { float a = (t < 8) ? sh[t] : 0.f; a = warpSum(a); if (t == 0) sh[0] = a; }
    __syncthreads();
    float mean = sh[0] * (1.0f / DIMn);
    __syncthreads();
    float ss = 0.f;
    #pragma unroll
    for (int i = 0; i < 4; i++) { float d = v[i] - mean; ss += d * d; }
    ss = warpSum(ss);
    if ((t & 31) == 0) sh[t >> 5] = ss;
    __syncthreads();
    if (t < 32) { float a = (t < 8) ? sh[t] : 0.f; a = warpSum(a); if (t == 0) sh[0] = a; }
    __syncthreads();
    float rstd = rsqrtf(sh[0] * (1.0f / DIMn) + 1e-5f);
    float4 w4 = *(const float4*)(w + c0);
    float4 b4 = *(const float4*)(b + c0);
    long idx = row * DIMn + c0;
    st_half4(out + idx,
             (v[0] - mean) * rstd * w4.x + b4.x,
             (v[1] - mean) * rstd * w4.y + b4.y,
             (v[2] - mean) * rstd * w4.z + b4.z,
             (v[3] - mean) * rstd * w4.w + b4.w);
}

// ---------------- router mean over LR ----------------
__global__ void rimean_k(const float* __restrict__ ri, float* __restrict__ rm) {
    int i = blockIdx.x * 256 + threadIdx.x;
    int b = i >> 10, d = i & 1023;
    float s = 0.f;
    for (int r = 0; r < LRn; r++) s += ri[((long)b * LRn + r) * DIMn + d];
    rm[i] = s * (1.0f / LRn);
}

// ---------------- router logits ----------------
__global__ __launch_bounds__(256) void logits_k(const float* __restrict__ rm,
                                                const float* __restrict__ Wr, const float* __restrict__ br,
                                                const float* __restrict__ Wn, const float* __restrict__ bn,
                                                float* __restrict__ lg, float* __restrict__ nl) {
    __shared__ float sh[16];
    int b = blockIdx.x >> 3, e = blockIdx.x & 7;
    int t = threadIdx.x;
    float s1 = 0.f, s2 = 0.f;
    for (int d = t; d < DIMn; d += 256) {
        float r = rm[b * DIMn + d];
        s1 += r * Wr[(long)d * En + e];
        s2 += r * Wn[(long)d * En + e];
    }
    s1 = warpSum(s1); s2 = warpSum(s2);
    if ((t & 31) == 0) { sh[t >> 5] = s1; sh[8 + (t >> 5)] = s2; }
    __syncthreads();
    if (t == 0) {
        float a = 0.f, c = 0.f;
        for (int i = 0; i < 8; i++) { a += sh[i]; c += sh[8 + i]; }
        lg[blockIdx.x] = a + br[e];
        nl[blockIdx.x] = c + bn[e];
    }
}

// ---------------- noisy top-k routing + capacity + used-expert flags ----------------
__global__ void route_k(const float* __restrict__ logits, const float* __restrict__ nlog, int l,
                        int* __restrict__ fe, float* __restrict__ fw, int* __restrict__ used) {
    __shared__ float sc[64];
    __shared__ int se[16];
    __shared__ float sg[16];
    int t = threadIdx.x;
    if (t < 64) {
        unsigned kk0, kk1;
        tf2x32(0u, 42u, 0u, (unsigned)l, kk0, kk1);
        unsigned o0, o1;
        tf2x32(kk0, kk1, 0u, (unsigned)t, o0, o1);
        unsigned bits = o0 ^ o1;
        float f = __uint_as_float(0x3f800000u | (bits >> 9)) - 1.0f;
        const float lo = -0.99999994f;
        float u = f * 2.0f + lo;
        u = fmaxf(lo, u);
        float g = 1.41421356237309515f * erfinvf(u);
        float xnl = nlog[t];
        float sp = fmaxf(xnl, 0.f) + log1pf(expf(-fabsf(xnl)));
        sc[t] = logits[t] + g * sp;
    }
    __syncthreads();
    if (t < 8) {
        const float* row = sc + t * 8;
        int e0 = 0; float v0 = row[0];
        for (int e = 1; e < 8; e++) if (row[e] > v0) { v0 = row[e]; e0 = e; }
        int e1 = -1; float v1 = -INFINITY;
        for (int e = 0; e < 8; e++) if (e != e0 && row[e] > v1) { v1 = row[e]; e1 = e; }
        float d = expf(v1 - v0);
        float inv = 1.0f / (1.0f + d);
        se[t * 2] = e0; se[t * 2 + 1] = e1;
        sg[t * 2] = inv; sg[t * 2 + 1] = d * inv;
    }
    __syncthreads();
    if (t == 0) {
        int cnt[8] = {0, 0, 0, 0, 0, 0, 0, 0};
        int us[8]  = {0, 0, 0, 0, 0, 0, 0, 0};
        for (int n = 0; n < 16; n++) {
            int e = se[n];
            float w = (cnt[e] < CAPn) ? sg[n] : 0.0f;
            cnt[e]++;
            fe[n] = e; fw[n] = w;
            if (w != 0.0f) us[e] = 1;
        }
        for (int e = 0; e < 8; e++) used[e] = us[e];
    }
}

// ---------------- host launch ----------------
static void conv_w_on(cudaStream_t st, const float* src, __half* dst, long n) {
    long half = n / 8;   // n4/2
    int blocks = (int)((half + 255) / 256);
    f2h4<<<blocks, 256, 0, st>>>((const float4*)src, (__half2*)dst, n / 4);
}

extern "C" void kernel_launch(void* const* d_in, const int* in_sizes, int n_in,
                              void* d_out, int out_size) {
    (void)in_sizes; (void)n_in; (void)out_size;
    const float* router_input = (const float*)d_in[0];
    const float* x0   = (const float*)d_in[1];
    const float* nq_w = (const float*)d_in[2];
    const float* nq_b = (const float*)d_in[3];
    const float* nk_w = (const float*)d_in[4];
    const float* nk_b = (const float*)d_in[5];
    const float* nv_w = (const float*)d_in[6];
    const float* nv_b = (const float*)d_in[7];
    const float* Wq   = (const float*)d_in[8];
    const float* Wk   = (const float*)d_in[9];
    const float* Wv   = (const float*)d_in[10];
    const float* Wo   = (const float*)d_in[11];
    const float* bo   = (const float*)d_in[12];
    const float* nm_w = (const float*)d_in[13];
    const float* nm_b = (const float*)d_in[14];
    const float* Wr   = (const float*)d_in[15];
    const float* br   = (const float*)d_in[16];
    const float* Wn   = (const float*)d_in[17];
    const float* bn   = (const float*)d_in[18];
    const float* W1   = (const float*)d_in[19];
    const float* b1   = (const float*)d_in[20];
    const float* W2   = (const float*)d_in[21];
    const float* b2   = (const float*)d_in[22];

    float* X = (float*)d_out;
    float* arena = nullptr;
    cudaGetSymbolAddress((void**)&arena, g_arena);
    __half* ha = nullptr;
    cudaGetSymbolAddress((void**)&ha, g_harena);

    float* rm   = arena + O_RM;
    float* lg   = arena + O_LG;
    float* nl   = arena + O_NL;
    float* fw   = arena + O_FW;
    int*   fe   = (int*)(arena + O_FE);
    int*   used = (int*)(arena + O_USE);

    __half* lnq = ha + H_LNQ;
    __half* lnk = ha + H_LNK;
    __half* lnv = ha + H_LNV;
    __half* xnh = ha + H_XN;
    __half* obh = ha + H_OB;
    __half* qh  = ha + H_Q;
    __half* kh  = ha + H_K;
    __half* vh  = ha + H_V;
    __half* sch = ha + H_S;
    __half* phh = ha + H_P;
    __half* hbh = ha + H_H;
    __half* Wq16 = ha + H_WQ;
    __half* Wk16 = ha + H_WK;
    __half* Wv16 = ha + H_WV;
    __half* Wo16 = ha + H_WO;
    __half* W116 = ha + H_W1;
    __half* W216 = ha + H_W2;

    cudaFuncSetAttribute(qkv_h, cudaFuncAttributeMaxDynamicSharedMemorySize, SMEMH_BYTES);
    cudaFuncSetAttribute(wo_h, cudaFuncAttributeMaxDynamicSharedMemorySize, SMEMH_BYTES);
    cudaFuncSetAttribute(moe1_h, cudaFuncAttributeMaxDynamicSharedMemorySize, SMEMH_BYTES);
    cudaFuncSetAttribute(moe2_h, cudaFuncAttributeMaxDynamicSharedMemorySize, SMEMH_BYTES);
    cudaFuncSetAttribute(pv_h, cudaFuncAttributeMaxDynamicSharedMemorySize, SMEMPV_BYTES);

    // persistent side streams + events (created once on first, uncaptured call;
    // every call enqueues the identical DAG — work is deterministic per call)
    static cudaStream_t sDense = nullptr, sMoe = nullptr;
    static cudaEvent_t evRoot = nullptr, evDense = nullptr, evRoute = nullptr, evMoeW = nullptr;
    if (!sDense) {
        cudaStreamCreateWithFlags(&sDense, cudaStreamNonBlocking);
        cudaStreamCreateWithFlags(&sMoe, cudaStreamNonBlocking);
        cudaEventCreateWithFlags(&evRoot, cudaEventDisableTiming);
        cudaEventCreateWithFlags(&evDense, cudaEventDisableTiming);
        cudaEventCreateWithFlags(&evRoute, cudaEventDisableTiming);
        cudaEventCreateWithFlags(&evMoeW, cudaEventDisableTiming);
    }

    // ---- fork sDense at entry: dense weight conversions ----
    cudaEventRecord(evRoot, 0);
    cudaStreamWaitEvent(sDense, evRoot, 0);
    conv_w_on(sDense, Wq, Wq16, (long)Dlay * DIMn * INNERn);
    conv_w_on(sDense, Wk, Wk16, (long)Dlay * DIMn * INNERn);
    conv_w_on(sDense, Wv, Wv16, (long)Dlay * DIMn * INNERn);
    conv_w_on(sDense, Wo, Wo16, (long)Dlay * INNERn * DIMn);
    cudaEventRecord(evDense, sDense);

    // ---- main stream: routing chain ----
    rimean_k<<<32, 256>>>(router_input, rm);
    for (int l = 0; l < Dlay; l++) {
        logits_k<<<Bn * En, 256>>>(rm, Wr + (long)l * DIMn * En, br + l * En,
                                   Wn + (long)l * DIMn * En, bn + l * En, lg, nl);
        route_k<<<1, 64>>>(lg, nl, l, fe + 16 * l, fw + 16 * l, used + 8 * l);
    }

    // ---- fork sMoe after routing: selective W1/W2 conversions ----
    cudaEventRecord(evRoute, 0);
    cudaStreamWaitEvent(sMoe, evRoute, 0);
    {
        long n4_per = (long)DIMn * MLPn / 4;
        long half = n4_per >> 1;
        dim3 g((unsigned)((half + 255) / 256), Dlay * En);
        f2h_sel<<<g, 256, 0, sMoe>>>((const float4*)W1, (__half2*)W116, used, n4_per);
        f2h_sel<<<g, 256, 0, sMoe>>>((const float4*)W2, (__half2*)W216, used, n4_per);
    }
    cudaEventRecord(evMoeW, sMoe);

    // ---- main stream continues: X init + layers ----
    cudaMemcpyAsync(X, x0, sizeof(float) * SZX, cudaMemcpyDeviceToDevice);

    for (int l = 0; l < Dlay; l++) {
        const int* fe_l = fe + 16 * l;
        const float* fw_l = fw + 16 * l;

        ln3_k<<<Bn * Ssz, 256>>>(X, nq_w + l * DIMn, nq_b + l * DIMn,
                                 nk_w + l * DIMn, nk_b + l * DIMn,
                                 nv_w + l * DIMn, nv_b + l * DIMn, lnq, lnk, lnv);

        if (l == 0) cudaStreamWaitEvent(0, evDense, 0);   // dense weights ready before qkv

        qkv_h<<<dim3(INNERn / 128, Bn * Ssz / 128, 3), 256, SMEMH_BYTES>>>(
            lnq, lnk, lnv,
            Wq16 + (long)l * DIMn * INNERn, Wk16 + (long)l * DIMn * INNERn,
            Wv16 + (long)l * DIMn * INNERn, qh, kh, vh);

        qk_h<<<dim3(Ssz / 128, Ssz / 128, Bn * Hn), 256>>>(qh, kh, sch);

        softmax_h<<<Bn * Hn * Ssz, 128>>>(sch, phh);

        pv_h<<<dim3(1, Ssz / 128, Bn * Hn), 256, SMEMPV_BYTES>>>(phh, vh, obh);

        wo_h<<<dim3(DIMn / 128, Bn * Ssz / 128), 256, SMEMH_BYTES>>>(
            obh, Wo16 + (long)l * INNERn * DIMn, X, bo + l * DIMn);

        ln1_k<<<Bn * Ssz, 256>>>(X, nm_w + l * DIMn, nm_b + l * DIMn, xnh);

        if (l == 0) cudaStreamWaitEvent(0, evMoeW, 0);    // MoE weights ready before first moe1

        moe1_h<<<dim3(MLPn / 128, Ssz / 128, Bn * Kn), 256, SMEMH_BYTES>>>(
            xnh, W116 + (long)l * En * DIMn * MLPn, b1 + (long)l * En * MLPn, hbh, fe_l, fw_l);
        moe2_h<<<dim3(DIMn / 128, Ssz / 128, Bn * Kn), 256, SMEMH_BYTES>>>(
            hbh, W216 + (long)l * En * MLPn * DIMn, b2 + (long)l * En * DIMn, X, fe_l, fw_l);
    }
}

// round 17
// speedup vs baseline: 1.1679x; 1.0075x over previous
#include <cuda_runtime.h>
#include <cuda_fp16.h>
#include <math.h>
#include <mma.h>

using namespace nvcuda;

// ---------------- problem constants ----------------
#define Bn     8
#define Ssz    512
#define DIMn   1024
#define Hn     16
#define DHn    64
#define INNERn 1024
#define MLPn   4096
#define En     8
#define Kn     2
#define LRn    77
#define CAPn   2
#define Dlay   2

static const long SZX = (long)Bn * Ssz * DIMn;           // 4,194,304
static const long SZSC = (long)Bn * Hn * Ssz * Ssz;      // 33,554,432
static const long SZH  = (long)Bn * Kn * Ssz * MLPn;     // 33,554,432
static const long SZY  = (long)Bn * Kn * Ssz * DIMn;     // 8,388,608 (per-slot moe2 outputs)

// ---- fp32 arena ----
static const long O_RM  = 0;
static const long O_LG  = O_RM + 8192;
static const long O_NL  = O_LG + 64;
static const long O_FW  = O_NL + 64;      // 32 floats (2 layers x 16)
static const long O_FE  = O_FW + 32;      // 32 ints
static const long O_USE = O_FE + 32;      // 16 ints (2 layers x 8 experts)
static const long O_Y   = O_USE + 32;
static const long ARENA_FLOATS = O_Y + SZY;
__device__ __align__(16) float g_arena[ARENA_FLOATS];

// ---- fp16 arena ----
static const long H_LNQ = 0;
static const long H_LNK = H_LNQ + SZX;
static const long H_LNV = H_LNK + SZX;
static const long H_XN  = H_LNV + SZX;
static const long H_OB  = H_XN  + SZX;
static const long H_Q   = H_OB  + SZX;
static const long H_K   = H_Q   + SZX;
static const long H_V   = H_K   + SZX;
static const long H_S   = H_V   + SZX;            // fp16 scores
static const long H_P   = H_S   + SZSC;           // fp16 probs
static const long H_H   = H_P   + SZSC;
static const long H_WQ  = H_H   + SZH;
static const long H_WK  = H_WQ  + (long)Dlay * DIMn * INNERn;
static const long H_WV  = H_WK  + (long)Dlay * DIMn * INNERn;
static const long H_WO  = H_WV  + (long)Dlay * DIMn * INNERn;
static const long H_W1  = H_WO  + (long)Dlay * INNERn * DIMn;
static const long H_W2  = H_W1  + (long)Dlay * En * DIMn * MLPn;
static const long ARENA_HALVES = H_W2 + (long)Dlay * En * MLPn * DIMn;
__device__ __align__(16) __half g_harena[ARENA_HALVES];

// ---------------- reductions ----------------
__device__ __forceinline__ float warpSum(float v) {
    #pragma unroll
    for (int o = 16; o; o >>= 1) v += __shfl_xor_sync(0xffffffffu, v, o);
    return v;
}
__device__ __forceinline__ float warpMax(float v) {
    #pragma unroll
    for (int o = 16; o; o >>= 1) v = fmaxf(v, __shfl_xor_sync(0xffffffffu, v, o));
    return v;
}

// ---------------- threefry2x32 (JAX-exact) ----------------
__device__ __forceinline__ void tf2x32(unsigned k0, unsigned k1, unsigned x0, unsigned x1,
                                       unsigned& o0, unsigned& o1) {
    unsigned ks[3] = {k0, k1, k0 ^ k1 ^ 0x1BD11BDAu};
    const int R0[4] = {13, 15, 26, 6};
    const int R1[4] = {17, 29, 16, 24};
    x0 += ks[0]; x1 += ks[1];
    #pragma unroll
    for (int i = 0; i < 5; i++) {
        #pragma unroll
        for (int r = 0; r < 4; r++) {
            int rot = (i & 1) ? R1[r] : R0[r];
            x0 += x1;
            x1 = (x1 << rot) | (x1 >> (32 - rot));
            x1 ^= x0;
        }
        x0 += ks[(i + 1) % 3];
        x1 += ks[(i + 2) % 3] + (unsigned)(i + 1);
    }
    o0 = x0; o1 = x1;
}

// ---------------- fp32 -> fp16 converts (MLP=2, coalesced split) ----------------
__global__ void f2h4(const float4* __restrict__ src, __half2* __restrict__ dst, long n4) {
    long half = n4 >> 1;
    long i = (long)blockIdx.x * blockDim.x + threadIdx.x;
    if (i >= half) return;
    float4 v0 = src[i];
    float4 v1 = src[i + half];
    dst[2 * i]     = __floats2half2_rn(v0.x, v0.y);
    dst[2 * i + 1] = __floats2half2_rn(v0.z, v0.w);
    dst[2 * (i + half)]     = __floats2half2_rn(v1.x, v1.y);
    dst[2 * (i + half) + 1] = __floats2half2_rn(v1.z, v1.w);
}

// selective per-(layer,expert) conversion; early-exit if expert unused; MLP=2
__global__ void f2h_sel(const float4* __restrict__ src, __half2* __restrict__ dst,
                        const int* __restrict__ used, long n4_per) {
    int e = blockIdx.y;                      // 0..15 = l*8+e
    if (!used[e]) return;
    long half = n4_per >> 1;
    long i = (long)blockIdx.x * blockDim.x + threadIdx.x;
    if (i >= half) return;
    long base = (long)e * n4_per;
    long i0 = base + i, i1 = base + i + half;
    float4 v0 = src[i0];
    float4 v1 = src[i1];
    dst[2 * i0]     = __floats2half2_rn(v0.x, v0.y);
    dst[2 * i0 + 1] = __floats2half2_rn(v0.z, v0.w);
    dst[2 * i1]     = __floats2half2_rn(v1.x, v1.y);
    dst[2 * i1 + 1] = __floats2half2_rn(v1.z, v1.w);
}

// =================================================================
// fp16 WMMA machinery
// =================================================================
using HFragA  = wmma::fragment<wmma::matrix_a, 16, 16, 16, __half, wmma::row_major>;
using HFragB  = wmma::fragment<wmma::matrix_b, 16, 16, 16, __half, wmma::row_major>;
using HFragBc = wmma::fragment<wmma::matrix_b, 16, 16, 16, __half, wmma::col_major>;
using HFragC  = wmma::fragment<wmma::accumulator, 16, 16, 16, float>;

__device__ __forceinline__ void cpa16(void* dst_smem, const void* src) {
    unsigned d = (unsigned)__cvta_generic_to_shared(dst_smem);
    asm volatile("cp.async.cg.shared.global [%0], [%1], 16;\n" :: "r"(d), "l"(src));
}
__device__ __forceinline__ void cp_commit() { asm volatile("cp.async.commit_group;\n"); }
template <int N>
__device__ __forceinline__ void cp_wait() { asm volatile("cp.async.wait_group %0;\n" :: "n"(N)); }

// pack 8 fp32 -> one 16B fp16 store
__device__ __forceinline__ void st_half8(__half* dst, const float* v) {
    __half2 h0 = __floats2half2_rn(v[0], v[1]);
    __half2 h1 = __floats2half2_rn(v[2], v[3]);
    __half2 h2 = __floats2half2_rn(v[4], v[5]);
    __half2 h3 = __floats2half2_rn(v[6], v[7]);
    uint4 u;
    u.x = *(unsigned*)&h0; u.y = *(unsigned*)&h1;
    u.z = *(unsigned*)&h2; u.w = *(unsigned*)&h3;
    *(uint4*)dst = u;
}
// pack 4 fp32 -> one 8B fp16 store
__device__ __forceinline__ void st_half4(__half* dst, float a, float b, float c, float d) {
    __half2 h0 = __floats2half2_rn(a, b);
    __half2 h1 = __floats2half2_rn(c, d);
    uint2 u;
    u.x = *(unsigned*)&h0; u.y = *(unsigned*)&h1;
    *(uint2*)dst = u;
}

#define HA_STR 72
#define HB_STR 136
#define HA_STAGE (128 * HA_STR)
#define HB_STAGE (64 * HB_STR)
static const int SMEMH_BYTES = (2 * HA_STAGE + 2 * HB_STAGE) * 2;  // 71680 B

__device__ __forceinline__ void hmm_cp(const __half* __restrict__ A, const __half* __restrict__ B,
                                       int lda, int ldb, int K, int m0, int n0,
                                       __half* sm, HFragC (&acc)[2][4]) {
    __half* sA[2] = { sm, sm + HA_STAGE };
    __half* sB[2] = { sm + 2 * HA_STAGE, sm + 2 * HA_STAGE + HB_STAGE };
    int tid = threadIdx.x;
    int warp = tid >> 5, wm = warp & 3, wn = warp >> 2;
    int arow = tid >> 1, acH = (tid & 1) * 32;
    int brow = tid >> 2, bcH = (tid & 3) * 32;
    const __half* Ab = A + (long)(m0 + arow) * lda + acH;
    const __half* Bb = B + (long)brow * ldb + n0 + bcH;
    __half* dA[2] = { sA[0] + arow * HA_STR + acH, sA[1] + arow * HA_STR + acH };
    __half* dB[2] = { sB[0] + brow * HB_STR + bcH, sB[1] + brow * HB_STR + bcH };

    int nIt = K >> 6;
    #pragma unroll
    for (int i = 0; i < 4; i++) cpa16(dA[0] + i * 8, Ab + i * 8);
    #pragma unroll
    for (int i = 0; i < 4; i++) cpa16(dB[0] + i * 8, Bb + i * 8);
    cp_commit();

    #pragma unroll 1
    for (int it = 0; it < nIt; it++) {
        int s = it & 1;
        if (it + 1 < nIt) {
            int s2 = s ^ 1;
            const __half* a = Ab + (it + 1) * 64;
            const __half* b = Bb + (long)(it + 1) * 64 * ldb;
            #pragma unroll
            for (int i = 0; i < 4; i++) cpa16(dA[s2] + i * 8, a + i * 8);
            #pragma unroll
            for (int i = 0; i < 4; i++) cpa16(dB[s2] + i * 8, b + i * 8);
            cp_commit();
            cp_wait<1>();
        } else {
            cp_wait<0>();
        }
        __syncthreads();
        #pragma unroll
        for (int kk = 0; kk < 4; kk++) {
            HFragA af[2];
            #pragma unroll
            for (int i = 0; i < 2; i++)
                wmma::load_matrix_sync(af[i], sA[s] + (wm * 32 + i * 16) * HA_STR + kk * 16, HA_STR);
            #pragma unroll
            for (int j = 0; j < 4; j++) {
                HFragB bf;
                wmma::load_matrix_sync(bf, sB[s] + (kk * 16) * HB_STR + wn * 64 + j * 16, HB_STR);
                wmma::mma_sync(acc[0][j], af[0], bf, acc[0][j]);
                wmma::mma_sync(acc[1][j], af[1], bf, acc[1][j]);
            }
        }
        __syncthreads();
    }
}

__device__ __forceinline__ void hacc_zero(HFragC (&acc)[2][4]) {
    #pragma unroll
    for (int i = 0; i < 2; i++)
        #pragma unroll
        for (int j = 0; j < 4; j++) wmma::fill_fragment(acc[i][j], 0.0f);
}

// EPI: 1 = fp32 C += acc + bias (vec128) ; 2 = fp16 C = gelu(acc+bias) (vec128)
//      4 = fp16 C = acc (vec128) ; 5 = fp32 C = (acc + bias)*w (vec128, no RMW)
template <int EPI>
__device__ __forceinline__ void hepilogue(HFragC (&acc)[2][4], float* stage_w,
                                          void* __restrict__ Cv, const float* __restrict__ bias,
                                          int ldc, int m0, int n0, float w) {
    int tid = threadIdx.x, warp = tid >> 5, lane = tid & 31;
    int wm = warp & 3, wn = warp >> 2;
    int r = lane >> 1, cb = (lane & 1) * 8;
    #pragma unroll
    for (int i = 0; i < 2; i++)
        #pragma unroll
        for (int j = 0; j < 4; j++) {
            wmma::store_matrix_sync(stage_w, acc[i][j], 20, wmma::mem_row_major);
            __syncwarp();
            int row = m0 + wm * 32 + i * 16 + r;
            int col0 = n0 + wn * 64 + j * 16 + cb;
            long idx0 = (long)row * ldc + col0;
            float vals[8];
            #pragma unroll
            for (int c = 0; c < 8; c++) vals[c] = stage_w[r * 20 + cb + c];
            if (EPI == 1) {
                float* C = (float*)Cv;
                float4 c0 = *(float4*)(C + idx0);
                float4 c1 = *(float4*)(C + idx0 + 4);
                float4 b0 = *(const float4*)(bias + col0);
                float4 b1 = *(const float4*)(bias + col0 + 4);
                c0.x += vals[0] + b0.x; c0.y += vals[1] + b0.y;
                c0.z += vals[2] + b0.z; c0.w += vals[3] + b0.w;
                c1.x += vals[4] + b1.x; c1.y += vals[5] + b1.y;
                c1.z += vals[6] + b1.z; c1.w += vals[7] + b1.w;
                *(float4*)(C + idx0) = c0;
                *(float4*)(C + idx0 + 4) = c1;
            } else if (EPI == 2) {
                #pragma unroll
                for (int c = 0; c < 8; c++) {
                    float u = vals[c] + bias[col0 + c];
                    vals[c] = 0.5f * u * (1.0f + erff(u * 0.70710678118654752f));
                }
                st_half8((__half*)Cv + idx0, vals);
            } else if (EPI == 5) {
                float* C = (float*)Cv;
                float4 b0 = *(const float4*)(bias + col0);
                float4 b1 = *(const float4*)(bias + col0 + 4);
                float4 c0, c1;
                c0.x = (vals[0] + b0.x) * w; c0.y = (vals[1] + b0.y) * w;
                c0.z = (vals[2] + b0.z) * w; c0.w = (vals[3] + b0.w) * w;
                c1.x = (vals[4] + b1.x) * w; c1.y = (vals[5] + b1.y) * w;
                c1.z = (vals[6] + b1.z) * w; c1.w = (vals[7] + b1.w) * w;
                *(float4*)(C + idx0) = c0;
                *(float4*)(C + idx0 + 4) = c1;
            } else {
                st_half8((__half*)Cv + idx0, vals);
            }
            __syncwarp();
        }
}

// fused QKV (fp16 in, fp16 out)
__global__ __launch_bounds__(256, 2) void qkv_h(const __half* __restrict__ lnq, const __half* __restrict__ lnk,
                                                const __half* __restrict__ lnv,
                                                const __half* __restrict__ Wq, const __half* __restrict__ Wk,
                                                const __half* __restrict__ Wv,
                                                __half* __restrict__ q, __half* __restrict__ k,
                                                __half* __restrict__ v) {
    extern __shared__ __half smh[];
    int z = blockIdx.z;
    const __half* A = (z == 0) ? lnq : (z == 1) ? lnk : lnv;
    const __half* B = (z == 0) ? Wq : (z == 1) ? Wk : Wv;
    __half* C = (z == 0) ? q : (z == 1) ? k : v;
    int m0 = blockIdx.y * 128, n0 = blockIdx.x * 128;
    HFragC acc[2][4];
    hacc_zero(acc);
    hmm_cp(A, B, DIMn, INNERn, DIMn, m0, n0, smh, acc);
    float* stage = (float*)smh + (threadIdx.x >> 5) * 320;
    hepilogue<4>(acc, stage, C, nullptr, INNERn, m0, n0, 0.0f);
}

// X += ob @ Wo + bo
__global__ __launch_bounds__(256, 2) void wo_h(const __half* __restrict__ A, const __half* __restrict__ B,
                                               float* __restrict__ C, const float* __restrict__ bias) {
    extern __shared__ __half smh[];
    int m0 = blockIdx.y * 128, n0 = blockIdx.x * 128;
    HFragC acc[2][4];
    hacc_zero(acc);
    hmm_cp(A, B, INNERn, DIMn, INNERn, m0, n0, smh, acc);
    float* stage = (float*)smh + (threadIdx.x >> 5) * 320;
    hepilogue<1>(acc, stage, C, bias, DIMn, m0, n0, 0.0f);
}

// MoE 1: H16 = gelu(xn16 @ W1[e] + b1[e])
__global__ __launch_bounds__(256, 2) void moe1_h(const __half* __restrict__ xn, const __half* __restrict__ W1l,
                                                 const float* __restrict__ b1l, __half* __restrict__ H,
                                                 const int* __restrict__ fe, const float* __restrict__ fw) {
    extern __shared__ __half smh[];
    int n = blockIdx.z;
    if (fw[n] == 0.0f) return;
    int e = fe[n];
    const __half* A = xn + (long)(n >> 1) * Ssz * DIMn;
    const __half* B = W1l + (long)e * DIMn * MLPn;
    __half* C = H + (long)n * Ssz * MLPn;
    const float* bias = b1l + (long)e * MLPn;
    int m0 = blockIdx.y * 128, n0 = blockIdx.x * 128;
    HFragC acc[2][4];
    hacc_zero(acc);
    hmm_cp(A, B, DIMn, MLPn, DIMn, m0, n0, smh, acc);
    float* stage = (float*)smh + (threadIdx.x >> 5) * 320;
    hepilogue<2>(acc, stage, C, bias, MLPn, m0, n0, 0.0f);
}

// MoE 2: Y[slot] = (H16 @ W2[e] + b2[e]) * w   (plain vec stores, no atomics)
__global__ __launch_bounds__(256, 2) void moe2_h(const __half* __restrict__ H, const __half* __restrict__ W2l,
                                                 const float* __restrict__ b2l, float* __restrict__ Y,
                                                 const int* __restrict__ fe, const float* __restrict__ fw) {
    extern __shared__ __half smh[];
    int n = blockIdx.z;
    float w = fw[n];
    if (w == 0.0f) return;
    int e = fe[n];
    const __half* A = H + (long)n * Ssz * MLPn;
    const __half* B = W2l + (long)e * MLPn * DIMn;
    float* C = Y + (long)n * Ssz * DIMn;
    const float* bias = b2l + (long)e * DIMn;
    int m0 = blockIdx.y * 128, n0 = blockIdx.x * 128;
    HFragC acc[2][4];
    hacc_zero(acc);
    hmm_cp(A, B, MLPn, DIMn, MLPn, m0, n0, smh, acc);
    float* stage = (float*)smh + (threadIdx.x >> 5) * 320;
    hepilogue<5>(acc, stage, C, bias, DIMn, m0, n0, w);
}

// combine: X[b] += Y[2b] + Y[2b+1]  (skip dropped slots)
#define SAMP4 (Ssz * DIMn / 4)   // 131072 float4 per sample
__global__ __launch_bounds__(256) void comb_k(const float4* __restrict__ Y, float4* __restrict__ X,
                                              const float* __restrict__ fw) {
    long i = (long)blockIdx.x * 256 + threadIdx.x;   // over SZX/4
    int b = (int)(i / SAMP4);
    long o = i - (long)b * SAMP4;
    float4 x = X[i];
    if (fw[2 * b] != 0.0f) {
        float4 y = Y[(long)(2 * b) * SAMP4 + o];
        x.x += y.x; x.y += y.y; x.z += y.z; x.w += y.w;
    }
    if (fw[2 * b + 1] != 0.0f) {
        float4 y = Y[(long)(2 * b + 1) * SAMP4 + o];
        x.x += y.x; x.y += y.y; x.z += y.z; x.w += y.w;
    }
    X[i] = x;
}

// =================================================================
// Attention: QK^T (fp16 scores, vectorized epilogue), softmax (vec fp16), PV
// =================================================================
__global__ __launch_bounds__(256, 2) void qk_h(const __half* __restrict__ qh, const __half* __restrict__ kh,
                                               __half* __restrict__ sc) {
    __shared__ __half sQ[128 * 72];
    __shared__ __half sK[128 * 72];
    int z = blockIdx.z, b = z >> 4, h = z & 15;
    const __half* Qb = qh + (long)b * Ssz * INNERn + h * DHn;
    const __half* Kb = kh + (long)b * Ssz * INNERn + h * DHn;
    __half* C = sc + (long)z * Ssz * Ssz;
    int m0 = blockIdx.y * 128, n0 = blockIdx.x * 128;
    int tid = threadIdx.x;
    int row = tid >> 1, colH = (tid & 1) * 32;
    #pragma unroll
    for (int i = 0; i < 4; i++) {
        cpa16(sQ + row * 72 + colH + i * 8, Qb + (long)(m0 + row) * INNERn + colH + i * 8);
        cpa16(sK + row * 72 + colH + i * 8, Kb + (long)(n0 + row) * INNERn + colH + i * 8);
    }
    cp_commit(); cp_wait<0>();
    __syncthreads();
    int warp = tid >> 5, wm = warp & 3, wn = warp >> 2;
    HFragC acc[2][4];
    hacc_zero(acc);
    #pragma unroll
    for (int kk = 0; kk < 4; kk++) {
        HFragA af[2];
        #pragma unroll
        for (int i = 0; i < 2; i++)
            wmma::load_matrix_sync(af[i], sQ + (wm * 32 + i * 16) * 72 + kk * 16, 72);
        #pragma unroll
        for (int j = 0; j < 4; j++) {
            HFragBc bf;
            wmma::load_matrix_sync(bf, sK + (wn * 64 + j * 16) * 72 + kk * 16, 72);
            wmma::mma_sync(acc[0][j], af[0], bf, acc[0][j]);
            wmma::mma_sync(acc[1][j], af[1], bf, acc[1][j]);
        }
    }
    #pragma unroll
    for (int i = 0; i < 2; i++)
        #pragma unroll
        for (int j = 0; j < 4; j++)
            #pragma unroll
            for (int e = 0; e < acc[i][j].num_elements; e++) acc[i][j].x[e] *= 0.125f;
    __syncthreads();   // all smem MMA reads done; reuse sQ as epilogue stage
    float* stage = (float*)sQ + warp * 320;
    hepilogue<4>(acc, stage, C, nullptr, Ssz, m0, n0, 0.0f);
}

// softmax rows of 512: fp16 in -> fp16 out, 8B vector I/O
__global__ __launch_bounds__(128) void softmax_h(const __half* __restrict__ S, __half* __restrict__ P) {
    __shared__ float sh[4];
    long row = blockIdx.x;
    const uint2* p2 = (const uint2*)(S + row * 512);
    uint2* o2 = (uint2*)(P + row * 512);
    int t = threadIdx.x;
    uint2 u = p2[t];
    __half2 ha = *(__half2*)&u.x, hb = *(__half2*)&u.y;
    float2 a = __half22float2(ha);
    float2 b = __half22float2(hb);
    float v[4] = {a.x, a.y, b.x, b.y};
    float m = fmaxf(fmaxf(v[0], v[1]), fmaxf(v[2], v[3]));
    m = warpMax(m);
    if ((t & 31) == 0) sh[t >> 5] = m;
    __syncthreads();
    if (t < 32) { float x = (t < 4) ? sh[t] : -INFINITY; x = warpMax(x); if (t == 0) sh[0] = x; }
    __syncthreads();
    m = sh[0];
    __syncthreads();
    float s = 0.f;
    #pragma unroll
    for (int i = 0; i < 4; i++) { v[i] = expf(v[i] - m); s += v[i]; }
    s = warpSum(s);
    if ((t & 31) == 0) sh[t >> 5] = s;
    __syncthreads();
    if (t < 32) { float x = (t < 4) ? sh[t] : 0.f; x = warpSum(x); if (t == 0) sh[0] = x; }
    __syncthreads();
    float inv = 1.0f / sh[0];
    __half2 w0 = __floats2half2_rn(v[0] * inv, v[1] * inv);
    __half2 w1 = __floats2half2_rn(v[2] * inv, v[3] * inv);
    uint2 o;
    o.x = *(unsigned*)&w0; o.y = *(unsigned*)&w1;
    o2[t] = o;
}

#define PV_SPSZ (128 * 72)
#define PV_SVSZ (64 * 72)
static const int SMEMPV_BYTES = (2 * PV_SPSZ + 2 * PV_SVSZ) * 2;   // 55296 B

__global__ __launch_bounds__(256, 2) void pv_h(const __half* __restrict__ ph, const __half* __restrict__ vh,
                                               __half* __restrict__ ob) {
    extern __shared__ __half smp[];
    __half* sP[2] = { smp, smp + PV_SPSZ };
    __half* sV[2] = { smp + 2 * PV_SPSZ, smp + 2 * PV_SPSZ + PV_SVSZ };
    int z = blockIdx.z, b = z >> 4, h = z & 15;
    const __half* Pb = ph + (long)z * Ssz * Ssz;
    const __half* Vb = vh + (long)b * Ssz * INNERn + h * DHn;
    __half* Ob = ob + (long)b * Ssz * INNERn + h * DHn;
    int m0 = blockIdx.y * 128;
    int tid = threadIdx.x;
    int prow = tid >> 1, pcol = (tid & 1) * 32;
    int vrow = tid >> 2, vcol = (tid & 3) * 16;

    #pragma unroll
    for (int i = 0; i < 4; i++) cpa16(sP[0] + prow * 72 + pcol + i * 8, Pb + (long)(m0 + prow) * Ssz + pcol + i * 8);
    #pragma unroll
    for (int i = 0; i < 2; i++) cpa16(sV[0] + vrow * 72 + vcol + i * 8, Vb + (long)vrow * INNERn + vcol + i * 8);
    cp_commit();

    int warp = tid >> 5, wm = warp & 3, wn = warp >> 2;
    HFragC acc[2][2];
    #pragma unroll
    for (int i = 0; i < 2; i++)
        #pragma unroll
        for (int j = 0; j < 2; j++) wmma::fill_fragment(acc[i][j], 0.0f);

    #pragma unroll 1
    for (int it = 0; it < 8; it++) {
        int s = it & 1;
        if (it + 1 < 8) {
            int s2 = s ^ 1, k0 = (it + 1) * 64;
            #pragma unroll
            for (int i = 0; i < 4; i++)
                cpa16(sP[s2] + prow * 72 + pcol + i * 8, Pb + (long)(m0 + prow) * Ssz + k0 + pcol + i * 8);
            #pragma unroll
            for (int i = 0; i < 2; i++)
                cpa16(sV[s2] + vrow * 72 + vcol + i * 8, Vb + (long)(k0 + vrow) * INNERn + vcol + i * 8);
            cp_commit();
            cp_wait<1>();
        } else {
            cp_wait<0>();
        }
        __syncthreads();
        #pragma unroll
        for (int kk = 0; kk < 4; kk++) {
            HFragA af[2];
            #pragma unroll
            for (int i = 0; i < 2; i++)
                wmma::load_matrix_sync(af[i], sP[s] + (wm * 32 + i * 16) * 72 + kk * 16, 72);
            #pragma unroll
            for (int j = 0; j < 2; j++) {
                HFragB bf;
                wmma::load_matrix_sync(bf, sV[s] + (kk * 16) * 72 + wn * 32 + j * 16, 72);
                wmma::mma_sync(acc[0][j], af[0], bf, acc[0][j]);
                wmma::mma_sync(acc[1][j], af[1], bf, acc[1][j]);
            }
        }
        __syncthreads();
    }
    float* stage = (float*)smp + warp * 320;
    int lane = tid & 31, r = lane >> 1, cb = (lane & 1) * 8;
    #pragma unroll
    for (int i = 0; i < 2; i++)
        #pragma unroll
        for (int j = 0; j < 2; j++) {
            wmma::store_matrix_sync(stage, acc[i][j], 20, wmma::mem_row_major);
            __syncwarp();
            int row = m0 + wm * 32 + i * 16 + r;
            int col0 = wn * 32 + j * 16 + cb;
            float vals[8];
            #pragma unroll
            for (int c = 0; c < 8; c++) vals[c] = stage[r * 20 + cb + c];
            st_half8(Ob + (long)row * INNERn + col0, vals);
            __syncwarp();
        }
}

// ---------------- LayerNorm (vectorized, fp16 outputs) ----------------
__global__ __launch_bounds__(256) void ln3_k(const float* __restrict__ X,
                                             const float* __restrict__ wq, const float* __restrict__ bq,
                                             const float* __restrict__ wk, const float* __restrict__ bk,
                                             const float* __restrict__ wv, const float* __restrict__ bv,
                                             __half* __restrict__ oq, __half* __restrict__ ok,
                                             __half* __restrict__ ov) {
    __shared__ float sh[8];
    long row = blockIdx.x;
    const float* xr = X + row * DIMn;
    int t = threadIdx.x;
    int c0 = t * 4;
    float4 xv = *(const float4*)(xr + c0);
    float v[4] = {xv.x, xv.y, xv.z, xv.w};
    float s = v[0] + v[1] + v[2] + v[3];
    s = warpSum(s);
    if ((t & 31) == 0) sh[t >> 5] = s;
    __syncthreads();
    if (t < 32) { float a = (t < 8) ? sh[t] : 0.f; a = warpSum(a); if (t == 0) sh[0] = a; }
    __syncthreads();
    float mean = sh[0] * (1.0f / DIMn);
    __syncthreads();
    float ss = 0.f;
    #pragma unroll
    for (int i = 0; i < 4; i++) { float d = v[i] - mean; ss += d * d; }
    ss = warpSum(ss);
    if ((t & 31) == 0) sh[t >> 5] = ss;
    __syncthreads();
    if (t < 32) { float a = (t < 8) ? sh[t] : 0.f; a = warpSum(a); if (t == 0) sh[0] = a; }
    __syncthreads();
    float rstd = rsqrtf(sh[0] * (1.0f / DIMn) + 1e-5f);
    float xh[4];
    #pragma unroll
    for (int i = 0; i < 4; i++) xh[i] = (v[i] - mean) * rstd;
    long idx = row * DIMn + c0;
    float4 w4, b4;
    w4 = *(const float4*)(wq + c0); b4 = *(const float4*)(bq + c0);
    st_half4(oq + idx, xh[0] * w4.x + b4.x, xh[1] * w4.y + b4.y, xh[2] * w4.z + b4.z, xh[3] * w4.w + b4.w);
    w4 = *(const float4*)(wk + c0); b4 = *(const float4*)(bk + c0);
    st_half4(ok + idx, xh[0] * w4.x + b4.x, xh[1] * w4.y + b4.y, xh[2] * w4.z + b4.z, xh[3] * w4.w + b4.w);
    w4 = *(const float4*)(wv + c0); b4 = *(const float4*)(bv + c0);
    st_half4(ov + idx, xh[0] * w4.x + b4.x, xh[1] * w4.y + b4.y, xh[2] * w4.z + b4.z, xh[3] * w4.w + b4.w);
}

__global__ __launch_bounds__(256) void ln1_k(const float* __restrict__ X,
                                             const float* __restrict__ w, const float* __restrict__ b,
                                             __half* __restrict__ out) {
    __shared__ float sh[8];
    long row = blockIdx.x;
    const float* xr = X + row * DIMn;
    int t = threadIdx.x;
    int c0 = t * 4;
    float4 xv = *(const float4*)(xr + c0);
    float v[4] = {xv.x, xv.y, xv.z, xv.w};
    float s = v[0] + v[1] + v[2] + v[3];
    s = warpSum(s);
    if ((t & 31) == 0) sh[t >> 5] = s;
    __syncthreads();
    if (t < 32) { float a = (t < 8) ? sh[t] : 0.f; a = warpSum(a); if (t == 0) sh[0] = a; }
    __syncthreads();
    float mean = sh[0] * (1.0f / DIMn);
    __syncthreads();
    float ss = 0.f;
    #pragma unroll
    for (int i = 0; i < 4; i++) { float d = v[i] - mean; ss += d * d; }
    ss = warpSum(ss);
    if ((t & 31) == 0) sh[t >> 5] = ss;
    __syncthreads();
    if (t < 32) { float a = (t < 8) ? sh[t] : 0.f; a = warpSum(a); if (t == 0) sh[0] = a; }
    __syncthreads();
    float rstd = rsqrtf(sh[0] * (1.0f / DIMn) + 1e-5f);
    float4 w4 = *(const float4*)(w + c0);
    float4 b4 = *(const float4*)(b + c0);
    long idx = row * DIMn + c0;
    st_half4(out + idx,
             (v[0] - mean) * rstd * w4.x + b4.x,
             (v[1] - mean) * rstd * w4.y + b4.y,
             (v[2] - mean) * rstd * w4.z + b4.z,
             (v[3] - mean) * rstd * w4.w + b4.w);
}

// ---------------- router mean over LR ----------------
__global__ void rimean_k(const float* __restrict__ ri, float* __restrict__ rm) {
    int i = blockIdx.x * 256 + threadIdx.x;
    int b = i >> 10, d = i & 1023;
    float s = 0.f;
    for (int r = 0; r < LRn; r++) s += ri[((long)b * LRn + r) * DIMn + d];
    rm[i] = s * (1.0f / LRn);
}

// ---------------- router logits ----------------
__global__ __launch_bounds__(256) void logits_k(const float* __restrict__ rm,
                                                const float* __restrict__ Wr, const float* __restrict__ br,
                                                const float* __restrict__ Wn, const float* __restrict__ bn,
                                                float* __restrict__ lg, float* __restrict__ nl) {
    __shared__ float sh[16];
    int b = blockIdx.x >> 3, e = blockIdx.x & 7;
    int t = threadIdx.x;
    float s1 = 0.f, s2 = 0.f;
    for (int d = t; d < DIMn; d += 256) {
        float r = rm[b * DIMn + d];
        s1 += r * Wr[(long)d * En + e];
        s2 += r * Wn[(long)d * En + e];
    }
    s1 = warpSum(s1); s2 = warpSum(s2);
    if ((t & 31) == 0) { sh[t >> 5] = s1; sh[8 + (t >> 5)] = s2; }
    __syncthreads();
    if (t == 0) {
        float a = 0.f, c = 0.f;
        for (int i = 0; i < 8; i++) { a += sh[i]; c += sh[8 + i]; }
        lg[blockIdx.x] = a + br[e];
        nl[blockIdx.x] = c + bn[e];
    }
}

// ---------------- noisy top-k routing + capacity + used-expert flags ----------------
__global__ void route_k(const float* __restrict__ logits, const float* __restrict__ nlog, int l,
                        int* __restrict__ fe, float* __restrict__ fw, int* __restrict__ used) {
    __shared__ float sc[64];
    __shared__ int se[16];
    __shared__ float sg[16];
    int t = threadIdx.x;
    if (t < 64) {
        unsigned kk0, kk1;
        tf2x32(0u, 42u, 0u, (unsigned)l, kk0, kk1);
        unsigned o0, o1;
        tf2x32(kk0, kk1, 0u, (unsigned)t, o0, o1);
        unsigned bits = o0 ^ o1;
        float f = __uint_as_float(0x3f800000u | (bits >> 9)) - 1.0f;
        const float lo = -0.99999994f;
        float u = f * 2.0f + lo;
        u = fmaxf(lo, u);
        float g = 1.41421356237309515f * erfinvf(u);
        float xnl = nlog[t];
        float sp = fmaxf(xnl, 0.f) + log1pf(expf(-fabsf(xnl)));
        sc[t] = logits[t] + g * sp;
    }
    __syncthreads();
    if (t < 8) {
        const float* row = sc + t * 8;
        int e0 = 0; float v0 = row[0];
        for (int e = 1; e < 8; e++) if (row[e] > v0) { v0 = row[e]; e0 = e; }
        int e1 = -1; float v1 = -INFINITY;
        for (int e = 0; e < 8; e++) if (e != e0 && row[e] > v1) { v1 = row[e]; e1 = e; }
        float d = expf(v1 - v0);
        float inv = 1.0f / (1.0f + d);
        se[t * 2] = e0; se[t * 2 + 1] = e1;
        sg[t * 2] = inv; sg[t * 2 + 1] = d * inv;
    }
    __syncthreads();
    if (t == 0) {
        int cnt[8] = {0, 0, 0, 0, 0, 0, 0, 0};
        int us[8]  = {0, 0, 0, 0, 0, 0, 0, 0};
        for (int n = 0; n < 16; n++) {
            int e = se[n];
            float w = (cnt[e] < CAPn) ? sg[n] : 0.0f;
            cnt[e]++;
            fe[n] = e; fw[n] = w;
            if (w != 0.0f) us[e] = 1;
        }
        for (int e = 0; e < 8; e++) used[e] = us[e];
    }
}

// ---------------- host launch ----------------
static void conv_w_on(cudaStream_t st, const float* src, __half* dst, long n) {
    long half = n / 8;
    int blocks = (int)((half + 255) / 256);
    f2h4<<<blocks, 256, 0, st>>>((const float4*)src, (__half2*)dst, n / 4);
}

extern "C" void kernel_launch(void* const* d_in, const int* in_sizes, int n_in,
                              void* d_out, int out_size) {
    (void)in_sizes; (void)n_in; (void)out_size;
    const float* router_input = (const float*)d_in[0];
    const float* x0   = (const float*)d_in[1];
    const float* nq_w = (const float*)d_in[2];
    const float* nq_b = (const float*)d_in[3];
    const float* nk_w = (const float*)d_in[4];
    const float* nk_b = (const float*)d_in[5];
    const float* nv_w = (const float*)d_in[6];
    const float* nv_b = (const float*)d_in[7];
    const float* Wq   = (const float*)d_in[8];
    const float* Wk   = (const float*)d_in[9];
    const float* Wv   = (const float*)d_in[10];
    const float* Wo   = (const float*)d_in[11];
    const float* bo   = (const float*)d_in[12];
    const float* nm_w = (const float*)d_in[13];
    const float* nm_b = (const float*)d_in[14];
    const float* Wr   = (const float*)d_in[15];
    const float* br   = (const float*)d_in[16];
    const float* Wn   = (const float*)d_in[17];
    const float* bn   = (const float*)d_in[18];
    const float* W1   = (const float*)d_in[19];
    const float* b1   = (const float*)d_in[20];
    const float* W2   = (const float*)d_in[21];
    const float* b2   = (const float*)d_in[22];

    float* X = (float*)d_out;
    float* arena = nullptr;
    cudaGetSymbolAddress((void**)&arena, g_arena);
    __half* ha = nullptr;
    cudaGetSymbolAddress((void**)&ha, g_harena);

    float* rm   = arena + O_RM;
    float* lg   = arena + O_LG;
    float* nl   = arena + O_NL;
    float* fw   = arena + O_FW;
    int*   fe   = (int*)(arena + O_FE);
    int*   used = (int*)(arena + O_USE);
    float* Yb   = arena + O_Y;

    __half* lnq = ha + H_LNQ;
    __half* lnk = ha + H_LNK;
    __half* lnv = ha + H_LNV;
    __half* xnh = ha + H_XN;
    __half* obh = ha + H_OB;
    __half* qh  = ha + H_Q;
    __half* kh  = ha + H_K;
    __half* vh  = ha + H_V;
    __half* sch = ha + H_S;
    __half* phh = ha + H_P;
    __half* hbh = ha + H_H;
    __half* Wq16 = ha + H_WQ;
    __half* Wk16 = ha + H_WK;
    __half* Wv16 = ha + H_WV;
    __half* Wo16 = ha + H_WO;
    __half* W116 = ha + H_W1;
    __half* W216 = ha + H_W2;

    cudaFuncSetAttribute(qkv_h, cudaFuncAttributeMaxDynamicSharedMemorySize, SMEMH_BYTES);
    cudaFuncSetAttribute(wo_h, cudaFuncAttributeMaxDynamicSharedMemorySize, SMEMH_BYTES);
    cudaFuncSetAttribute(moe1_h, cudaFuncAttributeMaxDynamicSharedMemorySize, SMEMH_BYTES);
    cudaFuncSetAttribute(moe2_h, cudaFuncAttributeMaxDynamicSharedMemorySize, SMEMH_BYTES);
    cudaFuncSetAttribute(pv_h, cudaFuncAttributeMaxDynamicSharedMemorySize, SMEMPV_BYTES);

    static cudaStream_t sDense = nullptr, sMoe = nullptr;
    static cudaEvent_t evRoot = nullptr, evDense = nullptr, evRoute = nullptr, evMoeW = nullptr;
    if (!sDense) {
        cudaStreamCreateWithFlags(&sDense, cudaStreamNonBlocking);
        cudaStreamCreateWithFlags(&sMoe, cudaStreamNonBlocking);
        cudaEventCreateWithFlags(&evRoot, cudaEventDisableTiming);
        cudaEventCreateWithFlags(&evDense, cudaEventDisableTiming);
        cudaEventCreateWithFlags(&evRoute, cudaEventDisableTiming);
        cudaEventCreateWithFlags(&evMoeW, cudaEventDisableTiming);
    }

    // fork sDense at entry: dense weight conversions
    cudaEventRecord(evRoot, 0);
    cudaStreamWaitEvent(sDense, evRoot, 0);
    conv_w_on(sDense, Wq, Wq16, (long)Dlay * DIMn * INNERn);
    conv_w_on(sDense, Wk, Wk16, (long)Dlay * DIMn * INNERn);
    conv_w_on(sDense, Wv, Wv16, (long)Dlay * DIMn * INNERn);
    conv_w_on(sDense, Wo, Wo16, (long)Dlay * INNERn * DIMn);
    cudaEventRecord(evDense, sDense);

    // main stream: routing chain
    rimean_k<<<32, 256>>>(router_input, rm);
    for (int l = 0; l < Dlay; l++) {
        logits_k<<<Bn * En, 256>>>(rm, Wr + (long)l * DIMn * En, br + l * En,
                                   Wn + (long)l * DIMn * En, bn + l * En, lg, nl);
        route_k<<<1, 64>>>(lg, nl, l, fe + 16 * l, fw + 16 * l, used + 8 * l);
    }

    // fork sMoe after routing: selective W1/W2 conversions
    cudaEventRecord(evRoute, 0);
    cudaStreamWaitEvent(sMoe, evRoute, 0);
    {
        long n4_per = (long)DIMn * MLPn / 4;
        long half = n4_per >> 1;
        dim3 g((unsigned)((half + 255) / 256), Dlay * En);
        f2h_sel<<<g, 256, 0, sMoe>>>((const float4*)W1, (__half2*)W116, used, n4_per);
        f2h_sel<<<g, 256, 0, sMoe>>>((const float4*)W2, (__half2*)W216, used, n4_per);
    }
    cudaEventRecord(evMoeW, sMoe);

    cudaMemcpyAsync(X, x0, sizeof(float) * SZX, cudaMemcpyDeviceToDevice);

    for (int l = 0; l < Dlay; l++) {
        const int* fe_l = fe + 16 * l;
        const float* fw_l = fw + 16 * l;

        ln3_k<<<Bn * Ssz, 256>>>(X, nq_w + l * DIMn, nq_b + l * DIMn,
                                 nk_w + l * DIMn, nk_b + l * DIMn,
                                 nv_w + l * DIMn, nv_b + l * DIMn, lnq, lnk, lnv);

        if (l == 0) cudaStreamWaitEvent(0, evDense, 0);

        qkv_h<<<dim3(INNERn / 128, Bn * Ssz / 128, 3), 256, SMEMH_BYTES>>>(
            lnq, lnk, lnv,
            Wq16 + (long)l * DIMn * INNERn, Wk16 + (long)l * DIMn * INNERn,
            Wv16 + (long)l * DIMn * INNERn, qh, kh, vh);

        qk_h<<<dim3(Ssz / 128, Ssz / 128, Bn * Hn), 256>>>(qh, kh, sch);

        softmax_h<<<Bn * Hn * Ssz, 128>>>(sch, phh);

        pv_h<<<dim3(1, Ssz / 128, Bn * Hn), 256, SMEMPV_BYTES>>>(phh, vh, obh);

        wo_h<<<dim3(DIMn / 128, Bn * Ssz / 128), 256, SMEMH_BYTES>>>(
            obh, Wo16 + (long)l * INNERn * DIMn, X, bo + l * DIMn);

        ln1_k<<<Bn * Ssz, 256>>>(X, nm_w + l * DIMn, nm_b + l * DIMn, xnh);

        if (l == 0) cudaStreamWaitEvent(0, evMoeW, 0);

        moe1_h<<<dim3(MLPn / 128, Ssz / 128, Bn * Kn), 256, SMEMH_BYTES>>>(
            xnh, W116 + (long)l * En * DIMn * MLPn, b1 + (long)l * En * MLPn, hbh, fe_l, fw_l);
        moe2_h<<<dim3(DIMn / 128, Ssz / 128, Bn * Kn), 256, SMEMH_BYTES>>>(
            hbh, W216 + (long)l * En * MLPn * DIMn, b2 + (long)l * En * DIMn, Yb, fe_l, fw_l);
        comb_k<<<(unsigned)(SZX / 4 / 256), 256>>>((const float4*)Yb, (float4*)X, fw_l);
    }
}